// round 1
// baseline (speedup 1.0000x reference)
#include <cuda_runtime.h>
#include <cuda_bf16.h>
#include <math.h>

// ---------------- problem constants ----------------
#define BB 2
#define TT 2048
#define CC 1024
#define HH 16
#define DD 64
#define EE 8
#define HDIM 1536
#define M0 (BB*TT)          // 4096 tokens
#define MG 9216             // 4096*2 gathered rows + 8*128 worst-case padding
#define EPSV 1e-6f

// ---------------- device scratch (no allocations allowed) ----------------
__device__ float g_h   [M0*CC];
__device__ float g_q   [M0*CC];
__device__ float g_k   [M0*CC];
__device__ float g_v   [M0*CC];
__device__ float g_y   [M0*CC];
__device__ float g_x2  [M0*CC];
__device__ float g_hn  [M0*CC];
__device__ float g_t1  [MG*HDIM];
__device__ float g_t3  [MG*HDIM];
__device__ float g_gb  [MG*HDIM];
__device__ float g_ctr [MG*CC];
__device__ int   g_counts[EE];
__device__ int   g_cursor[EE];
__device__ int   g_poff[EE+1];
__device__ int   g_perm[MG];
__device__ float g_gatew[MG];
__device__ int   g_idx2[M0*2];
__device__ float g_wts2[M0*2];
__device__ int   g_tokrow[M0*2];

// ---------------- RMSNorm ----------------
__global__ void rmsnorm_k(const float* __restrict__ x, const float* __restrict__ w,
                          float* __restrict__ o) {
    int row = blockIdx.x;
    const float* xr = x + (long)row*CC;
    __shared__ float red[256];
    float s = 0.f;
    for (int c = threadIdx.x; c < CC; c += 256) { float v = xr[c]; s += v*v; }
    red[threadIdx.x] = s; __syncthreads();
    for (int st = 128; st > 0; st >>= 1) {
        if (threadIdx.x < st) red[threadIdx.x] += red[threadIdx.x+st];
        __syncthreads();
    }
    float inv = rsqrtf(red[0]/(float)CC + EPSV);
    for (int c = threadIdx.x; c < CC; c += 256)
        o[(long)row*CC + c] = w[c]*xr[c]*inv;
}

// ---------------- generic SGEMM: C[M,N] = gatherA(A)[M,K] @ W_e[N,K]^T ----------------
// optional: residual add R, per-row gather perm, per-rowtile expert via poff,
// per-row output scale rowscale. wstride = N*K stride between experts.
#define BM 128
#define BN 128
#define BK 16
__global__ __launch_bounds__(256)
void sgemm_k(const float* __restrict__ A, const float* __restrict__ Wb,
             float* __restrict__ Cout, int M, int N, int K,
             const float* __restrict__ R,
             const int* __restrict__ perm,
             const int* __restrict__ poff,
             const float* __restrict__ rowscale,
             long wstride) {
    __shared__ float As[BK][BM];
    __shared__ float Bs[BK][BN];
    int tileN = blockIdx.x, tileM = blockIdx.y;
    int row0 = tileM*BM;
    const float* W = Wb;
    if (poff) {
        int e = 0;
        #pragma unroll
        for (int q = 1; q < EE; q++) if (row0 >= poff[q]) e = q;
        W += (long)e * wstride;
    }
    int tid = threadIdx.x;
    int arow = tid >> 2;
    int acol = (tid & 3) * 4;
    int trow = (tid >> 4) * 8;
    int tcol = (tid & 15) * 8;
    float acc[8][8] = {};
    for (int k0 = 0; k0 < K; k0 += BK) {
        #pragma unroll
        for (int i = 0; i < 2; i++) {
            int r = arow + i*64;
            int grow = row0 + r;
            int src = perm ? perm[grow] : grow;
            float4 va = *(const float4*)(A + (long)src*K + k0 + acol);
            As[acol+0][r]=va.x; As[acol+1][r]=va.y; As[acol+2][r]=va.z; As[acol+3][r]=va.w;
            int n = arow + i*64;
            float4 vb = *(const float4*)(W + (long)(tileN*BN+n)*K + k0 + acol);
            Bs[acol+0][n]=vb.x; Bs[acol+1][n]=vb.y; Bs[acol+2][n]=vb.z; Bs[acol+3][n]=vb.w;
        }
        __syncthreads();
        #pragma unroll
        for (int k = 0; k < BK; k++) {
            float ra[8], rb[8];
            #pragma unroll
            for (int i = 0; i < 8; i++) ra[i] = As[k][trow+i];
            #pragma unroll
            for (int j = 0; j < 8; j++) rb[j] = Bs[k][tcol+j];
            #pragma unroll
            for (int i = 0; i < 8; i++)
                #pragma unroll
                for (int j = 0; j < 8; j++)
                    acc[i][j] += ra[i]*rb[j];
        }
        __syncthreads();
    }
    #pragma unroll
    for (int i = 0; i < 8; i++) {
        int grow = row0 + trow + i;
        float sc = rowscale ? rowscale[grow] : 1.f;
        #pragma unroll
        for (int j = 0; j < 8; j++) {
            int gcol = tileN*BN + tcol + j;
            float v = acc[i][j] * sc;
            if (R) v += R[(long)grow*N + gcol];
            Cout[(long)grow*N + gcol] = v;
        }
    }
}

// ---------------- RoPE (in-place on q and k, [B,T,H,D] layout) ----------------
__global__ void rope_k(float* __restrict__ q, float* __restrict__ k,
                       const float* __restrict__ cs, const float* __restrict__ sn) {
    int idx = blockIdx.x*blockDim.x + threadIdx.x;       // B*T*H*32
    if (idx >= M0*HH*32) return;
    int d  = idx & 31;
    int h  = (idx >> 5) & (HH-1);
    int bt = idx >> 9;
    int t  = bt & (TT-1);
    long base = (long)bt*CC + h*DD;
    float c1 = cs[t*DD + d], c2 = cs[t*DD + d + 32];
    float s1 = sn[t*DD + d], s2 = sn[t*DD + d + 32];
    float q1 = q[base+d], q2 = q[base+d+32];
    q[base+d]    = q1*c1 - q2*s1;
    q[base+d+32] = q2*c2 + q1*s2;
    float k1 = k[base+d], k2 = k[base+d+32];
    k[base+d]    = k1*c1 - k2*s1;
    k[base+d+32] = k2*c2 + k1*s2;
}

// ---------------- flash-style causal attention, fp32 ----------------
// grid (T/64, H, B), 64 threads; thread = one query row; online softmax.
__global__ __launch_bounds__(64)
void attn_k(const float* __restrict__ q, const float* __restrict__ k,
            const float* __restrict__ v, float* __restrict__ y) {
    int qb = blockIdx.x, h = blockIdx.y, b = blockIdx.z;
    int tq = qb*64 + threadIdx.x;
    __shared__ float Ks[64][DD+1];
    __shared__ float Vs[64][DD+1];
    float qr[DD];
    long qbase = ((long)(b*TT + tq)*HH + h)*DD;
    #pragma unroll
    for (int d = 0; d < DD; d++) qr[d] = q[qbase+d] * 0.125f;   // 1/sqrt(64)
    float m = -1e30f, l = 0.f, acc[DD] = {};
    int ktiles = qb + 1;
    for (int kt = 0; kt < ktiles; kt++) {
        for (int i = 0; i < 64; i++) {
            long kb = ((long)(b*TT + kt*64 + i)*HH + h)*DD + threadIdx.x;
            Ks[i][threadIdx.x] = k[kb];
            Vs[i][threadIdx.x] = v[kb];
        }
        __syncthreads();
        int jmax = (kt == qb) ? (threadIdx.x + 1) : 64;
        for (int j = 0; j < jmax; j++) {
            float s = 0.f;
            #pragma unroll
            for (int d = 0; d < DD; d++) s += qr[d]*Ks[j][d];
            if (s > m) {
                float corr = __expf(m - s);
                l *= corr;
                #pragma unroll
                for (int d = 0; d < DD; d++) acc[d] *= corr;
                m = s;
            }
            float p = __expf(s - m);
            l += p;
            #pragma unroll
            for (int d = 0; d < DD; d++) acc[d] += p*Vs[j][d];
        }
        __syncthreads();
    }
    float inv = 1.f/l;
    #pragma unroll
    for (int d = 0; d < DD; d++) y[qbase+d] = acc[d]*inv;
}

// ---------------- MoE router: logits + top-2 softmax + counts ----------------
__global__ void router_k(const float* __restrict__ hn, const float* __restrict__ rw,
                         int* __restrict__ idx2, float* __restrict__ wts2,
                         int* __restrict__ counts) {
    int warp = (blockIdx.x*blockDim.x + threadIdx.x) >> 5;
    int lane = threadIdx.x & 31;
    if (warp >= M0) return;
    float lg[EE];
    for (int e = 0; e < EE; e++) {
        float s = 0.f;
        for (int c = lane; c < CC; c += 32) s += hn[(long)warp*CC + c]*rw[(long)e*CC + c];
        for (int o = 16; o > 0; o >>= 1) s += __shfl_down_sync(0xffffffffu, s, o);
        lg[e] = __shfl_sync(0xffffffffu, s, 0);
    }
    if (lane == 0) {
        int i0 = 0;
        for (int e = 1; e < EE; e++) if (lg[e] > lg[i0]) i0 = e;
        int i1 = -1;
        for (int e = 0; e < EE; e++) {
            if (e == i0) continue;
            if (i1 < 0 || lg[e] > lg[i1]) i1 = e;
        }
        float e1 = __expf(lg[i1] - lg[i0]);     // top1 is the max
        float s  = 1.f + e1;
        idx2[warp*2]   = i0; idx2[warp*2+1] = i1;
        wts2[warp*2]   = 1.f/s; wts2[warp*2+1] = e1/s;
        atomicAdd(&counts[i0], 1); atomicAdd(&counts[i1], 1);
    }
}

__global__ void init_k(int* counts, int* perm, float* gatew) {
    int i = blockIdx.x*blockDim.x + threadIdx.x;
    if (i < EE) counts[i] = 0;
    if (i < MG) { perm[i] = 0; gatew[i] = 0.f; }
}

__global__ void offsets_k(const int* counts, int* poff, int* cursor) {
    if (threadIdx.x == 0 && blockIdx.x == 0) {
        int o = 0;
        for (int e = 0; e < EE; e++) {
            poff[e] = o; cursor[e] = 0;
            o += ((counts[e] + 127)/128)*128;   // pad segments to 128 rows
        }
        poff[EE] = o;
    }
}

__global__ void scatter_k(const int* __restrict__ idx2, const float* __restrict__ wts2,
                          int* __restrict__ cursor, const int* __restrict__ poff,
                          int* __restrict__ perm, float* __restrict__ gatew,
                          int* __restrict__ tokrow) {
    int t = blockIdx.x*blockDim.x + threadIdx.x;
    if (t >= M0) return;
    for (int kk = 0; kk < 2; kk++) {
        int e = idx2[t*2 + kk];
        int pos = atomicAdd(&cursor[e], 1);
        int r = poff[e] + pos;
        perm[r] = t; gatew[r] = wts2[t*2 + kk]; tokrow[t*2 + kk] = r;
    }
}

__global__ void silumul_k(const float* __restrict__ t1, const float* __restrict__ t3,
                          float* __restrict__ gb, long n) {
    long i = (long)blockIdx.x*blockDim.x + threadIdx.x;
    if (i < n) {
        float a = t1[i];
        float s = a / (1.f + __expf(-a));
        gb[i] = s * t3[i];
    }
}

__global__ void final_k(const float* __restrict__ x2, const float* __restrict__ ctr,
                        const int* __restrict__ tokrow, float* __restrict__ out) {
    long i = (long)blockIdx.x*blockDim.x + threadIdx.x;
    if (i >= (long)M0*CC) return;
    int t = (int)(i >> 10);
    int c = (int)(i & (CC-1));
    int r0 = tokrow[t*2], r1 = tokrow[t*2+1];
    out[i] = x2[i] + ctr[(long)r0*CC + c] + ctr[(long)r1*CC + c];
}

// ---------------- launch ----------------
static void* sym(const void* s) { void* p = nullptr; cudaGetSymbolAddress(&p, s); return p; }

extern "C" void kernel_launch(void* const* d_in, const int* in_sizes, int n_in,
                              void* d_out, int out_size) {
    const float* x    = (const float*)d_in[0];
    const float* rc   = (const float*)d_in[1];
    const float* rs   = (const float*)d_in[2];
    const float* anw  = (const float*)d_in[3];
    const float* qw   = (const float*)d_in[4];
    const float* kw   = (const float*)d_in[5];
    const float* vw   = (const float*)d_in[6];
    const float* ow   = (const float*)d_in[7];
    const float* fnw  = (const float*)d_in[8];
    const float* rw   = (const float*)d_in[9];
    const float* w1   = (const float*)d_in[10];
    const float* w2   = (const float*)d_in[11];
    const float* w3   = (const float*)d_in[12];
    float* out = (float*)d_out;

    float* h   = (float*)sym(g_h);
    float* q   = (float*)sym(g_q);
    float* k   = (float*)sym(g_k);
    float* v   = (float*)sym(g_v);
    float* y   = (float*)sym(g_y);
    float* x2  = (float*)sym(g_x2);
    float* hn  = (float*)sym(g_hn);
    float* t1  = (float*)sym(g_t1);
    float* t3  = (float*)sym(g_t3);
    float* gb  = (float*)sym(g_gb);
    float* ctr = (float*)sym(g_ctr);
    int*   counts = (int*)sym(g_counts);
    int*   cursor = (int*)sym(g_cursor);
    int*   poff   = (int*)sym(g_poff);
    int*   perm   = (int*)sym(g_perm);
    float* gatew  = (float*)sym(g_gatew);
    int*   idx2   = (int*)sym(g_idx2);
    float* wts2   = (float*)sym(g_wts2);
    int*   tokrow = (int*)sym(g_tokrow);

    // 1) attn rmsnorm
    rmsnorm_k<<<M0, 256>>>(x, anw, h);
    // 2) QKV projections
    sgemm_k<<<dim3(CC/BN, M0/BM), 256>>>(h, qw, q, M0, CC, CC, nullptr, nullptr, nullptr, nullptr, 0);
    sgemm_k<<<dim3(CC/BN, M0/BM), 256>>>(h, kw, k, M0, CC, CC, nullptr, nullptr, nullptr, nullptr, 0);
    sgemm_k<<<dim3(CC/BN, M0/BM), 256>>>(h, vw, v, M0, CC, CC, nullptr, nullptr, nullptr, nullptr, 0);
    // 3) RoPE
    rope_k<<<(M0*HH*32 + 255)/256, 256>>>(q, k, rc, rs);
    // 4) causal attention
    attn_k<<<dim3(TT/64, HH, BB), 64>>>(q, k, v, y);
    // 5) output projection + residual
    sgemm_k<<<dim3(CC/BN, M0/BM), 256>>>(y, ow, x2, M0, CC, CC, x, nullptr, nullptr, nullptr, 0);
    // 6) ffn rmsnorm
    rmsnorm_k<<<M0, 256>>>(x2, fnw, hn);
    // 7) router + gather bookkeeping
    init_k<<<(MG + 255)/256, 256>>>(counts, perm, gatew);
    router_k<<<(M0*32 + 255)/256, 256>>>(hn, rw, idx2, wts2, counts);
    offsets_k<<<1, 32>>>(counts, poff, cursor);
    scatter_k<<<(M0 + 255)/256, 256>>>(idx2, wts2, cursor, poff, perm, gatew, tokrow);
    // 8) expert GEMMs (gathered rows, padded per-expert segments)
    sgemm_k<<<dim3(HDIM/BN, MG/BM), 256>>>(hn, w1, t1, MG, HDIM, CC, nullptr, perm, poff, nullptr, (long)HDIM*CC);
    sgemm_k<<<dim3(HDIM/BN, MG/BM), 256>>>(hn, w3, t3, MG, HDIM, CC, nullptr, perm, poff, nullptr, (long)HDIM*CC);
    silumul_k<<<(int)(((long)MG*HDIM + 255)/256), 256>>>(t1, t3, gb, (long)MG*HDIM);
    sgemm_k<<<dim3(CC/BN, MG/BM), 256>>>(gb, w2, ctr, MG, CC, HDIM, nullptr, nullptr, poff, gatew, (long)CC*HDIM);
    // 9) combine expert outputs + residual -> final output
    final_k<<<(int)(((long)M0*CC + 255)/256), 256>>>(x2, ctr, tokrow, out);
}

// round 4
// speedup vs baseline: 2.1353x; 2.1353x over previous
#include <cuda_runtime.h>
#include <cuda_fp16.h>
#include <cstdint>
#include <stdint.h>
#include <math.h>

// ---------------- problem constants ----------------
#define BB 2
#define TT 2048
#define CC 1024
#define HH 16
#define DD 64
#define EE 8
#define HDIM 1536
#define M0 (BB*TT)          // 4096 tokens
#define MG 9216             // gathered rows + worst-case per-expert padding
#define EPSV 1e-6f

// ---------------- device scratch (no allocations allowed) ----------------
__device__ float  g_q   [M0*CC];
__device__ float  g_k   [M0*CC];
__device__ float  g_v   [M0*CC];
__device__ float  g_x2  [M0*CC];
__device__ float  g_hn  [M0*CC];
__device__ float  g_t1  [MG*HDIM];
__device__ float  g_t3  [MG*HDIM];
__device__ float  g_ctr [MG*CC];
__device__ __half g_h16 [M0*CC];
__device__ __half g_y16 [M0*CC];
__device__ __half g_hn16[M0*CC];
__device__ __half g_gb16[MG*HDIM];
__device__ __half g_qw16[CC*CC];
__device__ __half g_kw16[CC*CC];
__device__ __half g_vw16[CC*CC];
__device__ __half g_ow16[CC*CC];
__device__ __half g_w116[EE*HDIM*CC];
__device__ __half g_w216[EE*CC*HDIM];
__device__ __half g_w316[EE*HDIM*CC];
__device__ int    g_counts[EE];
__device__ int    g_cursor[EE];
__device__ int    g_poff[EE+1];
__device__ int    g_perm[MG];
__device__ float  g_gatew[MG];
__device__ int    g_idx2[M0*2];
__device__ float  g_wts2[M0*2];
__device__ int    g_tokrow[M0*2];

// ---------------- PTX helpers ----------------
__device__ __forceinline__ unsigned s2u(const void* p) {
    unsigned a;
    asm("{ .reg .u64 t; cvta.to.shared.u64 t, %1; cvt.u32.u64 %0, t; }" : "=r"(a) : "l"(p));
    return a;
}
__device__ __forceinline__ void ldm_x4(unsigned& r0, unsigned& r1, unsigned& r2, unsigned& r3, unsigned a) {
    asm volatile("ldmatrix.sync.aligned.m8n8.x4.shared.b16 {%0,%1,%2,%3}, [%4];"
                 : "=r"(r0), "=r"(r1), "=r"(r2), "=r"(r3) : "r"(a));
}
__device__ __forceinline__ void mma16816(float& d0, float& d1, float& d2, float& d3,
                                         unsigned a0, unsigned a1, unsigned a2, unsigned a3,
                                         unsigned b0, unsigned b1) {
    asm volatile("mma.sync.aligned.m16n8k16.row.col.f32.f16.f16.f32 "
                 "{%0,%1,%2,%3}, {%4,%5,%6,%7}, {%8,%9}, {%0,%1,%2,%3};"
                 : "+f"(d0), "+f"(d1), "+f"(d2), "+f"(d3)
                 : "r"(a0), "r"(a1), "r"(a2), "r"(a3), "r"(b0), "r"(b1));
}

// ---------------- fp32 -> fp16 convert ----------------
__global__ void f2h_k(const float* __restrict__ s, __half* __restrict__ d, int n4) {
    int i = blockIdx.x*blockDim.x + threadIdx.x;
    if (i < n4) {
        float4 v = ((const float4*)s)[i];
        ((__half2*)d)[i*2]   = __floats2half2_rn(v.x, v.y);
        ((__half2*)d)[i*2+1] = __floats2half2_rn(v.z, v.w);
    }
}

// ---------------- RMSNorm (writes fp16, optional fp32) ----------------
__global__ void rmsnorm_k(const float* __restrict__ x, const float* __restrict__ w,
                          float* __restrict__ o32, __half* __restrict__ o16) {
    int row = blockIdx.x;
    const float* xr = x + (long)row*CC;
    __shared__ float red[256];
    float s = 0.f;
    for (int c = threadIdx.x; c < CC; c += 256) { float v = xr[c]; s += v*v; }
    red[threadIdx.x] = s; __syncthreads();
    for (int st = 128; st > 0; st >>= 1) {
        if (threadIdx.x < st) red[threadIdx.x] += red[threadIdx.x+st];
        __syncthreads();
    }
    float inv = rsqrtf(red[0]/(float)CC + EPSV);
    for (int c = threadIdx.x; c < CC; c += 256) {
        float v = w[c]*xr[c]*inv;
        if (o32) o32[(long)row*CC + c] = v;
        o16[(long)row*CC + c] = __float2half(v);
    }
}

// ---------------- HMMA fp16 GEMM: C[M,N] = gatherA(A)[M,K] @ W_e[N,K]^T ----------------
// 128x128x32 tile, 256 threads (8 warps, 2x4), warp tile 64x32.
// smem rows padded to 40 halves (80B) -> conflict-free ldmatrix.
#define GBM 128
#define GBN 128
#define GBK 32
#define LDP 40      // padded row length in halves
__global__ __launch_bounds__(256)
void gemm16_k(const __half* __restrict__ A, const __half* __restrict__ Wb,
              float* __restrict__ Cout, int N, int K,
              const float* __restrict__ R,
              const int* __restrict__ perm,
              const int* __restrict__ poff,
              const float* __restrict__ rowscale,
              long wstride) {
    __shared__ __half As[2][GBM*LDP];
    __shared__ __half Bs[2][GBN*LDP];
    __shared__ int rowsrc[GBM];

    int tid = threadIdx.x, wid = tid >> 5, lane = tid & 31;
    int tileN = blockIdx.x, tileM = blockIdx.y;
    int row0 = tileM*GBM;

    const __half* W = Wb;
    if (poff) {
        int e = 0;
        #pragma unroll
        for (int q2 = 1; q2 < EE; q2++) if (row0 >= poff[q2]) e = q2;
        W += (long)e * wstride;
    }
    if (tid < GBM) rowsrc[tid] = perm ? perm[row0 + tid] : (row0 + tid);
    __syncthreads();

    int warp_m = (wid >> 2) * 64;      // 0 or 64
    int warp_n = (wid & 3) * 32;       // 0,32,64,96

    unsigned sA[2], sB[2];
    sA[0] = s2u(&As[0][0]); sA[1] = s2u(&As[1][0]);
    sB[0] = s2u(&Bs[0][0]); sB[1] = s2u(&Bs[1][0]);

    // cp.async tile load: 512 chunks of 16B per matrix; thread t does chunks t, t+256
    auto load_stage = [&](int s) {
        int b = s & 1;
        long k0 = (long)s * GBK;
        #pragma unroll
        for (int c = 0; c < 2; c++) {
            int id = tid + c*256;
            int r = id >> 2, ch = id & 3;
            const __half* srcA = A + (long)rowsrc[r]*K + k0 + ch*8;
            unsigned da = sA[b] + (r*LDP + ch*8)*2;
            asm volatile("cp.async.cg.shared.global [%0], [%1], 16;" :: "r"(da), "l"(srcA));
            const __half* srcB = W + (long)(tileN*GBN + r)*K + k0 + ch*8;
            unsigned db = sB[b] + (r*LDP + ch*8)*2;
            asm volatile("cp.async.cg.shared.global [%0], [%1], 16;" :: "r"(db), "l"(srcB));
        }
        asm volatile("cp.async.commit_group;");
    };

    float acc[4][4][4] = {};
    int ns = K / GBK;
    load_stage(0);

    for (int s = 0; s < ns; s++) {
        if (s + 1 < ns) {
            load_stage(s + 1);
            asm volatile("cp.async.wait_group 1;");
        } else {
            asm volatile("cp.async.wait_group 0;");
        }
        __syncthreads();
        int b = s & 1;
        #pragma unroll
        for (int kk = 0; kk < 2; kk++) {
            unsigned af[4][4], bf[2][4];
            #pragma unroll
            for (int mi = 0; mi < 4; mi++) {
                int r = warp_m + mi*16 + (lane & 15);
                int cH = kk*16 + ((lane >> 4) << 3);
                ldm_x4(af[mi][0], af[mi][1], af[mi][2], af[mi][3], sA[b] + (r*LDP + cH)*2);
            }
            #pragma unroll
            for (int pj = 0; pj < 2; pj++) {
                int n = warp_n + pj*16 + (lane & 7) + ((lane >> 4) << 3);
                int cH = kk*16 + (((lane >> 3) & 1) << 3);
                ldm_x4(bf[pj][0], bf[pj][1], bf[pj][2], bf[pj][3], sB[b] + (n*LDP + cH)*2);
            }
            #pragma unroll
            for (int mi = 0; mi < 4; mi++)
                #pragma unroll
                for (int nj = 0; nj < 4; nj++) {
                    unsigned b0 = bf[nj >> 1][(nj & 1)*2];
                    unsigned b1 = bf[nj >> 1][(nj & 1)*2 + 1];
                    mma16816(acc[mi][nj][0], acc[mi][nj][1], acc[mi][nj][2], acc[mi][nj][3],
                             af[mi][0], af[mi][1], af[mi][2], af[mi][3], b0, b1);
                }
        }
        __syncthreads();
    }

    // epilogue: direct register -> gmem (float2 per frag-half)
    int lrow = lane >> 2;
    int lcol = (lane & 3) * 2;
    #pragma unroll
    for (int mi = 0; mi < 4; mi++) {
        #pragma unroll
        for (int half = 0; half < 2; half++) {
            int grow = row0 + warp_m + mi*16 + lrow + half*8;
            float sc = rowscale ? rowscale[grow] : 1.f;
            long obase = (long)grow*N + tileN*GBN + warp_n;
            #pragma unroll
            for (int nj = 0; nj < 4; nj++) {
                float2 vv;
                vv.x = acc[mi][nj][half*2 + 0] * sc;
                vv.y = acc[mi][nj][half*2 + 1] * sc;
                long off = obase + nj*8 + lcol;
                if (R) {
                    const float2 rv = *(const float2*)(R + off);
                    vv.x += rv.x; vv.y += rv.y;
                }
                *(float2*)(Cout + off) = vv;
            }
        }
    }
}

// ---------------- RoPE (in-place on q and k, [B,T,H,D] layout) ----------------
__global__ void rope_k(float* __restrict__ q, float* __restrict__ k,
                       const float* __restrict__ cs, const float* __restrict__ sn) {
    int idx = blockIdx.x*blockDim.x + threadIdx.x;
    if (idx >= M0*HH*32) return;
    int d  = idx & 31;
    int h  = (idx >> 5) & (HH-1);
    int bt = idx >> 9;
    int t  = bt & (TT-1);
    long base = (long)bt*CC + h*DD;
    float c1 = cs[t*DD + d], c2 = cs[t*DD + d + 32];
    float s1 = sn[t*DD + d], s2 = sn[t*DD + d + 32];
    float q1 = q[base+d], q2 = q[base+d+32];
    q[base+d]    = q1*c1 - q2*s1;
    q[base+d+32] = q2*c2 + q1*s2;
    float k1 = k[base+d], k2 = k[base+d+32];
    k[base+d]    = k1*c1 - k2*s1;
    k[base+d+32] = k2*c2 + k1*s2;
}

// ---------------- flash-style causal attention, fp32, fp16 output ----------------
__global__ __launch_bounds__(64)
void attn_k(const float* __restrict__ q, const float* __restrict__ k,
            const float* __restrict__ v, __half* __restrict__ y) {
    int qb = blockIdx.x, h = blockIdx.y, b = blockIdx.z;
    int tq = qb*64 + threadIdx.x;
    __shared__ float Ks[64][DD+1];
    __shared__ float Vs[64][DD+1];
    float qr[DD];
    long qbase = ((long)(b*TT + tq)*HH + h)*DD;
    #pragma unroll
    for (int d = 0; d < DD; d++) qr[d] = q[qbase+d] * 0.125f;
    float m = -1e30f, l = 0.f, acc[DD] = {};
    int ktiles = qb + 1;
    for (int kt = 0; kt < ktiles; kt++) {
        for (int i = 0; i < 64; i++) {
            long kb = ((long)(b*TT + kt*64 + i)*HH + h)*DD + threadIdx.x;
            Ks[i][threadIdx.x] = k[kb];
            Vs[i][threadIdx.x] = v[kb];
        }
        __syncthreads();
        int jmax = (kt == qb) ? ((int)threadIdx.x + 1) : 64;
        for (int j = 0; j < jmax; j++) {
            float s = 0.f;
            #pragma unroll
            for (int d = 0; d < DD; d++) s += qr[d]*Ks[j][d];
            if (s > m) {
                float corr = __expf(m - s);
                l *= corr;
                #pragma unroll
                for (int d = 0; d < DD; d++) acc[d] *= corr;
                m = s;
            }
            float p = __expf(s - m);
            l += p;
            #pragma unroll
            for (int d = 0; d < DD; d++) acc[d] += p*Vs[j][d];
        }
        __syncthreads();
    }
    float inv = 1.f/l;
    #pragma unroll
    for (int d = 0; d < DD; d++) y[qbase+d] = __float2half(acc[d]*inv);
}

// ---------------- MoE router ----------------
__global__ void router_k(const float* __restrict__ hn, const float* __restrict__ rw,
                         int* __restrict__ idx2, float* __restrict__ wts2,
                         int* __restrict__ counts) {
    int warp = (blockIdx.x*blockDim.x + threadIdx.x) >> 5;
    int lane = threadIdx.x & 31;
    if (warp >= M0) return;
    float lg[EE];
    for (int e = 0; e < EE; e++) {
        float s = 0.f;
        for (int c = lane; c < CC; c += 32) s += hn[(long)warp*CC + c]*rw[(long)e*CC + c];
        for (int o = 16; o > 0; o >>= 1) s += __shfl_down_sync(0xffffffffu, s, o);
        lg[e] = __shfl_sync(0xffffffffu, s, 0);
    }
    if (lane == 0) {
        int i0 = 0;
        for (int e = 1; e < EE; e++) if (lg[e] > lg[i0]) i0 = e;
        int i1 = -1;
        for (int e = 0; e < EE; e++) {
            if (e == i0) continue;
            if (i1 < 0 || lg[e] > lg[i1]) i1 = e;
        }
        float e1 = __expf(lg[i1] - lg[i0]);
        float s  = 1.f + e1;
        idx2[warp*2]   = i0; idx2[warp*2+1] = i1;
        wts2[warp*2]   = 1.f/s; wts2[warp*2+1] = e1/s;
        atomicAdd(&counts[i0], 1); atomicAdd(&counts[i1], 1);
    }
}

__global__ void init_k(int* counts, int* perm, float* gatew) {
    int i = blockIdx.x*blockDim.x + threadIdx.x;
    if (i < EE) counts[i] = 0;
    if (i < MG) { perm[i] = 0; gatew[i] = 0.f; }
}

__global__ void offsets_k(const int* counts, int* poff, int* cursor) {
    if (threadIdx.x == 0 && blockIdx.x == 0) {
        int o = 0;
        for (int e = 0; e < EE; e++) {
            poff[e] = o; cursor[e] = 0;
            o += ((counts[e] + 127)/128)*128;
        }
        poff[EE] = o;
    }
}

__global__ void scatter_k(const int* __restrict__ idx2, const float* __restrict__ wts2,
                          int* __restrict__ cursor, const int* __restrict__ poff,
                          int* __restrict__ perm, float* __restrict__ gatew,
                          int* __restrict__ tokrow) {
    int t = blockIdx.x*blockDim.x + threadIdx.x;
    if (t >= M0) return;
    for (int kk = 0; kk < 2; kk++) {
        int e = idx2[t*2 + kk];
        int pos = atomicAdd(&cursor[e], 1);
        int r = poff[e] + pos;
        perm[r] = t; gatew[r] = wts2[t*2 + kk]; tokrow[t*2 + kk] = r;
    }
}

__global__ void silumul_k(const float* __restrict__ t1, const float* __restrict__ t3,
                          __half* __restrict__ gb, long n) {
    long i = (long)blockIdx.x*blockDim.x + threadIdx.x;
    if (i < n) {
        float a = t1[i];
        float s = a / (1.f + __expf(-a));
        gb[i] = __float2half(s * t3[i]);
    }
}

__global__ void final_k(const float* __restrict__ x2, const float* __restrict__ ctr,
                        const int* __restrict__ tokrow, float* __restrict__ out) {
    long i = (long)blockIdx.x*blockDim.x + threadIdx.x;
    if (i >= (long)M0*CC) return;
    int t = (int)(i >> 10);
    int c = (int)(i & (CC-1));
    int r0 = tokrow[t*2], r1 = tokrow[t*2+1];
    out[i] = x2[i] + ctr[(long)r0*CC + c] + ctr[(long)r1*CC + c];
}

// ---------------- launch ----------------
static void* sym(const void* s) { void* p = nullptr; cudaGetSymbolAddress(&p, s); return p; }

extern "C" void kernel_launch(void* const* d_in, const int* in_sizes, int n_in,
                              void* d_out, int out_size) {
    const float* x    = (const float*)d_in[0];
    const float* rc   = (const float*)d_in[1];
    const float* rs   = (const float*)d_in[2];
    const float* anw  = (const float*)d_in[3];
    const float* qw   = (const float*)d_in[4];
    const float* kw   = (const float*)d_in[5];
    const float* vw   = (const float*)d_in[6];
    const float* ow   = (const float*)d_in[7];
    const float* fnw  = (const float*)d_in[8];
    const float* rw   = (const float*)d_in[9];
    const float* w1   = (const float*)d_in[10];
    const float* w2   = (const float*)d_in[11];
    const float* w3   = (const float*)d_in[12];
    float* out = (float*)d_out;

    float*  q    = (float*)sym(g_q);
    float*  k    = (float*)sym(g_k);
    float*  v    = (float*)sym(g_v);
    float*  x2   = (float*)sym(g_x2);
    float*  hn   = (float*)sym(g_hn);
    float*  t1   = (float*)sym(g_t1);
    float*  t3   = (float*)sym(g_t3);
    float*  ctr  = (float*)sym(g_ctr);
    __half* h16  = (__half*)sym(g_h16);
    __half* y16  = (__half*)sym(g_y16);
    __half* hn16 = (__half*)sym(g_hn16);
    __half* gb16 = (__half*)sym(g_gb16);
    __half* qw16 = (__half*)sym(g_qw16);
    __half* kw16 = (__half*)sym(g_kw16);
    __half* vw16 = (__half*)sym(g_vw16);
    __half* ow16 = (__half*)sym(g_ow16);
    __half* w116 = (__half*)sym(g_w116);
    __half* w216 = (__half*)sym(g_w216);
    __half* w316 = (__half*)sym(g_w316);
    int*   counts = (int*)sym(g_counts);
    int*   cursor = (int*)sym(g_cursor);
    int*   poff   = (int*)sym(g_poff);
    int*   perm   = (int*)sym(g_perm);
    float* gatew  = (float*)sym(g_gatew);
    int*   idx2   = (int*)sym(g_idx2);
    float* wts2   = (float*)sym(g_wts2);
    int*   tokrow = (int*)sym(g_tokrow);

    // 0) weight conversions to fp16
    int n4c = CC*CC/4;
    int n4e = EE*HDIM*CC/4;
    f2h_k<<<(n4c+255)/256, 256>>>(qw, qw16, n4c);
    f2h_k<<<(n4c+255)/256, 256>>>(kw, kw16, n4c);
    f2h_k<<<(n4c+255)/256, 256>>>(vw, vw16, n4c);
    f2h_k<<<(n4c+255)/256, 256>>>(ow, ow16, n4c);
    f2h_k<<<(n4e+255)/256, 256>>>(w1, w116, n4e);
    f2h_k<<<(n4e+255)/256, 256>>>(w2, w216, n4e);
    f2h_k<<<(n4e+255)/256, 256>>>(w3, w316, n4e);

    // 1) attn rmsnorm (fp16 out)
    rmsnorm_k<<<M0, 256>>>(x, anw, nullptr, h16);
    // 2) QKV projections (HMMA tensor cores)
    gemm16_k<<<dim3(CC/GBN, M0/GBM), 256>>>(h16, qw16, q, CC, CC, nullptr, nullptr, nullptr, nullptr, 0);
    gemm16_k<<<dim3(CC/GBN, M0/GBM), 256>>>(h16, kw16, k, CC, CC, nullptr, nullptr, nullptr, nullptr, 0);
    gemm16_k<<<dim3(CC/GBN, M0/GBM), 256>>>(h16, vw16, v, CC, CC, nullptr, nullptr, nullptr, nullptr, 0);
    // 3) RoPE
    rope_k<<<(M0*HH*32 + 255)/256, 256>>>(q, k, rc, rs);
    // 4) causal attention (fp16 out for o-proj)
    attn_k<<<dim3(TT/64, HH, BB), 64>>>(q, k, v, y16);
    // 5) output projection + residual
    gemm16_k<<<dim3(CC/GBN, M0/GBM), 256>>>(y16, ow16, x2, CC, CC, x, nullptr, nullptr, nullptr, 0);
    // 6) ffn rmsnorm (fp32 for router + fp16 for experts)
    rmsnorm_k<<<M0, 256>>>(x2, fnw, hn, hn16);
    // 7) router + gather bookkeeping
    init_k<<<(MG + 255)/256, 256>>>(counts, perm, gatew);
    router_k<<<(M0*32 + 255)/256, 256>>>(hn, rw, idx2, wts2, counts);
    offsets_k<<<1, 32>>>(counts, poff, cursor);
    scatter_k<<<(M0 + 255)/256, 256>>>(idx2, wts2, cursor, poff, perm, gatew, tokrow);
    // 8) expert GEMMs (gathered rows, padded per-expert segments)
    gemm16_k<<<dim3(HDIM/GBN, MG/GBM), 256>>>(hn16, w116, t1, HDIM, CC, nullptr, perm, poff, nullptr, (long)HDIM*CC);
    gemm16_k<<<dim3(HDIM/GBN, MG/GBM), 256>>>(hn16, w316, t3, HDIM, CC, nullptr, perm, poff, nullptr, (long)HDIM*CC);
    silumul_k<<<(int)(((long)MG*HDIM + 255)/256), 256>>>(t1, t3, gb16, (long)MG*HDIM);
    gemm16_k<<<dim3(CC/GBN, MG/GBM), 256>>>(gb16, w216, ctr, CC, HDIM, nullptr, nullptr, poff, gatew, (long)CC*HDIM);
    // 9) combine expert outputs + residual -> final output
    final_k<<<(int)(((long)M0*CC + 255)/256), 256>>>(x2, ctr, tokrow, out);
}

// round 5
// speedup vs baseline: 6.2202x; 2.9130x over previous
#include <cuda_runtime.h>
#include <cuda_fp16.h>
#include <cstdint>
#include <stdint.h>
#include <math.h>

// ---------------- problem constants ----------------
#define BB 2
#define TT 2048
#define CC 1024
#define HH 16
#define DD 64
#define EE 8
#define HDIM 1536
#define M0 (BB*TT)
#define MG 9216
#define EPSV 1e-6f

// ---------------- device scratch ----------------
__device__ float  g_q   [M0*CC];
__device__ float  g_k   [M0*CC];
__device__ float  g_v   [M0*CC];
__device__ float  g_x2  [M0*CC];
__device__ float  g_hn  [M0*CC];
__device__ float  g_t1  [MG*HDIM];
__device__ float  g_t3  [MG*HDIM];
__device__ float  g_ctr [MG*CC];
__device__ __half g_h16 [M0*CC];
__device__ __half g_q16 [M0*CC];
__device__ __half g_k16 [M0*CC];
__device__ __half g_v16 [M0*CC];
__device__ __half g_y16 [M0*CC];
__device__ __half g_hn16[M0*CC];
__device__ __half g_gb16[MG*HDIM];
__device__ __half g_qw16[CC*CC];
__device__ __half g_kw16[CC*CC];
__device__ __half g_vw16[CC*CC];
__device__ __half g_ow16[CC*CC];
__device__ __half g_w116[EE*HDIM*CC];
__device__ __half g_w216[EE*CC*HDIM];
__device__ __half g_w316[EE*HDIM*CC];
__device__ int    g_counts[EE];
__device__ int    g_cursor[EE];
__device__ int    g_poff[EE+1];
__device__ int    g_perm[MG];
__device__ float  g_gatew[MG];
__device__ int    g_idx2[M0*2];
__device__ float  g_wts2[M0*2];
__device__ int    g_tokrow[M0*2];

// ---------------- PTX helpers ----------------
__device__ __forceinline__ unsigned s2u(const void* p) {
    unsigned a;
    asm("{ .reg .u64 t; cvta.to.shared.u64 t, %1; cvt.u32.u64 %0, t; }" : "=r"(a) : "l"(p));
    return a;
}
__device__ __forceinline__ void ldm_x4(unsigned& r0, unsigned& r1, unsigned& r2, unsigned& r3, unsigned a) {
    asm volatile("ldmatrix.sync.aligned.m8n8.x4.shared.b16 {%0,%1,%2,%3}, [%4];"
                 : "=r"(r0), "=r"(r1), "=r"(r2), "=r"(r3) : "r"(a));
}
__device__ __forceinline__ void ldm_x4t(unsigned& r0, unsigned& r1, unsigned& r2, unsigned& r3, unsigned a) {
    asm volatile("ldmatrix.sync.aligned.m8n8.x4.trans.shared.b16 {%0,%1,%2,%3}, [%4];"
                 : "=r"(r0), "=r"(r1), "=r"(r2), "=r"(r3) : "r"(a));
}
__device__ __forceinline__ void mma16816(float& d0, float& d1, float& d2, float& d3,
                                         unsigned a0, unsigned a1, unsigned a2, unsigned a3,
                                         unsigned b0, unsigned b1) {
    asm volatile("mma.sync.aligned.m16n8k16.row.col.f32.f16.f16.f32 "
                 "{%0,%1,%2,%3}, {%4,%5,%6,%7}, {%8,%9}, {%0,%1,%2,%3};"
                 : "+f"(d0), "+f"(d1), "+f"(d2), "+f"(d3)
                 : "r"(a0), "r"(a1), "r"(a2), "r"(a3), "r"(b0), "r"(b1));
}
#define CPA16(dst, src) asm volatile("cp.async.cg.shared.global [%0], [%1], 16;" :: "r"(dst), "l"(src))

// ---------------- fp32 -> fp16 convert ----------------
__global__ void f2h_k(const float* __restrict__ s, __half* __restrict__ d, int n4) {
    int i = blockIdx.x*blockDim.x + threadIdx.x;
    if (i < n4) {
        float4 v = ((const float4*)s)[i];
        ((__half2*)d)[i*2]   = __floats2half2_rn(v.x, v.y);
        ((__half2*)d)[i*2+1] = __floats2half2_rn(v.z, v.w);
    }
}

// ---------------- RMSNorm ----------------
__global__ void rmsnorm_k(const float* __restrict__ x, const float* __restrict__ w,
                          float* __restrict__ o32, __half* __restrict__ o16) {
    int row = blockIdx.x;
    const float* xr = x + (long)row*CC;
    __shared__ float red[256];
    float s = 0.f;
    for (int c = threadIdx.x; c < CC; c += 256) { float v = xr[c]; s += v*v; }
    red[threadIdx.x] = s; __syncthreads();
    for (int st = 128; st > 0; st >>= 1) {
        if (threadIdx.x < st) red[threadIdx.x] += red[threadIdx.x+st];
        __syncthreads();
    }
    float inv = rsqrtf(red[0]/(float)CC + EPSV);
    for (int c = threadIdx.x; c < CC; c += 256) {
        float v = w[c]*xr[c]*inv;
        if (o32) o32[(long)row*CC + c] = v;
        o16[(long)row*CC + c] = __float2half(v);
    }
}

// ---------------- HMMA fp16 GEMM ----------------
#define GBM 128
#define GBN 128
#define GBK 32
#define LDP 40
__global__ __launch_bounds__(256)
void gemm16_k(const __half* __restrict__ A, const __half* __restrict__ Wb,
              float* __restrict__ Cout, int N, int K,
              const float* __restrict__ R,
              const int* __restrict__ perm,
              const int* __restrict__ poff,
              const float* __restrict__ rowscale,
              long wstride) {
    __shared__ __half As[2][GBM*LDP];
    __shared__ __half Bs[2][GBN*LDP];
    __shared__ int rowsrc[GBM];

    int tid = threadIdx.x, wid = tid >> 5, lane = tid & 31;
    int tileN = blockIdx.x, tileM = blockIdx.y;
    int row0 = tileM*GBM;

    const __half* W = Wb;
    if (poff) {
        int e = 0;
        #pragma unroll
        for (int q2 = 1; q2 < EE; q2++) if (row0 >= poff[q2]) e = q2;
        W += (long)e * wstride;
    }
    if (tid < GBM) rowsrc[tid] = perm ? perm[row0 + tid] : (row0 + tid);
    __syncthreads();

    int warp_m = (wid >> 2) * 64;
    int warp_n = (wid & 3) * 32;

    unsigned sA[2], sB[2];
    sA[0] = s2u(&As[0][0]); sA[1] = s2u(&As[1][0]);
    sB[0] = s2u(&Bs[0][0]); sB[1] = s2u(&Bs[1][0]);

    auto load_stage = [&](int s) {
        int b = s & 1;
        long k0 = (long)s * GBK;
        #pragma unroll
        for (int c = 0; c < 2; c++) {
            int id = tid + c*256;
            int r = id >> 2, ch = id & 3;
            const __half* srcA = A + (long)rowsrc[r]*K + k0 + ch*8;
            unsigned da = sA[b] + (r*LDP + ch*8)*2;
            CPA16(da, srcA);
            const __half* srcB = W + (long)(tileN*GBN + r)*K + k0 + ch*8;
            unsigned db = sB[b] + (r*LDP + ch*8)*2;
            CPA16(db, srcB);
        }
        asm volatile("cp.async.commit_group;");
    };

    float acc[4][4][4] = {};
    int ns = K / GBK;
    load_stage(0);

    for (int s = 0; s < ns; s++) {
        if (s + 1 < ns) {
            load_stage(s + 1);
            asm volatile("cp.async.wait_group 1;");
        } else {
            asm volatile("cp.async.wait_group 0;");
        }
        __syncthreads();
        int b = s & 1;
        #pragma unroll
        for (int kk = 0; kk < 2; kk++) {
            unsigned af[4][4], bf[2][4];
            #pragma unroll
            for (int mi = 0; mi < 4; mi++) {
                int r = warp_m + mi*16 + (lane & 15);
                int cH = kk*16 + ((lane >> 4) << 3);
                ldm_x4(af[mi][0], af[mi][1], af[mi][2], af[mi][3], sA[b] + (r*LDP + cH)*2);
            }
            #pragma unroll
            for (int pj = 0; pj < 2; pj++) {
                int n = warp_n + pj*16 + (lane & 7) + ((lane >> 4) << 3);
                int cH = kk*16 + (((lane >> 3) & 1) << 3);
                ldm_x4(bf[pj][0], bf[pj][1], bf[pj][2], bf[pj][3], sB[b] + (n*LDP + cH)*2);
            }
            #pragma unroll
            for (int mi = 0; mi < 4; mi++)
                #pragma unroll
                for (int nj = 0; nj < 4; nj++) {
                    unsigned b0 = bf[nj >> 1][(nj & 1)*2];
                    unsigned b1 = bf[nj >> 1][(nj & 1)*2 + 1];
                    mma16816(acc[mi][nj][0], acc[mi][nj][1], acc[mi][nj][2], acc[mi][nj][3],
                             af[mi][0], af[mi][1], af[mi][2], af[mi][3], b0, b1);
                }
        }
        __syncthreads();
    }

    int lrow = lane >> 2;
    int lcol = (lane & 3) * 2;
    #pragma unroll
    for (int mi = 0; mi < 4; mi++) {
        #pragma unroll
        for (int half = 0; half < 2; half++) {
            int grow = row0 + warp_m + mi*16 + lrow + half*8;
            float sc = rowscale ? rowscale[grow] : 1.f;
            long obase = (long)grow*N + tileN*GBN + warp_n;
            #pragma unroll
            for (int nj = 0; nj < 4; nj++) {
                float2 vv;
                vv.x = acc[mi][nj][half*2 + 0] * sc;
                vv.y = acc[mi][nj][half*2 + 1] * sc;
                long off = obase + nj*8 + lcol;
                if (R) {
                    const float2 rv = *(const float2*)(R + off);
                    vv.x += rv.x; vv.y += rv.y;
                }
                *(float2*)(Cout + off) = vv;
            }
        }
    }
}

// ---------------- RoPE: fp32 q,k -> fp16 q(scaled),k ; v -> fp16 ----------------
__global__ void rope_k(const float* __restrict__ q, const float* __restrict__ k,
                       const float* __restrict__ v,
                       __half* __restrict__ q16, __half* __restrict__ k16,
                       __half* __restrict__ v16,
                       const float* __restrict__ cs, const float* __restrict__ sn) {
    int idx = blockIdx.x*blockDim.x + threadIdx.x;
    if (idx >= M0*HH*32) return;
    int d  = idx & 31;
    int h  = (idx >> 5) & (HH-1);
    int bt = idx >> 9;
    int t  = bt & (TT-1);
    long base = (long)bt*CC + h*DD;
    float c1 = cs[t*DD + d], c2 = cs[t*DD + d + 32];
    float s1 = sn[t*DD + d], s2 = sn[t*DD + d + 32];
    float q1 = q[base+d], q2 = q[base+d+32];
    q16[base+d]    = __float2half((q1*c1 - q2*s1) * 0.125f);
    q16[base+d+32] = __float2half((q2*c2 + q1*s2) * 0.125f);
    float k1 = k[base+d], k2 = k[base+d+32];
    k16[base+d]    = __float2half(k1*c1 - k2*s1);
    k16[base+d+32] = __float2half(k2*c2 + k1*s2);
    v16[base+d]    = __float2half(v[base+d]);
    v16[base+d+32] = __float2half(v[base+d+32]);
}

// ---------------- FlashAttention-2 style HMMA causal attention ----------------
// block = 128 threads (4 warps), 64 query rows per block, key tiles of 64.
#define ASTR 72
__global__ __launch_bounds__(128)
void fattn_k(const __half* __restrict__ q, const __half* __restrict__ k,
             const __half* __restrict__ v, __half* __restrict__ y) {
    __shared__ __half sQ[64*ASTR];
    __shared__ __half sK[2][64*ASTR];
    __shared__ __half sV[2][64*ASTR];

    int qb = blockIdx.x, h = blockIdx.y, b = blockIdx.z;
    int tid = threadIdx.x, wid = tid >> 5, lane = tid & 31;

    unsigned uQ = s2u(sQ);
    unsigned uK[2] = { s2u(&sK[0][0]), s2u(&sK[1][0]) };
    unsigned uV[2] = { s2u(&sV[0][0]), s2u(&sV[1][0]) };

    long qbase = ((long)(b*TT + qb*64)*HH + h)*DD;
    #pragma unroll
    for (int c = 0; c < 4; c++) {
        int id = tid + c*128;
        int r = id >> 3, ch = id & 7;
        CPA16(uQ + (r*ASTR + ch*8)*2, q + qbase + (long)r*CC + ch*8);
    }
    asm volatile("cp.async.commit_group;");

    auto load_kv = [&](int s) {
        int bb = s & 1;
        long kvb = ((long)(b*TT + s*64)*HH + h)*DD;
        #pragma unroll
        for (int c = 0; c < 4; c++) {
            int id = tid + c*128;
            int r = id >> 3, ch = id & 7;
            CPA16(uK[bb] + (r*ASTR + ch*8)*2, k + kvb + (long)r*CC + ch*8);
            CPA16(uV[bb] + (r*ASTR + ch*8)*2, v + kvb + (long)r*CC + ch*8);
        }
        asm volatile("cp.async.commit_group;");
    };

    load_kv(0);
    asm volatile("cp.async.wait_group 0;");
    __syncthreads();

    // Q fragments (a-frags), warp owns rows wid*16..+15
    unsigned qa[4][4];
    #pragma unroll
    for (int kk = 0; kk < 4; kk++) {
        int r = wid*16 + (lane & 15);
        int cH = kk*16 + ((lane >> 4) << 3);
        ldm_x4(qa[kk][0], qa[kk][1], qa[kk][2], qa[kk][3], uQ + (r*ASTR + cH)*2);
    }

    float m0 = -1e30f, m1 = -1e30f, l0 = 0.f, l1 = 0.f;
    float oa[8][4] = {};

    for (int kt = 0; kt <= qb; kt++) {
        if (kt + 1 <= qb) { load_kv(kt + 1); asm volatile("cp.async.wait_group 1;"); }
        else              { asm volatile("cp.async.wait_group 0;"); }
        __syncthreads();
        int bb = kt & 1;

        // S = Q @ K^T
        float sc[8][4] = {};
        #pragma unroll
        for (int kk = 0; kk < 4; kk++) {
            unsigned bf[4][4];
            #pragma unroll
            for (int pj = 0; pj < 4; pj++) {
                int n = pj*16 + (lane & 7) + ((lane >> 4) << 3);
                int cH = kk*16 + (((lane >> 3) & 1) << 3);
                ldm_x4(bf[pj][0], bf[pj][1], bf[pj][2], bf[pj][3], uK[bb] + (n*ASTR + cH)*2);
            }
            #pragma unroll
            for (int nj = 0; nj < 8; nj++)
                mma16816(sc[nj][0], sc[nj][1], sc[nj][2], sc[nj][3],
                         qa[kk][0], qa[kk][1], qa[kk][2], qa[kk][3],
                         bf[nj >> 1][(nj & 1)*2], bf[nj >> 1][(nj & 1)*2 + 1]);
        }

        // causal mask on diagonal tile
        if (kt == qb) {
            int r0 = wid*16 + (lane >> 2);
            #pragma unroll
            for (int nj = 0; nj < 8; nj++) {
                int c0 = nj*8 + (lane & 3)*2;
                if (c0     > r0)   sc[nj][0] = -1e30f;
                if (c0 + 1 > r0)   sc[nj][1] = -1e30f;
                if (c0     > r0+8) sc[nj][2] = -1e30f;
                if (c0 + 1 > r0+8) sc[nj][3] = -1e30f;
            }
        }

        // row max (quad reduce)
        float rm0 = -1e30f, rm1 = -1e30f;
        #pragma unroll
        for (int nj = 0; nj < 8; nj++) {
            rm0 = fmaxf(rm0, fmaxf(sc[nj][0], sc[nj][1]));
            rm1 = fmaxf(rm1, fmaxf(sc[nj][2], sc[nj][3]));
        }
        rm0 = fmaxf(rm0, __shfl_xor_sync(0xffffffffu, rm0, 1));
        rm0 = fmaxf(rm0, __shfl_xor_sync(0xffffffffu, rm0, 2));
        rm1 = fmaxf(rm1, __shfl_xor_sync(0xffffffffu, rm1, 1));
        rm1 = fmaxf(rm1, __shfl_xor_sync(0xffffffffu, rm1, 2));
        float mn0 = fmaxf(m0, rm0), mn1 = fmaxf(m1, rm1);
        float corr0 = __expf(m0 - mn0), corr1 = __expf(m1 - mn1);
        m0 = mn0; m1 = mn1;

        // P = exp(S - m), build a-frags, row sums
        unsigned pa[4][4];
        float ps0 = 0.f, ps1 = 0.f;
        #pragma unroll
        for (int j = 0; j < 4; j++) {
            float p00 = __expf(sc[2*j][0]   - m0), p01 = __expf(sc[2*j][1]   - m0);
            float p02 = __expf(sc[2*j][2]   - m1), p03 = __expf(sc[2*j][3]   - m1);
            float p10 = __expf(sc[2*j+1][0] - m0), p11 = __expf(sc[2*j+1][1] - m0);
            float p12 = __expf(sc[2*j+1][2] - m1), p13 = __expf(sc[2*j+1][3] - m1);
            ps0 += p00 + p01 + p10 + p11;
            ps1 += p02 + p03 + p12 + p13;
            __half2 h0 = __floats2half2_rn(p00, p01);
            __half2 h1 = __floats2half2_rn(p02, p03);
            __half2 h2 = __floats2half2_rn(p10, p11);
            __half2 h3 = __floats2half2_rn(p12, p13);
            pa[j][0] = *(unsigned*)&h0;
            pa[j][1] = *(unsigned*)&h1;
            pa[j][2] = *(unsigned*)&h2;
            pa[j][3] = *(unsigned*)&h3;
        }
        ps0 += __shfl_xor_sync(0xffffffffu, ps0, 1);
        ps0 += __shfl_xor_sync(0xffffffffu, ps0, 2);
        ps1 += __shfl_xor_sync(0xffffffffu, ps1, 1);
        ps1 += __shfl_xor_sync(0xffffffffu, ps1, 2);
        l0 = l0*corr0 + ps0;
        l1 = l1*corr1 + ps1;

        #pragma unroll
        for (int nj = 0; nj < 8; nj++) {
            oa[nj][0] *= corr0; oa[nj][1] *= corr0;
            oa[nj][2] *= corr1; oa[nj][3] *= corr1;
        }

        // O += P @ V  (V row-major [key][d] -> trans ldmatrix b-frags)
        #pragma unroll
        for (int j = 0; j < 4; j++) {
            unsigned vf[4][4];
            #pragma unroll
            for (int pd = 0; pd < 4; pd++) {
                int r = j*16 + (lane & 15);
                int cH = pd*16 + ((lane >> 4) << 3);
                ldm_x4t(vf[pd][0], vf[pd][1], vf[pd][2], vf[pd][3], uV[bb] + (r*ASTR + cH)*2);
            }
            #pragma unroll
            for (int dn = 0; dn < 8; dn++)
                mma16816(oa[dn][0], oa[dn][1], oa[dn][2], oa[dn][3],
                         pa[j][0], pa[j][1], pa[j][2], pa[j][3],
                         vf[dn >> 1][(dn & 1)*2], vf[dn >> 1][(dn & 1)*2 + 1]);
        }
        __syncthreads();
    }

    float il0 = 1.f/l0, il1 = 1.f/l1;
    int r0 = qb*64 + wid*16 + (lane >> 2);
    #pragma unroll
    for (int dn = 0; dn < 8; dn++) {
        int col = dn*8 + (lane & 3)*2;
        long o0 = ((long)(b*TT + r0)*HH + h)*DD + col;
        long o1 = ((long)(b*TT + r0 + 8)*HH + h)*DD + col;
        *(__half2*)(y + o0) = __floats2half2_rn(oa[dn][0]*il0, oa[dn][1]*il0);
        *(__half2*)(y + o1) = __floats2half2_rn(oa[dn][2]*il1, oa[dn][3]*il1);
    }
}

// ---------------- MoE router ----------------
__global__ void router_k(const float* __restrict__ hn, const float* __restrict__ rw,
                         int* __restrict__ idx2, float* __restrict__ wts2,
                         int* __restrict__ counts) {
    int warp = (blockIdx.x*blockDim.x + threadIdx.x) >> 5;
    int lane = threadIdx.x & 31;
    if (warp >= M0) return;
    float lg[EE];
    for (int e = 0; e < EE; e++) {
        float s = 0.f;
        for (int c = lane; c < CC; c += 32) s += hn[(long)warp*CC + c]*rw[(long)e*CC + c];
        for (int o = 16; o > 0; o >>= 1) s += __shfl_down_sync(0xffffffffu, s, o);
        lg[e] = __shfl_sync(0xffffffffu, s, 0);
    }
    if (lane == 0) {
        int i0 = 0;
        for (int e = 1; e < EE; e++) if (lg[e] > lg[i0]) i0 = e;
        int i1 = -1;
        for (int e = 0; e < EE; e++) {
            if (e == i0) continue;
            if (i1 < 0 || lg[e] > lg[i1]) i1 = e;
        }
        float e1 = __expf(lg[i1] - lg[i0]);
        float s  = 1.f + e1;
        idx2[warp*2]   = i0; idx2[warp*2+1] = i1;
        wts2[warp*2]   = 1.f/s; wts2[warp*2+1] = e1/s;
        atomicAdd(&counts[i0], 1); atomicAdd(&counts[i1], 1);
    }
}

__global__ void init_k(int* counts, int* perm, float* gatew) {
    int i = blockIdx.x*blockDim.x + threadIdx.x;
    if (i < EE) counts[i] = 0;
    if (i < MG) { perm[i] = 0; gatew[i] = 0.f; }
}

__global__ void offsets_k(const int* counts, int* poff, int* cursor) {
    if (threadIdx.x == 0 && blockIdx.x == 0) {
        int o = 0;
        for (int e = 0; e < EE; e++) {
            poff[e] = o; cursor[e] = 0;
            o += ((counts[e] + 127)/128)*128;
        }
        poff[EE] = o;
    }
}

__global__ void scatter_k(const int* __restrict__ idx2, const float* __restrict__ wts2,
                          int* __restrict__ cursor, const int* __restrict__ poff,
                          int* __restrict__ perm, float* __restrict__ gatew,
                          int* __restrict__ tokrow) {
    int t = blockIdx.x*blockDim.x + threadIdx.x;
    if (t >= M0) return;
    for (int kk = 0; kk < 2; kk++) {
        int e = idx2[t*2 + kk];
        int pos = atomicAdd(&cursor[e], 1);
        int r = poff[e] + pos;
        perm[r] = t; gatew[r] = wts2[t*2 + kk]; tokrow[t*2 + kk] = r;
    }
}

__global__ void silumul_k(const float4* __restrict__ t1, const float4* __restrict__ t3,
                          __half2* __restrict__ gb, int n4) {
    int i = blockIdx.x*blockDim.x + threadIdx.x;
    if (i < n4) {
        float4 a = t1[i], c = t3[i];
        float s0 = a.x / (1.f + __expf(-a.x)) * c.x;
        float s1 = a.y / (1.f + __expf(-a.y)) * c.y;
        float s2 = a.z / (1.f + __expf(-a.z)) * c.z;
        float s3 = a.w / (1.f + __expf(-a.w)) * c.w;
        gb[i*2]   = __floats2half2_rn(s0, s1);
        gb[i*2+1] = __floats2half2_rn(s2, s3);
    }
}

__global__ void final_k(const float* __restrict__ x2, const float* __restrict__ ctr,
                        const int* __restrict__ tokrow, float* __restrict__ out) {
    long i = (long)blockIdx.x*blockDim.x + threadIdx.x;
    if (i >= (long)M0*CC) return;
    int t = (int)(i >> 10);
    int c = (int)(i & (CC-1));
    int r0 = tokrow[t*2], r1 = tokrow[t*2+1];
    out[i] = x2[i] + ctr[(long)r0*CC + c] + ctr[(long)r1*CC + c];
}

// ---------------- launch ----------------
static void* sym(const void* s) { void* p = nullptr; cudaGetSymbolAddress(&p, s); return p; }

extern "C" void kernel_launch(void* const* d_in, const int* in_sizes, int n_in,
                              void* d_out, int out_size) {
    const float* x    = (const float*)d_in[0];
    const float* rc   = (const float*)d_in[1];
    const float* rs   = (const float*)d_in[2];
    const float* anw  = (const float*)d_in[3];
    const float* qw   = (const float*)d_in[4];
    const float* kw   = (const float*)d_in[5];
    const float* vw   = (const float*)d_in[6];
    const float* ow   = (const float*)d_in[7];
    const float* fnw  = (const float*)d_in[8];
    const float* rw   = (const float*)d_in[9];
    const float* w1   = (const float*)d_in[10];
    const float* w2   = (const float*)d_in[11];
    const float* w3   = (const float*)d_in[12];
    float* out = (float*)d_out;

    float*  q    = (float*)sym(g_q);
    float*  k    = (float*)sym(g_k);
    float*  v    = (float*)sym(g_v);
    float*  x2   = (float*)sym(g_x2);
    float*  hn   = (float*)sym(g_hn);
    float*  t1   = (float*)sym(g_t1);
    float*  t3   = (float*)sym(g_t3);
    float*  ctr  = (float*)sym(g_ctr);
    __half* h16  = (__half*)sym(g_h16);
    __half* q16  = (__half*)sym(g_q16);
    __half* k16  = (__half*)sym(g_k16);
    __half* v16  = (__half*)sym(g_v16);
    __half* y16  = (__half*)sym(g_y16);
    __half* hn16 = (__half*)sym(g_hn16);
    __half* gb16 = (__half*)sym(g_gb16);
    __half* qw16 = (__half*)sym(g_qw16);
    __half* kw16 = (__half*)sym(g_kw16);
    __half* vw16 = (__half*)sym(g_vw16);
    __half* ow16 = (__half*)sym(g_ow16);
    __half* w116 = (__half*)sym(g_w116);
    __half* w216 = (__half*)sym(g_w216);
    __half* w316 = (__half*)sym(g_w316);
    int*   counts = (int*)sym(g_counts);
    int*   cursor = (int*)sym(g_cursor);
    int*   poff   = (int*)sym(g_poff);
    int*   perm   = (int*)sym(g_perm);
    float* gatew  = (float*)sym(g_gatew);
    int*   idx2   = (int*)sym(g_idx2);
    float* wts2   = (float*)sym(g_wts2);
    int*   tokrow = (int*)sym(g_tokrow);

    // 0) weight conversions to fp16
    int n4c = CC*CC/4;
    int n4e = EE*HDIM*CC/4;
    f2h_k<<<(n4c+255)/256, 256>>>(qw, qw16, n4c);
    f2h_k<<<(n4c+255)/256, 256>>>(kw, kw16, n4c);
    f2h_k<<<(n4c+255)/256, 256>>>(vw, vw16, n4c);
    f2h_k<<<(n4c+255)/256, 256>>>(ow, ow16, n4c);
    f2h_k<<<(n4e+255)/256, 256>>>(w1, w116, n4e);
    f2h_k<<<(n4e+255)/256, 256>>>(w2, w216, n4e);
    f2h_k<<<(n4e+255)/256, 256>>>(w3, w316, n4e);

    // 1) attn rmsnorm (fp16 out)
    rmsnorm_k<<<M0, 256>>>(x, anw, nullptr, h16);
    // 2) QKV projections (HMMA)
    gemm16_k<<<dim3(CC/GBN, M0/GBM), 256>>>(h16, qw16, q, CC, CC, nullptr, nullptr, nullptr, nullptr, 0);
    gemm16_k<<<dim3(CC/GBN, M0/GBM), 256>>>(h16, kw16, k, CC, CC, nullptr, nullptr, nullptr, nullptr, 0);
    gemm16_k<<<dim3(CC/GBN, M0/GBM), 256>>>(h16, vw16, v, CC, CC, nullptr, nullptr, nullptr, nullptr, 0);
    // 3) RoPE -> fp16 q(scaled), k, v
    rope_k<<<(M0*HH*32 + 255)/256, 256>>>(q, k, v, q16, k16, v16, rc, rs);
    // 4) causal attention (HMMA flash)
    fattn_k<<<dim3(TT/64, HH, BB), 128>>>(q16, k16, v16, y16);
    // 5) output projection + residual
    gemm16_k<<<dim3(CC/GBN, M0/GBM), 256>>>(y16, ow16, x2, CC, CC, x, nullptr, nullptr, nullptr, 0);
    // 6) ffn rmsnorm
    rmsnorm_k<<<M0, 256>>>(x2, fnw, hn, hn16);
    // 7) router + gather bookkeeping
    init_k<<<(MG + 255)/256, 256>>>(counts, perm, gatew);
    router_k<<<(M0*32 + 255)/256, 256>>>(hn, rw, idx2, wts2, counts);
    offsets_k<<<1, 32>>>(counts, poff, cursor);
    scatter_k<<<(M0 + 255)/256, 256>>>(idx2, wts2, cursor, poff, perm, gatew, tokrow);
    // 8) expert GEMMs
    gemm16_k<<<dim3(HDIM/GBN, MG/GBM), 256>>>(hn16, w116, t1, HDIM, CC, nullptr, perm, poff, nullptr, (long)HDIM*CC);
    gemm16_k<<<dim3(HDIM/GBN, MG/GBM), 256>>>(hn16, w316, t3, HDIM, CC, nullptr, perm, poff, nullptr, (long)HDIM*CC);
    silumul_k<<<(MG*HDIM/4 + 255)/256, 256>>>((const float4*)t1, (const float4*)t3, (__half2*)gb16, MG*HDIM/4);
    gemm16_k<<<dim3(CC/GBN, MG/GBM), 256>>>(gb16, w216, ctr, CC, HDIM, nullptr, nullptr, poff, gatew, (long)CC*HDIM);
    // 9) combine
    final_k<<<(int)(((long)M0*CC + 255)/256), 256>>>(x2, ctr, tokrow, out);
}

// round 6
// speedup vs baseline: 6.4001x; 1.0289x over previous
#include <cuda_runtime.h>
#include <cuda_fp16.h>
#include <cstdint>
#include <stdint.h>
#include <math.h>

// ---------------- problem constants ----------------
#define BB 2
#define TT 2048
#define CC 1024
#define HH 16
#define DD 64
#define EE 8
#define HDIM 1536
#define M0 (BB*TT)
#define MG 9216
#define EPSV 1e-6f

// ---------------- device scratch ----------------
__device__ float  g_x2  [M0*CC];
__device__ float  g_hn  [M0*CC];
__device__ float  g_ctr [MG*CC];
__device__ __half g_h16 [M0*CC];
__device__ __half g_qkv16[M0*3*CC];
__device__ __half g_y16 [M0*CC];
__device__ __half g_hn16[M0*CC];
__device__ __half g_gb16[MG*HDIM];
__device__ __half g_wqkv16[3*CC*CC];
__device__ __half g_ow16[CC*CC];
__device__ __half g_w116[EE*HDIM*CC];
__device__ __half g_w216[EE*CC*HDIM];
__device__ __half g_w316[EE*HDIM*CC];
__device__ int    g_counts[EE];
__device__ int    g_cursor[EE];
__device__ int    g_poff[EE+1];
__device__ int    g_perm[MG];
__device__ float  g_gatew[MG];
__device__ int    g_idx2[M0*2];
__device__ float  g_wts2[M0*2];
__device__ int    g_tokrow[M0*2];

// ---------------- PTX helpers ----------------
__device__ __forceinline__ unsigned s2u(const void* p) {
    unsigned a;
    asm("{ .reg .u64 t; cvta.to.shared.u64 t, %1; cvt.u32.u64 %0, t; }" : "=r"(a) : "l"(p));
    return a;
}
__device__ __forceinline__ void ldm_x4(unsigned& r0, unsigned& r1, unsigned& r2, unsigned& r3, unsigned a) {
    asm volatile("ldmatrix.sync.aligned.m8n8.x4.shared.b16 {%0,%1,%2,%3}, [%4];"
                 : "=r"(r0), "=r"(r1), "=r"(r2), "=r"(r3) : "r"(a));
}
__device__ __forceinline__ void ldm_x4t(unsigned& r0, unsigned& r1, unsigned& r2, unsigned& r3, unsigned a) {
    asm volatile("ldmatrix.sync.aligned.m8n8.x4.trans.shared.b16 {%0,%1,%2,%3}, [%4];"
                 : "=r"(r0), "=r"(r1), "=r"(r2), "=r"(r3) : "r"(a));
}
__device__ __forceinline__ void mma16816(float& d0, float& d1, float& d2, float& d3,
                                         unsigned a0, unsigned a1, unsigned a2, unsigned a3,
                                         unsigned b0, unsigned b1) {
    asm volatile("mma.sync.aligned.m16n8k16.row.col.f32.f16.f16.f32 "
                 "{%0,%1,%2,%3}, {%4,%5,%6,%7}, {%8,%9}, {%0,%1,%2,%3};"
                 : "+f"(d0), "+f"(d1), "+f"(d2), "+f"(d3)
                 : "r"(a0), "r"(a1), "r"(a2), "r"(a3), "r"(b0), "r"(b1));
}
#define CPA16(dst, src) asm volatile("cp.async.cg.shared.global [%0], [%1], 16;" :: "r"(dst), "l"(src))

// ---------------- fp32 -> fp16 convert ----------------
__global__ void f2h_k(const float* __restrict__ s, __half* __restrict__ d, int n4) {
    int i = blockIdx.x*blockDim.x + threadIdx.x;
    if (i < n4) {
        float4 v = ((const float4*)s)[i];
        ((__half2*)d)[i*2]   = __floats2half2_rn(v.x, v.y);
        ((__half2*)d)[i*2+1] = __floats2half2_rn(v.z, v.w);
    }
}

// ---------------- RMSNorm ----------------
__global__ void rmsnorm_k(const float* __restrict__ x, const float* __restrict__ w,
                          float* __restrict__ o32, __half* __restrict__ o16) {
    int row = blockIdx.x;
    const float* xr = x + (long)row*CC;
    __shared__ float red[256];
    float s = 0.f;
    for (int c = threadIdx.x; c < CC; c += 256) { float v = xr[c]; s += v*v; }
    red[threadIdx.x] = s; __syncthreads();
    for (int st = 128; st > 0; st >>= 1) {
        if (threadIdx.x < st) red[threadIdx.x] += red[threadIdx.x+st];
        __syncthreads();
    }
    float inv = rsqrtf(red[0]/(float)CC + EPSV);
    for (int c = threadIdx.x; c < CC; c += 256) {
        float v = w[c]*xr[c]*inv;
        if (o32) o32[(long)row*CC + c] = v;
        o16[(long)row*CC + c] = __float2half(v);
    }
}

// ---------------- HMMA fp16 GEMM (fp32 or fp16 output) ----------------
#define GBM 128
#define GBN 128
#define GBK 32
#define LDP 40
__global__ __launch_bounds__(256)
void gemm16_k(const __half* __restrict__ A, const __half* __restrict__ Wb,
              float* __restrict__ Cout, __half* __restrict__ Cout16,
              int N, int K,
              const float* __restrict__ R,
              const int* __restrict__ perm,
              const int* __restrict__ poff,
              const float* __restrict__ rowscale,
              long wstride) {
    __shared__ __half As[2][GBM*LDP];
    __shared__ __half Bs[2][GBN*LDP];
    __shared__ int rowsrc[GBM];

    int tid = threadIdx.x, wid = tid >> 5, lane = tid & 31;
    int tileN = blockIdx.x, tileM = blockIdx.y;
    int row0 = tileM*GBM;

    const __half* W = Wb;
    if (poff) {
        int e = 0;
        #pragma unroll
        for (int q2 = 1; q2 < EE; q2++) if (row0 >= poff[q2]) e = q2;
        W += (long)e * wstride;
    }
    if (tid < GBM) rowsrc[tid] = perm ? perm[row0 + tid] : (row0 + tid);
    __syncthreads();

    int warp_m = (wid >> 2) * 64;
    int warp_n = (wid & 3) * 32;

    unsigned sA[2], sB[2];
    sA[0] = s2u(&As[0][0]); sA[1] = s2u(&As[1][0]);
    sB[0] = s2u(&Bs[0][0]); sB[1] = s2u(&Bs[1][0]);

    auto load_stage = [&](int s) {
        int b = s & 1;
        long k0 = (long)s * GBK;
        #pragma unroll
        for (int c = 0; c < 2; c++) {
            int id = tid + c*256;
            int r = id >> 2, ch = id & 3;
            CPA16(sA[b] + (r*LDP + ch*8)*2, A + (long)rowsrc[r]*K + k0 + ch*8);
            CPA16(sB[b] + (r*LDP + ch*8)*2, W + (long)(tileN*GBN + r)*K + k0 + ch*8);
        }
        asm volatile("cp.async.commit_group;");
    };

    float acc[4][4][4] = {};
    int ns = K / GBK;
    load_stage(0);

    for (int s = 0; s < ns; s++) {
        if (s + 1 < ns) {
            load_stage(s + 1);
            asm volatile("cp.async.wait_group 1;");
        } else {
            asm volatile("cp.async.wait_group 0;");
        }
        __syncthreads();
        int b = s & 1;
        #pragma unroll
        for (int kk = 0; kk < 2; kk++) {
            unsigned af[4][4], bf[2][4];
            #pragma unroll
            for (int mi = 0; mi < 4; mi++) {
                int r = warp_m + mi*16 + (lane & 15);
                int cH = kk*16 + ((lane >> 4) << 3);
                ldm_x4(af[mi][0], af[mi][1], af[mi][2], af[mi][3], sA[b] + (r*LDP + cH)*2);
            }
            #pragma unroll
            for (int pj = 0; pj < 2; pj++) {
                int n = warp_n + pj*16 + (lane & 7) + ((lane >> 4) << 3);
                int cH = kk*16 + (((lane >> 3) & 1) << 3);
                ldm_x4(bf[pj][0], bf[pj][1], bf[pj][2], bf[pj][3], sB[b] + (n*LDP + cH)*2);
            }
            #pragma unroll
            for (int mi = 0; mi < 4; mi++)
                #pragma unroll
                for (int nj = 0; nj < 4; nj++)
                    mma16816(acc[mi][nj][0], acc[mi][nj][1], acc[mi][nj][2], acc[mi][nj][3],
                             af[mi][0], af[mi][1], af[mi][2], af[mi][3],
                             bf[nj >> 1][(nj & 1)*2], bf[nj >> 1][(nj & 1)*2 + 1]);
        }
        __syncthreads();
    }

    int lrow = lane >> 2;
    int lcol = (lane & 3) * 2;
    #pragma unroll
    for (int mi = 0; mi < 4; mi++) {
        #pragma unroll
        for (int half = 0; half < 2; half++) {
            int grow = row0 + warp_m + mi*16 + lrow + half*8;
            float sc = rowscale ? rowscale[grow] : 1.f;
            long obase = (long)grow*N + tileN*GBN + warp_n;
            #pragma unroll
            for (int nj = 0; nj < 4; nj++) {
                float vx = acc[mi][nj][half*2 + 0] * sc;
                float vy = acc[mi][nj][half*2 + 1] * sc;
                long off = obase + nj*8 + lcol;
                if (Cout16) {
                    *(__half2*)(Cout16 + off) = __floats2half2_rn(vx, vy);
                } else {
                    if (R) {
                        const float2 rv = *(const float2*)(R + off);
                        vx += rv.x; vy += rv.y;
                    }
                    float2 vv = { vx, vy };
                    *(float2*)(Cout + off) = vv;
                }
            }
        }
    }
}

// ---------------- fused MoE w1/w3 GEMM + silu*mul -> fp16 ----------------
__global__ __launch_bounds__(256)
void moe13_k(const __half* __restrict__ A, const __half* __restrict__ W1b,
             const __half* __restrict__ W3b, __half* __restrict__ G,
             const int* __restrict__ perm, const int* __restrict__ poff) {
    extern __shared__ __half sm[];
    __half* Asp = sm;                       // 2 * 128*LDP
    __half* B1p = sm + 2*GBM*LDP;
    __half* B3p = sm + 4*GBM*LDP;
    __shared__ int rowsrc[GBM];

    int tid = threadIdx.x, wid = tid >> 5, lane = tid & 31;
    int tileN = blockIdx.x, tileM = blockIdx.y;
    int row0 = tileM*GBM;
    const int K = CC;

    int e = 0;
    #pragma unroll
    for (int q2 = 1; q2 < EE; q2++) if (row0 >= poff[q2]) e = q2;
    const __half* W1 = W1b + (long)e*HDIM*CC;
    const __half* W3 = W3b + (long)e*HDIM*CC;

    if (tid < GBM) rowsrc[tid] = perm[row0 + tid];
    __syncthreads();

    int warp_m = (wid >> 2) * 64;
    int warp_n = (wid & 3) * 32;

    unsigned sA[2], sB1[2], sB3[2];
    sA[0]  = s2u(Asp);             sA[1]  = s2u(Asp + GBM*LDP);
    sB1[0] = s2u(B1p);             sB1[1] = s2u(B1p + GBM*LDP);
    sB3[0] = s2u(B3p);             sB3[1] = s2u(B3p + GBM*LDP);

    auto load_stage = [&](int s) {
        int b = s & 1;
        long k0 = (long)s * GBK;
        #pragma unroll
        for (int c = 0; c < 2; c++) {
            int id = tid + c*256;
            int r = id >> 2, ch = id & 3;
            CPA16(sA[b]  + (r*LDP + ch*8)*2, A  + (long)rowsrc[r]*K + k0 + ch*8);
            CPA16(sB1[b] + (r*LDP + ch*8)*2, W1 + (long)(tileN*GBN + r)*K + k0 + ch*8);
            CPA16(sB3[b] + (r*LDP + ch*8)*2, W3 + (long)(tileN*GBN + r)*K + k0 + ch*8);
        }
        asm volatile("cp.async.commit_group;");
    };

    float a1[4][4][4] = {};
    float a3[4][4][4] = {};
    int ns = K / GBK;
    load_stage(0);

    for (int s = 0; s < ns; s++) {
        if (s + 1 < ns) {
            load_stage(s + 1);
            asm volatile("cp.async.wait_group 1;");
        } else {
            asm volatile("cp.async.wait_group 0;");
        }
        __syncthreads();
        int b = s & 1;
        #pragma unroll
        for (int kk = 0; kk < 2; kk++) {
            unsigned af[4][4], b1f[2][4], b3f[2][4];
            #pragma unroll
            for (int mi = 0; mi < 4; mi++) {
                int r = warp_m + mi*16 + (lane & 15);
                int cH = kk*16 + ((lane >> 4) << 3);
                ldm_x4(af[mi][0], af[mi][1], af[mi][2], af[mi][3], sA[b] + (r*LDP + cH)*2);
            }
            #pragma unroll
            for (int pj = 0; pj < 2; pj++) {
                int n = warp_n + pj*16 + (lane & 7) + ((lane >> 4) << 3);
                int cH = kk*16 + (((lane >> 3) & 1) << 3);
                ldm_x4(b1f[pj][0], b1f[pj][1], b1f[pj][2], b1f[pj][3], sB1[b] + (n*LDP + cH)*2);
                ldm_x4(b3f[pj][0], b3f[pj][1], b3f[pj][2], b3f[pj][3], sB3[b] + (n*LDP + cH)*2);
            }
            #pragma unroll
            for (int mi = 0; mi < 4; mi++)
                #pragma unroll
                for (int nj = 0; nj < 4; nj++) {
                    mma16816(a1[mi][nj][0], a1[mi][nj][1], a1[mi][nj][2], a1[mi][nj][3],
                             af[mi][0], af[mi][1], af[mi][2], af[mi][3],
                             b1f[nj >> 1][(nj & 1)*2], b1f[nj >> 1][(nj & 1)*2 + 1]);
                    mma16816(a3[mi][nj][0], a3[mi][nj][1], a3[mi][nj][2], a3[mi][nj][3],
                             af[mi][0], af[mi][1], af[mi][2], af[mi][3],
                             b3f[nj >> 1][(nj & 1)*2], b3f[nj >> 1][(nj & 1)*2 + 1]);
                }
        }
        __syncthreads();
    }

    int lrow = lane >> 2;
    int lcol = (lane & 3) * 2;
    #pragma unroll
    for (int mi = 0; mi < 4; mi++) {
        #pragma unroll
        for (int half = 0; half < 2; half++) {
            int grow = row0 + warp_m + mi*16 + lrow + half*8;
            long obase = (long)grow*HDIM + tileN*GBN + warp_n;
            #pragma unroll
            for (int nj = 0; nj < 4; nj++) {
                float u0 = a1[mi][nj][half*2 + 0];
                float u1 = a1[mi][nj][half*2 + 1];
                float w0 = a3[mi][nj][half*2 + 0];
                float w1 = a3[mi][nj][half*2 + 1];
                float g0 = u0 / (1.f + __expf(-u0)) * w0;
                float g1 = u1 / (1.f + __expf(-u1)) * w1;
                *(__half2*)(G + obase + nj*8 + lcol) = __floats2half2_rn(g0, g1);
            }
        }
    }
}

// ---------------- RoPE in-place on packed fp16 qkv ----------------
__global__ void rope_k(__half* __restrict__ qkv,
                       const float* __restrict__ cs, const float* __restrict__ sn) {
    int idx = blockIdx.x*blockDim.x + threadIdx.x;
    if (idx >= M0*HH*32) return;
    int d  = idx & 31;
    int h  = (idx >> 5) & (HH-1);
    int bt = idx >> 9;
    int t  = bt & (TT-1);
    long base = (long)bt*(3*CC) + h*DD;
    float c1 = cs[t*DD + d], c2 = cs[t*DD + d + 32];
    float s1 = sn[t*DD + d], s2 = sn[t*DD + d + 32];
    float q1 = __half2float(qkv[base+d]), q2 = __half2float(qkv[base+d+32]);
    qkv[base+d]    = __float2half((q1*c1 - q2*s1) * 0.125f);
    qkv[base+d+32] = __float2half((q2*c2 + q1*s2) * 0.125f);
    float k1 = __half2float(qkv[base+CC+d]), k2 = __half2float(qkv[base+CC+d+32]);
    qkv[base+CC+d]    = __float2half(k1*c1 - k2*s1);
    qkv[base+CC+d+32] = __float2half(k2*c2 + k1*s2);
}

// ---------------- FlashAttention-2 style HMMA causal attention ----------------
#define ASTR 72
#define QKVS (3*CC)
__global__ __launch_bounds__(128)
void fattn_k(const __half* __restrict__ qkv, __half* __restrict__ y) {
    __shared__ __half sQ[64*ASTR];
    __shared__ __half sK[2][64*ASTR];
    __shared__ __half sV[2][64*ASTR];

    int qb = blockIdx.x, h = blockIdx.y, b = blockIdx.z;
    int tid = threadIdx.x, wid = tid >> 5, lane = tid & 31;

    unsigned uQ = s2u(sQ);
    unsigned uK[2] = { s2u(&sK[0][0]), s2u(&sK[1][0]) };
    unsigned uV[2] = { s2u(&sV[0][0]), s2u(&sV[1][0]) };

    long qbase = (long)(b*TT + qb*64)*QKVS + h*DD;
    #pragma unroll
    for (int c = 0; c < 4; c++) {
        int id = tid + c*128;
        int r = id >> 3, ch = id & 7;
        CPA16(uQ + (r*ASTR + ch*8)*2, qkv + qbase + (long)r*QKVS + ch*8);
    }
    asm volatile("cp.async.commit_group;");

    auto load_kv = [&](int s) {
        int bb = s & 1;
        long kvb = (long)(b*TT + s*64)*QKVS + h*DD + CC;
        #pragma unroll
        for (int c = 0; c < 4; c++) {
            int id = tid + c*128;
            int r = id >> 3, ch = id & 7;
            CPA16(uK[bb] + (r*ASTR + ch*8)*2, qkv + kvb + (long)r*QKVS + ch*8);
            CPA16(uV[bb] + (r*ASTR + ch*8)*2, qkv + kvb + CC + (long)r*QKVS + ch*8);
        }
        asm volatile("cp.async.commit_group;");
    };

    load_kv(0);
    asm volatile("cp.async.wait_group 0;");
    __syncthreads();

    unsigned qa[4][4];
    #pragma unroll
    for (int kk = 0; kk < 4; kk++) {
        int r = wid*16 + (lane & 15);
        int cH = kk*16 + ((lane >> 4) << 3);
        ldm_x4(qa[kk][0], qa[kk][1], qa[kk][2], qa[kk][3], uQ + (r*ASTR + cH)*2);
    }

    float m0 = -1e30f, m1 = -1e30f, l0 = 0.f, l1 = 0.f;
    float oa[8][4] = {};

    for (int kt = 0; kt <= qb; kt++) {
        if (kt + 1 <= qb) { load_kv(kt + 1); asm volatile("cp.async.wait_group 1;"); }
        else              { asm volatile("cp.async.wait_group 0;"); }
        __syncthreads();
        int bb = kt & 1;

        float sc[8][4] = {};
        #pragma unroll
        for (int kk = 0; kk < 4; kk++) {
            unsigned bf[4][4];
            #pragma unroll
            for (int pj = 0; pj < 4; pj++) {
                int n = pj*16 + (lane & 7) + ((lane >> 4) << 3);
                int cH = kk*16 + (((lane >> 3) & 1) << 3);
                ldm_x4(bf[pj][0], bf[pj][1], bf[pj][2], bf[pj][3], uK[bb] + (n*ASTR + cH)*2);
            }
            #pragma unroll
            for (int nj = 0; nj < 8; nj++)
                mma16816(sc[nj][0], sc[nj][1], sc[nj][2], sc[nj][3],
                         qa[kk][0], qa[kk][1], qa[kk][2], qa[kk][3],
                         bf[nj >> 1][(nj & 1)*2], bf[nj >> 1][(nj & 1)*2 + 1]);
        }

        if (kt == qb) {
            int r0 = wid*16 + (lane >> 2);
            #pragma unroll
            for (int nj = 0; nj < 8; nj++) {
                int c0 = nj*8 + (lane & 3)*2;
                if (c0     > r0)   sc[nj][0] = -1e30f;
                if (c0 + 1 > r0)   sc[nj][1] = -1e30f;
                if (c0     > r0+8) sc[nj][2] = -1e30f;
                if (c0 + 1 > r0+8) sc[nj][3] = -1e30f;
            }
        }

        float rm0 = -1e30f, rm1 = -1e30f;
        #pragma unroll
        for (int nj = 0; nj < 8; nj++) {
            rm0 = fmaxf(rm0, fmaxf(sc[nj][0], sc[nj][1]));
            rm1 = fmaxf(rm1, fmaxf(sc[nj][2], sc[nj][3]));
        }
        rm0 = fmaxf(rm0, __shfl_xor_sync(0xffffffffu, rm0, 1));
        rm0 = fmaxf(rm0, __shfl_xor_sync(0xffffffffu, rm0, 2));
        rm1 = fmaxf(rm1, __shfl_xor_sync(0xffffffffu, rm1, 1));
        rm1 = fmaxf(rm1, __shfl_xor_sync(0xffffffffu, rm1, 2));
        float mn0 = fmaxf(m0, rm0), mn1 = fmaxf(m1, rm1);
        float corr0 = __expf(m0 - mn0), corr1 = __expf(m1 - mn1);
        m0 = mn0; m1 = mn1;

        unsigned pa[4][4];
        float ps0 = 0.f, ps1 = 0.f;
        #pragma unroll
        for (int j = 0; j < 4; j++) {
            float p00 = __expf(sc[2*j][0]   - m0), p01 = __expf(sc[2*j][1]   - m0);
            float p02 = __expf(sc[2*j][2]   - m1), p03 = __expf(sc[2*j][3]   - m1);
            float p10 = __expf(sc[2*j+1][0] - m0), p11 = __expf(sc[2*j+1][1] - m0);
            float p12 = __expf(sc[2*j+1][2] - m1), p13 = __expf(sc[2*j+1][3] - m1);
            ps0 += p00 + p01 + p10 + p11;
            ps1 += p02 + p03 + p12 + p13;
            __half2 h0 = __floats2half2_rn(p00, p01);
            __half2 h1 = __floats2half2_rn(p02, p03);
            __half2 h2 = __floats2half2_rn(p10, p11);
            __half2 h3 = __floats2half2_rn(p12, p13);
            pa[j][0] = *(unsigned*)&h0;
            pa[j][1] = *(unsigned*)&h1;
            pa[j][2] = *(unsigned*)&h2;
            pa[j][3] = *(unsigned*)&h3;
        }
        ps0 += __shfl_xor_sync(0xffffffffu, ps0, 1);
        ps0 += __shfl_xor_sync(0xffffffffu, ps0, 2);
        ps1 += __shfl_xor_sync(0xffffffffu, ps1, 1);
        ps1 += __shfl_xor_sync(0xffffffffu, ps1, 2);
        l0 = l0*corr0 + ps0;
        l1 = l1*corr1 + ps1;

        #pragma unroll
        for (int nj = 0; nj < 8; nj++) {
            oa[nj][0] *= corr0; oa[nj][1] *= corr0;
            oa[nj][2] *= corr1; oa[nj][3] *= corr1;
        }

        #pragma unroll
        for (int j = 0; j < 4; j++) {
            unsigned vf[4][4];
            #pragma unroll
            for (int pd = 0; pd < 4; pd++) {
                int r = j*16 + (lane & 15);
                int cH = pd*16 + ((lane >> 4) << 3);
                ldm_x4t(vf[pd][0], vf[pd][1], vf[pd][2], vf[pd][3], uV[bb] + (r*ASTR + cH)*2);
            }
            #pragma unroll
            for (int dn = 0; dn < 8; dn++)
                mma16816(oa[dn][0], oa[dn][1], oa[dn][2], oa[dn][3],
                         pa[j][0], pa[j][1], pa[j][2], pa[j][3],
                         vf[dn >> 1][(dn & 1)*2], vf[dn >> 1][(dn & 1)*2 + 1]);
        }
        __syncthreads();
    }

    float il0 = 1.f/l0, il1 = 1.f/l1;
    int r0 = qb*64 + wid*16 + (lane >> 2);
    #pragma unroll
    for (int dn = 0; dn < 8; dn++) {
        int col = dn*8 + (lane & 3)*2;
        long o0 = ((long)(b*TT + r0)*HH + h)*DD + col;
        long o1 = ((long)(b*TT + r0 + 8)*HH + h)*DD + col;
        *(__half2*)(y + o0) = __floats2half2_rn(oa[dn][0]*il0, oa[dn][1]*il0);
        *(__half2*)(y + o1) = __floats2half2_rn(oa[dn][2]*il1, oa[dn][3]*il1);
    }
}

// ---------------- MoE router ----------------
__global__ void router_k(const float* __restrict__ hn, const float* __restrict__ rw,
                         int* __restrict__ idx2, float* __restrict__ wts2,
                         int* __restrict__ counts) {
    int warp = (blockIdx.x*blockDim.x + threadIdx.x) >> 5;
    int lane = threadIdx.x & 31;
    if (warp >= M0) return;
    float lg[EE];
    for (int e = 0; e < EE; e++) {
        float s = 0.f;
        for (int c = lane; c < CC; c += 32) s += hn[(long)warp*CC + c]*rw[(long)e*CC + c];
        for (int o = 16; o > 0; o >>= 1) s += __shfl_down_sync(0xffffffffu, s, o);
        lg[e] = __shfl_sync(0xffffffffu, s, 0);
    }
    if (lane == 0) {
        int i0 = 0;
        for (int e = 1; e < EE; e++) if (lg[e] > lg[i0]) i0 = e;
        int i1 = -1;
        for (int e = 0; e < EE; e++) {
            if (e == i0) continue;
            if (i1 < 0 || lg[e] > lg[i1]) i1 = e;
        }
        float e1 = __expf(lg[i1] - lg[i0]);
        float s  = 1.f + e1;
        idx2[warp*2]   = i0; idx2[warp*2+1] = i1;
        wts2[warp*2]   = 1.f/s; wts2[warp*2+1] = e1/s;
        atomicAdd(&counts[i0], 1); atomicAdd(&counts[i1], 1);
    }
}

__global__ void init_k(int* counts, int* perm, float* gatew) {
    int i = blockIdx.x*blockDim.x + threadIdx.x;
    if (i < EE) counts[i] = 0;
    if (i < MG) { perm[i] = 0; gatew[i] = 0.f; }
}

__global__ void offsets_k(const int* counts, int* poff, int* cursor) {
    if (threadIdx.x == 0 && blockIdx.x == 0) {
        int o = 0;
        for (int e = 0; e < EE; e++) {
            poff[e] = o; cursor[e] = 0;
            o += ((counts[e] + 127)/128)*128;
        }
        poff[EE] = o;
    }
}

__global__ void scatter_k(const int* __restrict__ idx2, const float* __restrict__ wts2,
                          int* __restrict__ cursor, const int* __restrict__ poff,
                          int* __restrict__ perm, float* __restrict__ gatew,
                          int* __restrict__ tokrow) {
    int t = blockIdx.x*blockDim.x + threadIdx.x;
    if (t >= M0) return;
    for (int kk = 0; kk < 2; kk++) {
        int e = idx2[t*2 + kk];
        int pos = atomicAdd(&cursor[e], 1);
        int r = poff[e] + pos;
        perm[r] = t; gatew[r] = wts2[t*2 + kk]; tokrow[t*2 + kk] = r;
    }
}

__global__ void final_k(const float* __restrict__ x2, const float* __restrict__ ctr,
                        const int* __restrict__ tokrow, float* __restrict__ out) {
    long i = (long)blockIdx.x*blockDim.x + threadIdx.x;
    if (i >= (long)M0*CC) return;
    int t = (int)(i >> 10);
    int c = (int)(i & (CC-1));
    int r0 = tokrow[t*2], r1 = tokrow[t*2+1];
    out[i] = x2[i] + ctr[(long)r0*CC + c] + ctr[(long)r1*CC + c];
}

// ---------------- launch ----------------
static void* sym(const void* s) { void* p = nullptr; cudaGetSymbolAddress(&p, s); return p; }

extern "C" void kernel_launch(void* const* d_in, const int* in_sizes, int n_in,
                              void* d_out, int out_size) {
    const float* x    = (const float*)d_in[0];
    const float* rc   = (const float*)d_in[1];
    const float* rs   = (const float*)d_in[2];
    const float* anw  = (const float*)d_in[3];
    const float* qw   = (const float*)d_in[4];
    const float* kw   = (const float*)d_in[5];
    const float* vw   = (const float*)d_in[6];
    const float* ow   = (const float*)d_in[7];
    const float* fnw  = (const float*)d_in[8];
    const float* rw   = (const float*)d_in[9];
    const float* w1   = (const float*)d_in[10];
    const float* w2   = (const float*)d_in[11];
    const float* w3   = (const float*)d_in[12];
    float* out = (float*)d_out;

    float*  x2    = (float*)sym(g_x2);
    float*  hn    = (float*)sym(g_hn);
    float*  ctr   = (float*)sym(g_ctr);
    __half* h16   = (__half*)sym(g_h16);
    __half* qkv16 = (__half*)sym(g_qkv16);
    __half* y16   = (__half*)sym(g_y16);
    __half* hn16  = (__half*)sym(g_hn16);
    __half* gb16  = (__half*)sym(g_gb16);
    __half* wqkv16= (__half*)sym(g_wqkv16);
    __half* ow16  = (__half*)sym(g_ow16);
    __half* w116  = (__half*)sym(g_w116);
    __half* w216  = (__half*)sym(g_w216);
    __half* w316  = (__half*)sym(g_w316);
    int*   counts = (int*)sym(g_counts);
    int*   cursor = (int*)sym(g_cursor);
    int*   poff   = (int*)sym(g_poff);
    int*   perm   = (int*)sym(g_perm);
    float* gatew  = (float*)sym(g_gatew);
    int*   idx2   = (int*)sym(g_idx2);
    float* wts2   = (float*)sym(g_wts2);
    int*   tokrow = (int*)sym(g_tokrow);

    const int MOE_SMEM = 6*GBM*LDP*2;   // 61440 bytes
    cudaFuncSetAttribute(moe13_k, cudaFuncAttributeMaxDynamicSharedMemorySize, MOE_SMEM);

    // 0) weight conversions to fp16
    int n4c = CC*CC/4;
    int n4e = EE*HDIM*CC/4;
    f2h_k<<<(n4c+255)/256, 256>>>(qw, wqkv16, n4c);
    f2h_k<<<(n4c+255)/256, 256>>>(kw, wqkv16 + CC*CC, n4c);
    f2h_k<<<(n4c+255)/256, 256>>>(vw, wqkv16 + 2*CC*CC, n4c);
    f2h_k<<<(n4c+255)/256, 256>>>(ow, ow16, n4c);
    f2h_k<<<(n4e+255)/256, 256>>>(w1, w116, n4e);
    f2h_k<<<(n4e+255)/256, 256>>>(w2, w216, n4e);
    f2h_k<<<(n4e+255)/256, 256>>>(w3, w316, n4e);

    // 1) attn rmsnorm (fp16 out)
    rmsnorm_k<<<M0, 256>>>(x, anw, nullptr, h16);
    // 2) fused QKV projection (fp16 out, packed rows of 3C)
    gemm16_k<<<dim3(3*CC/GBN, M0/GBM), 256>>>(h16, wqkv16, nullptr, qkv16, 3*CC, CC,
                                              nullptr, nullptr, nullptr, nullptr, 0);
    // 3) RoPE in-place (q scaled by 1/sqrt(D))
    rope_k<<<(M0*HH*32 + 255)/256, 256>>>(qkv16, rc, rs);
    // 4) causal flash attention
    fattn_k<<<dim3(TT/64, HH, BB), 128>>>(qkv16, y16);
    // 5) output projection + residual (fp32 out)
    gemm16_k<<<dim3(CC/GBN, M0/GBM), 256>>>(y16, ow16, x2, nullptr, CC, CC,
                                            x, nullptr, nullptr, nullptr, 0);
    // 6) ffn rmsnorm (fp32 for router + fp16 for experts)
    rmsnorm_k<<<M0, 256>>>(x2, fnw, hn, hn16);
    // 7) router + gather bookkeeping
    init_k<<<(MG + 255)/256, 256>>>(counts, perm, gatew);
    router_k<<<(M0*32 + 255)/256, 256>>>(hn, rw, idx2, wts2, counts);
    offsets_k<<<1, 32>>>(counts, poff, cursor);
    scatter_k<<<(M0 + 255)/256, 256>>>(idx2, wts2, cursor, poff, perm, gatew, tokrow);
    // 8) fused expert up-projection + silu*mul (fp16 out)
    moe13_k<<<dim3(HDIM/GBN, MG/GBM), 256, MOE_SMEM>>>(hn16, w116, w316, gb16, perm, poff);
    //    down-projection with gate scaling
    gemm16_k<<<dim3(CC/GBN, MG/GBM), 256>>>(gb16, w216, ctr, nullptr, CC, HDIM,
                                            nullptr, nullptr, poff, gatew, (long)CC*HDIM);
    // 9) combine
    final_k<<<(int)(((long)M0*CC + 255)/256), 256>>>(x2, ctr, tokrow, out);
}

// round 7
// speedup vs baseline: 6.4338x; 1.0053x over previous
#include <cuda_runtime.h>
#include <cuda_fp16.h>
#include <cstdint>
#include <stdint.h>
#include <math.h>

// ---------------- problem constants ----------------
#define BB 2
#define TT 2048
#define CC 1024
#define HH 16
#define DD 64
#define EE 8
#define HDIM 1536
#define M0 (BB*TT)
#define MG 9216
#define EPSV 1e-6f

#define N4C (CC*CC/4)
#define N4E (EE*HDIM*CC/4)
#define OFF_OW (3*CC*CC)
#define OFF_W1 (4*CC*CC)
#define OFF_W2 (OFF_W1 + EE*HDIM*CC)
#define OFF_W3 (OFF_W2 + EE*HDIM*CC)
#define W16TOT (OFF_W3 + EE*HDIM*CC)

// ---------------- device scratch ----------------
__device__ float  g_x2  [M0*CC];
__device__ float  g_hn  [M0*CC];
__device__ float  g_ctr [MG*CC];
__device__ __half g_h16 [M0*CC];
__device__ __half g_qkv16[M0*3*CC];
__device__ __half g_y16 [M0*CC];
__device__ __half g_hn16[M0*CC];
__device__ __half g_gb16[MG*HDIM];
__device__ __half g_w16all[W16TOT];
__device__ int    g_counts[EE];
__device__ int    g_cursor[EE];
__device__ int    g_poff[EE+1];
__device__ int    g_perm[MG];
__device__ float  g_gatew[MG];
__device__ int    g_idx2[M0*2];
__device__ float  g_wts2[M0*2];
__device__ int    g_tokrow[M0*2];

// ---------------- PTX helpers ----------------
__device__ __forceinline__ unsigned s2u(const void* p) {
    unsigned a;
    asm("{ .reg .u64 t; cvta.to.shared.u64 t, %1; cvt.u32.u64 %0, t; }" : "=r"(a) : "l"(p));
    return a;
}
__device__ __forceinline__ void ldm_x4(unsigned& r0, unsigned& r1, unsigned& r2, unsigned& r3, unsigned a) {
    asm volatile("ldmatrix.sync.aligned.m8n8.x4.shared.b16 {%0,%1,%2,%3}, [%4];"
                 : "=r"(r0), "=r"(r1), "=r"(r2), "=r"(r3) : "r"(a));
}
__device__ __forceinline__ void ldm_x4t(unsigned& r0, unsigned& r1, unsigned& r2, unsigned& r3, unsigned a) {
    asm volatile("ldmatrix.sync.aligned.m8n8.x4.trans.shared.b16 {%0,%1,%2,%3}, [%4];"
                 : "=r"(r0), "=r"(r1), "=r"(r2), "=r"(r3) : "r"(a));
}
__device__ __forceinline__ void mma16816(float& d0, float& d1, float& d2, float& d3,
                                         unsigned a0, unsigned a1, unsigned a2, unsigned a3,
                                         unsigned b0, unsigned b1) {
    asm volatile("mma.sync.aligned.m16n8k16.row.col.f32.f16.f16.f32 "
                 "{%0,%1,%2,%3}, {%4,%5,%6,%7}, {%8,%9}, {%0,%1,%2,%3};"
                 : "+f"(d0), "+f"(d1), "+f"(d2), "+f"(d3)
                 : "r"(a0), "r"(a1), "r"(a2), "r"(a3), "r"(b0), "r"(b1));
}
#define CPA16(dst, src) asm volatile("cp.async.cg.shared.global [%0], [%1], 16;" :: "r"(dst), "l"(src))

// ---------------- fused weight conversion: all fp32 weights -> packed fp16 arena ----------------
__global__ void convw_k(const float4* __restrict__ q, const float4* __restrict__ k,
                        const float4* __restrict__ v, const float4* __restrict__ o,
                        const float4* __restrict__ w1, const float4* __restrict__ w2,
                        const float4* __restrict__ w3, __half2* __restrict__ dst) {
    int i = blockIdx.x*blockDim.x + threadIdx.x;
    if (i >= 4*N4C + 3*N4E) return;
    const float4* s;
    long base;
    if (i < 4*N4C) {
        int seg = i / N4C, off = i - seg*N4C;
        s = (seg == 0 ? q : seg == 1 ? k : seg == 2 ? v : o) + off;
        base = (long)seg*N4C + off;
    } else {
        int j = i - 4*N4C;
        int seg = j / N4E, off = j - seg*N4E;
        s = (seg == 0 ? w1 : seg == 1 ? w2 : w3) + off;
        base = (long)4*N4C + (long)seg*N4E + off;
    }
    float4 val = *s;
    dst[base*2]   = __floats2half2_rn(val.x, val.y);
    dst[base*2+1] = __floats2half2_rn(val.z, val.w);
}

// ---------------- RMSNorm ----------------
__global__ void rmsnorm_k(const float* __restrict__ x, const float* __restrict__ w,
                          float* __restrict__ o32, __half* __restrict__ o16) {
    int row = blockIdx.x;
    const float* xr = x + (long)row*CC;
    __shared__ float red[256];
    float s = 0.f;
    for (int c = threadIdx.x; c < CC; c += 256) { float v = xr[c]; s += v*v; }
    red[threadIdx.x] = s; __syncthreads();
    for (int st = 128; st > 0; st >>= 1) {
        if (threadIdx.x < st) red[threadIdx.x] += red[threadIdx.x+st];
        __syncthreads();
    }
    float inv = rsqrtf(red[0]/(float)CC + EPSV);
    for (int c = threadIdx.x; c < CC; c += 256) {
        float v = w[c]*xr[c]*inv;
        if (o32) o32[(long)row*CC + c] = v;
        o16[(long)row*CC + c] = __float2half(v);
    }
}

// ---------------- HMMA fp16 GEMM, 3-stage cp.async pipeline ----------------
#define GBM 128
#define GBN 128
#define GBK 32
#define LDP 40
#define DSM_G (6*GBM*LDP*2)
__global__ __launch_bounds__(256)
void gemm16_k(const __half* __restrict__ A, const __half* __restrict__ Wb,
              float* __restrict__ Cout, __half* __restrict__ Cout16,
              int N, int K,
              const float* __restrict__ R,
              const int* __restrict__ perm,
              const int* __restrict__ poff,
              const float* __restrict__ rowscale,
              long wstride) {
    extern __shared__ __half gsm[];
    __shared__ int rowsrc[GBM];

    int tid = threadIdx.x, wid = tid >> 5, lane = tid & 31;
    int tileN = blockIdx.x, tileM = blockIdx.y;
    int row0 = tileM*GBM;

    const __half* W = Wb;
    if (poff) {
        int e = 0;
        #pragma unroll
        for (int q2 = 1; q2 < EE; q2++) if (row0 >= poff[q2]) e = q2;
        W += (long)e * wstride;
    }
    if (tid < GBM) rowsrc[tid] = perm ? perm[row0 + tid] : (row0 + tid);
    __syncthreads();

    int warp_m = (wid >> 2) * 64;
    int warp_n = (wid & 3) * 32;

    unsigned sA[3], sB[3];
    #pragma unroll
    for (int i = 0; i < 3; i++) {
        sA[i] = s2u(gsm + i*GBM*LDP);
        sB[i] = s2u(gsm + (3 + i)*GBM*LDP);
    }

    auto load_stage = [&](int s) {
        int b = s % 3;
        long k0 = (long)s * GBK;
        #pragma unroll
        for (int c = 0; c < 2; c++) {
            int id = tid + c*256;
            int r = id >> 2, ch = id & 3;
            CPA16(sA[b] + (r*LDP + ch*8)*2, A + (long)rowsrc[r]*K + k0 + ch*8);
            CPA16(sB[b] + (r*LDP + ch*8)*2, W + (long)(tileN*GBN + r)*K + k0 + ch*8);
        }
        asm volatile("cp.async.commit_group;");
    };

    float acc[4][4][4] = {};
    int ns = K / GBK;
    load_stage(0);
    load_stage(1);

    for (int s = 0; s < ns; s++) {
        if (s + 1 < ns) asm volatile("cp.async.wait_group 1;");
        else            asm volatile("cp.async.wait_group 0;");
        __syncthreads();
        if (s + 2 < ns) load_stage(s + 2);
        int b = s % 3;
        #pragma unroll
        for (int kk = 0; kk < 2; kk++) {
            unsigned af[4][4], bf[2][4];
            #pragma unroll
            for (int mi = 0; mi < 4; mi++) {
                int r = warp_m + mi*16 + (lane & 15);
                int cH = kk*16 + ((lane >> 4) << 3);
                ldm_x4(af[mi][0], af[mi][1], af[mi][2], af[mi][3], sA[b] + (r*LDP + cH)*2);
            }
            #pragma unroll
            for (int pj = 0; pj < 2; pj++) {
                int n = warp_n + pj*16 + (lane & 7) + ((lane >> 4) << 3);
                int cH = kk*16 + (((lane >> 3) & 1) << 3);
                ldm_x4(bf[pj][0], bf[pj][1], bf[pj][2], bf[pj][3], sB[b] + (n*LDP + cH)*2);
            }
            #pragma unroll
            for (int mi = 0; mi < 4; mi++)
                #pragma unroll
                for (int nj = 0; nj < 4; nj++)
                    mma16816(acc[mi][nj][0], acc[mi][nj][1], acc[mi][nj][2], acc[mi][nj][3],
                             af[mi][0], af[mi][1], af[mi][2], af[mi][3],
                             bf[nj >> 1][(nj & 1)*2], bf[nj >> 1][(nj & 1)*2 + 1]);
        }
    }

    int lrow = lane >> 2;
    int lcol = (lane & 3) * 2;
    #pragma unroll
    for (int mi = 0; mi < 4; mi++) {
        #pragma unroll
        for (int half = 0; half < 2; half++) {
            int grow = row0 + warp_m + mi*16 + lrow + half*8;
            float sc = rowscale ? rowscale[grow] : 1.f;
            long obase = (long)grow*N + tileN*GBN + warp_n;
            #pragma unroll
            for (int nj = 0; nj < 4; nj++) {
                float vx = acc[mi][nj][half*2 + 0] * sc;
                float vy = acc[mi][nj][half*2 + 1] * sc;
                long off = obase + nj*8 + lcol;
                if (Cout16) {
                    *(__half2*)(Cout16 + off) = __floats2half2_rn(vx, vy);
                } else {
                    if (R) {
                        const float2 rv = *(const float2*)(R + off);
                        vx += rv.x; vy += rv.y;
                    }
                    float2 vv = { vx, vy };
                    *(float2*)(Cout + off) = vv;
                }
            }
        }
    }
}

// ---------------- fused MoE w1/w3 GEMM + silu*mul -> fp16, 3-stage ----------------
#define DSM_M (9*GBM*LDP*2)
__global__ __launch_bounds__(256)
void moe13_k(const __half* __restrict__ A, const __half* __restrict__ W1b,
             const __half* __restrict__ W3b, __half* __restrict__ G,
             const int* __restrict__ perm, const int* __restrict__ poff) {
    extern __shared__ __half sm[];
    __shared__ int rowsrc[GBM];

    int tid = threadIdx.x, wid = tid >> 5, lane = tid & 31;
    int tileN = blockIdx.x, tileM = blockIdx.y;
    int row0 = tileM*GBM;
    const int K = CC;

    int e = 0;
    #pragma unroll
    for (int q2 = 1; q2 < EE; q2++) if (row0 >= poff[q2]) e = q2;
    const __half* W1 = W1b + (long)e*HDIM*CC;
    const __half* W3 = W3b + (long)e*HDIM*CC;

    if (tid < GBM) rowsrc[tid] = perm[row0 + tid];
    __syncthreads();

    int warp_m = (wid >> 2) * 64;
    int warp_n = (wid & 3) * 32;

    unsigned sA[3], sB1[3], sB3[3];
    #pragma unroll
    for (int i = 0; i < 3; i++) {
        sA[i]  = s2u(sm + i*GBM*LDP);
        sB1[i] = s2u(sm + (3 + i)*GBM*LDP);
        sB3[i] = s2u(sm + (6 + i)*GBM*LDP);
    }

    auto load_stage = [&](int s) {
        int b = s % 3;
        long k0 = (long)s * GBK;
        #pragma unroll
        for (int c = 0; c < 2; c++) {
            int id = tid + c*256;
            int r = id >> 2, ch = id & 3;
            CPA16(sA[b]  + (r*LDP + ch*8)*2, A  + (long)rowsrc[r]*K + k0 + ch*8);
            CPA16(sB1[b] + (r*LDP + ch*8)*2, W1 + (long)(tileN*GBN + r)*K + k0 + ch*8);
            CPA16(sB3[b] + (r*LDP + ch*8)*2, W3 + (long)(tileN*GBN + r)*K + k0 + ch*8);
        }
        asm volatile("cp.async.commit_group;");
    };

    float a1[4][4][4] = {};
    float a3[4][4][4] = {};
    int ns = K / GBK;
    load_stage(0);
    load_stage(1);

    for (int s = 0; s < ns; s++) {
        if (s + 1 < ns) asm volatile("cp.async.wait_group 1;");
        else            asm volatile("cp.async.wait_group 0;");
        __syncthreads();
        if (s + 2 < ns) load_stage(s + 2);
        int b = s % 3;
        #pragma unroll
        for (int kk = 0; kk < 2; kk++) {
            unsigned af[4][4], b1f[2][4], b3f[2][4];
            #pragma unroll
            for (int mi = 0; mi < 4; mi++) {
                int r = warp_m + mi*16 + (lane & 15);
                int cH = kk*16 + ((lane >> 4) << 3);
                ldm_x4(af[mi][0], af[mi][1], af[mi][2], af[mi][3], sA[b] + (r*LDP + cH)*2);
            }
            #pragma unroll
            for (int pj = 0; pj < 2; pj++) {
                int n = warp_n + pj*16 + (lane & 7) + ((lane >> 4) << 3);
                int cH = kk*16 + (((lane >> 3) & 1) << 3);
                ldm_x4(b1f[pj][0], b1f[pj][1], b1f[pj][2], b1f[pj][3], sB1[b] + (n*LDP + cH)*2);
                ldm_x4(b3f[pj][0], b3f[pj][1], b3f[pj][2], b3f[pj][3], sB3[b] + (n*LDP + cH)*2);
            }
            #pragma unroll
            for (int mi = 0; mi < 4; mi++)
                #pragma unroll
                for (int nj = 0; nj < 4; nj++) {
                    mma16816(a1[mi][nj][0], a1[mi][nj][1], a1[mi][nj][2], a1[mi][nj][3],
                             af[mi][0], af[mi][1], af[mi][2], af[mi][3],
                             b1f[nj >> 1][(nj & 1)*2], b1f[nj >> 1][(nj & 1)*2 + 1]);
                    mma16816(a3[mi][nj][0], a3[mi][nj][1], a3[mi][nj][2], a3[mi][nj][3],
                             af[mi][0], af[mi][1], af[mi][2], af[mi][3],
                             b3f[nj >> 1][(nj & 1)*2], b3f[nj >> 1][(nj & 1)*2 + 1]);
                }
        }
    }

    int lrow = lane >> 2;
    int lcol = (lane & 3) * 2;
    #pragma unroll
    for (int mi = 0; mi < 4; mi++) {
        #pragma unroll
        for (int half = 0; half < 2; half++) {
            int grow = row0 + warp_m + mi*16 + lrow + half*8;
            long obase = (long)grow*HDIM + tileN*GBN + warp_n;
            #pragma unroll
            for (int nj = 0; nj < 4; nj++) {
                float u0 = a1[mi][nj][half*2 + 0];
                float u1 = a1[mi][nj][half*2 + 1];
                float w0 = a3[mi][nj][half*2 + 0];
                float w1 = a3[mi][nj][half*2 + 1];
                float g0 = u0 / (1.f + __expf(-u0)) * w0;
                float g1 = u1 / (1.f + __expf(-u1)) * w1;
                *(__half2*)(G + obase + nj*8 + lcol) = __floats2half2_rn(g0, g1);
            }
        }
    }
}

// ---------------- RoPE in-place on packed fp16 qkv ----------------
__global__ void rope_k(__half* __restrict__ qkv,
                       const float* __restrict__ cs, const float* __restrict__ sn) {
    int idx = blockIdx.x*blockDim.x + threadIdx.x;
    if (idx >= M0*HH*32) return;
    int d  = idx & 31;
    int h  = (idx >> 5) & (HH-1);
    int bt = idx >> 9;
    int t  = bt & (TT-1);
    long base = (long)bt*(3*CC) + h*DD;
    float c1 = cs[t*DD + d], c2 = cs[t*DD + d + 32];
    float s1 = sn[t*DD + d], s2 = sn[t*DD + d + 32];
    float q1 = __half2float(qkv[base+d]), q2 = __half2float(qkv[base+d+32]);
    qkv[base+d]    = __float2half((q1*c1 - q2*s1) * 0.125f);
    qkv[base+d+32] = __float2half((q2*c2 + q1*s2) * 0.125f);
    float k1 = __half2float(qkv[base+CC+d]), k2 = __half2float(qkv[base+CC+d+32]);
    qkv[base+CC+d]    = __float2half(k1*c1 - k2*s1);
    qkv[base+CC+d+32] = __float2half(k2*c2 + k1*s2);
}

// ---------------- FlashAttention-2 style HMMA causal attention ----------------
#define ASTR 72
#define QKVS (3*CC)
__global__ __launch_bounds__(128)
void fattn_k(const __half* __restrict__ qkv, __half* __restrict__ y) {
    __shared__ __half sQ[64*ASTR];
    __shared__ __half sK[2][64*ASTR];
    __shared__ __half sV[2][64*ASTR];

    int qb = blockIdx.x, h = blockIdx.y, b = blockIdx.z;
    int tid = threadIdx.x, wid = tid >> 5, lane = tid & 31;

    unsigned uQ = s2u(sQ);
    unsigned uK[2] = { s2u(&sK[0][0]), s2u(&sK[1][0]) };
    unsigned uV[2] = { s2u(&sV[0][0]), s2u(&sV[1][0]) };

    long qbase = (long)(b*TT + qb*64)*QKVS + h*DD;
    #pragma unroll
    for (int c = 0; c < 4; c++) {
        int id = tid + c*128;
        int r = id >> 3, ch = id & 7;
        CPA16(uQ + (r*ASTR + ch*8)*2, qkv + qbase + (long)r*QKVS + ch*8);
    }
    asm volatile("cp.async.commit_group;");

    auto load_kv = [&](int s) {
        int bb = s & 1;
        long kvb = (long)(b*TT + s*64)*QKVS + h*DD + CC;
        #pragma unroll
        for (int c = 0; c < 4; c++) {
            int id = tid + c*128;
            int r = id >> 3, ch = id & 7;
            CPA16(uK[bb] + (r*ASTR + ch*8)*2, qkv + kvb + (long)r*QKVS + ch*8);
            CPA16(uV[bb] + (r*ASTR + ch*8)*2, qkv + kvb + CC + (long)r*QKVS + ch*8);
        }
        asm volatile("cp.async.commit_group;");
    };

    load_kv(0);
    asm volatile("cp.async.wait_group 0;");
    __syncthreads();

    unsigned qa[4][4];
    #pragma unroll
    for (int kk = 0; kk < 4; kk++) {
        int r = wid*16 + (lane & 15);
        int cH = kk*16 + ((lane >> 4) << 3);
        ldm_x4(qa[kk][0], qa[kk][1], qa[kk][2], qa[kk][3], uQ + (r*ASTR + cH)*2);
    }

    float m0 = -1e30f, m1 = -1e30f, l0 = 0.f, l1 = 0.f;
    float oa[8][4] = {};

    for (int kt = 0; kt <= qb; kt++) {
        if (kt + 1 <= qb) { load_kv(kt + 1); asm volatile("cp.async.wait_group 1;"); }
        else              { asm volatile("cp.async.wait_group 0;"); }
        __syncthreads();
        int bb = kt & 1;

        float sc[8][4] = {};
        #pragma unroll
        for (int kk = 0; kk < 4; kk++) {
            unsigned bf[4][4];
            #pragma unroll
            for (int pj = 0; pj < 4; pj++) {
                int n = pj*16 + (lane & 7) + ((lane >> 4) << 3);
                int cH = kk*16 + (((lane >> 3) & 1) << 3);
                ldm_x4(bf[pj][0], bf[pj][1], bf[pj][2], bf[pj][3], uK[bb] + (n*ASTR + cH)*2);
            }
            #pragma unroll
            for (int nj = 0; nj < 8; nj++)
                mma16816(sc[nj][0], sc[nj][1], sc[nj][2], sc[nj][3],
                         qa[kk][0], qa[kk][1], qa[kk][2], qa[kk][3],
                         bf[nj >> 1][(nj & 1)*2], bf[nj >> 1][(nj & 1)*2 + 1]);
        }

        if (kt == qb) {
            int r0 = wid*16 + (lane >> 2);
            #pragma unroll
            for (int nj = 0; nj < 8; nj++) {
                int c0 = nj*8 + (lane & 3)*2;
                if (c0     > r0)   sc[nj][0] = -1e30f;
                if (c0 + 1 > r0)   sc[nj][1] = -1e30f;
                if (c0     > r0+8) sc[nj][2] = -1e30f;
                if (c0 + 1 > r0+8) sc[nj][3] = -1e30f;
            }
        }

        float rm0 = -1e30f, rm1 = -1e30f;
        #pragma unroll
        for (int nj = 0; nj < 8; nj++) {
            rm0 = fmaxf(rm0, fmaxf(sc[nj][0], sc[nj][1]));
            rm1 = fmaxf(rm1, fmaxf(sc[nj][2], sc[nj][3]));
        }
        rm0 = fmaxf(rm0, __shfl_xor_sync(0xffffffffu, rm0, 1));
        rm0 = fmaxf(rm0, __shfl_xor_sync(0xffffffffu, rm0, 2));
        rm1 = fmaxf(rm1, __shfl_xor_sync(0xffffffffu, rm1, 1));
        rm1 = fmaxf(rm1, __shfl_xor_sync(0xffffffffu, rm1, 2));
        float mn0 = fmaxf(m0, rm0), mn1 = fmaxf(m1, rm1);
        float corr0 = __expf(m0 - mn0), corr1 = __expf(m1 - mn1);
        m0 = mn0; m1 = mn1;

        unsigned pa[4][4];
        float ps0 = 0.f, ps1 = 0.f;
        #pragma unroll
        for (int j = 0; j < 4; j++) {
            float p00 = __expf(sc[2*j][0]   - m0), p01 = __expf(sc[2*j][1]   - m0);
            float p02 = __expf(sc[2*j][2]   - m1), p03 = __expf(sc[2*j][3]   - m1);
            float p10 = __expf(sc[2*j+1][0] - m0), p11 = __expf(sc[2*j+1][1] - m0);
            float p12 = __expf(sc[2*j+1][2] - m1), p13 = __expf(sc[2*j+1][3] - m1);
            ps0 += p00 + p01 + p10 + p11;
            ps1 += p02 + p03 + p12 + p13;
            __half2 h0 = __floats2half2_rn(p00, p01);
            __half2 h1 = __floats2half2_rn(p02, p03);
            __half2 h2 = __floats2half2_rn(p10, p11);
            __half2 h3 = __floats2half2_rn(p12, p13);
            pa[j][0] = *(unsigned*)&h0;
            pa[j][1] = *(unsigned*)&h1;
            pa[j][2] = *(unsigned*)&h2;
            pa[j][3] = *(unsigned*)&h3;
        }
        ps0 += __shfl_xor_sync(0xffffffffu, ps0, 1);
        ps0 += __shfl_xor_sync(0xffffffffu, ps0, 2);
        ps1 += __shfl_xor_sync(0xffffffffu, ps1, 1);
        ps1 += __shfl_xor_sync(0xffffffffu, ps1, 2);
        l0 = l0*corr0 + ps0;
        l1 = l1*corr1 + ps1;

        #pragma unroll
        for (int nj = 0; nj < 8; nj++) {
            oa[nj][0] *= corr0; oa[nj][1] *= corr0;
            oa[nj][2] *= corr1; oa[nj][3] *= corr1;
        }

        #pragma unroll
        for (int j = 0; j < 4; j++) {
            unsigned vf[4][4];
            #pragma unroll
            for (int pd = 0; pd < 4; pd++) {
                int r = j*16 + (lane & 15);
                int cH = pd*16 + ((lane >> 4) << 3);
                ldm_x4t(vf[pd][0], vf[pd][1], vf[pd][2], vf[pd][3], uV[bb] + (r*ASTR + cH)*2);
            }
            #pragma unroll
            for (int dn = 0; dn < 8; dn++)
                mma16816(oa[dn][0], oa[dn][1], oa[dn][2], oa[dn][3],
                         pa[j][0], pa[j][1], pa[j][2], pa[j][3],
                         vf[dn >> 1][(dn & 1)*2], vf[dn >> 1][(dn & 1)*2 + 1]);
        }
        __syncthreads();
    }

    float il0 = 1.f/l0, il1 = 1.f/l1;
    int r0 = qb*64 + wid*16 + (lane >> 2);
    #pragma unroll
    for (int dn = 0; dn < 8; dn++) {
        int col = dn*8 + (lane & 3)*2;
        long o0 = ((long)(b*TT + r0)*HH + h)*DD + col;
        long o1 = ((long)(b*TT + r0 + 8)*HH + h)*DD + col;
        *(__half2*)(y + o0) = __floats2half2_rn(oa[dn][0]*il0, oa[dn][1]*il0);
        *(__half2*)(y + o1) = __floats2half2_rn(oa[dn][2]*il1, oa[dn][3]*il1);
    }
}

// ---------------- MoE router ----------------
__global__ void router_k(const float* __restrict__ hn, const float* __restrict__ rw,
                         int* __restrict__ idx2, float* __restrict__ wts2,
                         int* __restrict__ counts) {
    int warp = (blockIdx.x*blockDim.x + threadIdx.x) >> 5;
    int lane = threadIdx.x & 31;
    if (warp >= M0) return;
    float lg[EE];
    for (int e = 0; e < EE; e++) {
        float s = 0.f;
        for (int c = lane; c < CC; c += 32) s += hn[(long)warp*CC + c]*rw[(long)e*CC + c];
        for (int o = 16; o > 0; o >>= 1) s += __shfl_down_sync(0xffffffffu, s, o);
        lg[e] = __shfl_sync(0xffffffffu, s, 0);
    }
    if (lane == 0) {
        int i0 = 0;
        for (int e = 1; e < EE; e++) if (lg[e] > lg[i0]) i0 = e;
        int i1 = -1;
        for (int e = 0; e < EE; e++) {
            if (e == i0) continue;
            if (i1 < 0 || lg[e] > lg[i1]) i1 = e;
        }
        float e1 = __expf(lg[i1] - lg[i0]);
        float s  = 1.f + e1;
        idx2[warp*2]   = i0; idx2[warp*2+1] = i1;
        wts2[warp*2]   = 1.f/s; wts2[warp*2+1] = e1/s;
        atomicAdd(&counts[i0], 1); atomicAdd(&counts[i1], 1);
    }
}

__global__ void init_k(int* counts, int* perm, float* gatew) {
    int i = blockIdx.x*blockDim.x + threadIdx.x;
    if (i < EE) counts[i] = 0;
    if (i < MG) { perm[i] = 0; gatew[i] = 0.f; }
}

__global__ void offsets_k(const int* counts, int* poff, int* cursor) {
    if (threadIdx.x == 0 && blockIdx.x == 0) {
        int o = 0;
        for (int e = 0; e < EE; e++) {
            poff[e] = o; cursor[e] = 0;
            o += ((counts[e] + 127)/128)*128;
        }
        poff[EE] = o;
    }
}

__global__ void scatter_k(const int* __restrict__ idx2, const float* __restrict__ wts2,
                          int* __restrict__ cursor, const int* __restrict__ poff,
                          int* __restrict__ perm, float* __restrict__ gatew,
                          int* __restrict__ tokrow) {
    int t = blockIdx.x*blockDim.x + threadIdx.x;
    if (t >= M0) return;
    for (int kk = 0; kk < 2; kk++) {
        int e = idx2[t*2 + kk];
        int pos = atomicAdd(&cursor[e], 1);
        int r = poff[e] + pos;
        perm[r] = t; gatew[r] = wts2[t*2 + kk]; tokrow[t*2 + kk] = r;
    }
}

__global__ void final_k(const float* __restrict__ x2, const float* __restrict__ ctr,
                        const int* __restrict__ tokrow, float* __restrict__ out) {
    long i = (long)blockIdx.x*blockDim.x + threadIdx.x;
    if (i >= (long)M0*CC) return;
    int t = (int)(i >> 10);
    int c = (int)(i & (CC-1));
    int r0 = tokrow[t*2], r1 = tokrow[t*2+1];
    out[i] = x2[i] + ctr[(long)r0*CC + c] + ctr[(long)r1*CC + c];
}

// ---------------- launch ----------------
static void* sym(const void* s) { void* p = nullptr; cudaGetSymbolAddress(&p, s); return p; }

extern "C" void kernel_launch(void* const* d_in, const int* in_sizes, int n_in,
                              void* d_out, int out_size) {
    const float* x    = (const float*)d_in[0];
    const float* rc   = (const float*)d_in[1];
    const float* rs   = (const float*)d_in[2];
    const float* anw  = (const float*)d_in[3];
    const float* qw   = (const float*)d_in[4];
    const float* kw   = (const float*)d_in[5];
    const float* vw   = (const float*)d_in[6];
    const float* ow   = (const float*)d_in[7];
    const float* fnw  = (const float*)d_in[8];
    const float* rw   = (const float*)d_in[9];
    const float* w1   = (const float*)d_in[10];
    const float* w2   = (const float*)d_in[11];
    const float* w3   = (const float*)d_in[12];
    float* out = (float*)d_out;

    float*  x2    = (float*)sym(g_x2);
    float*  hn    = (float*)sym(g_hn);
    float*  ctr   = (float*)sym(g_ctr);
    __half* h16   = (__half*)sym(g_h16);
    __half* qkv16 = (__half*)sym(g_qkv16);
    __half* y16   = (__half*)sym(g_y16);
    __half* hn16  = (__half*)sym(g_hn16);
    __half* gb16  = (__half*)sym(g_gb16);
    __half* w16   = (__half*)sym(g_w16all);
    __half* wqkv16= w16;
    __half* ow16  = w16 + OFF_OW;
    __half* w116  = w16 + OFF_W1;
    __half* w216  = w16 + OFF_W2;
    __half* w316  = w16 + OFF_W3;
    int*   counts = (int*)sym(g_counts);
    int*   cursor = (int*)sym(g_cursor);
    int*   poff   = (int*)sym(g_poff);
    int*   perm   = (int*)sym(g_perm);
    float* gatew  = (float*)sym(g_gatew);
    int*   idx2   = (int*)sym(g_idx2);
    float* wts2   = (float*)sym(g_wts2);
    int*   tokrow = (int*)sym(g_tokrow);

    cudaFuncSetAttribute(gemm16_k, cudaFuncAttributeMaxDynamicSharedMemorySize, DSM_G);
    cudaFuncSetAttribute(moe13_k, cudaFuncAttributeMaxDynamicSharedMemorySize, DSM_M);

    // 0) fused weight conversion (one kernel, full-chip BW)
    int ncv = 4*N4C + 3*N4E;
    convw_k<<<(ncv + 255)/256, 256>>>((const float4*)qw, (const float4*)kw, (const float4*)vw,
                                      (const float4*)ow, (const float4*)w1, (const float4*)w2,
                                      (const float4*)w3, (__half2*)w16);
    // 1) attn rmsnorm (fp16 out)
    rmsnorm_k<<<M0, 256>>>(x, anw, nullptr, h16);
    // 2) fused QKV projection (fp16 out, packed rows of 3C)
    gemm16_k<<<dim3(3*CC/GBN, M0/GBM), 256, DSM_G>>>(h16, wqkv16, nullptr, qkv16, 3*CC, CC,
                                                     nullptr, nullptr, nullptr, nullptr, 0);
    // 3) RoPE in-place (q scaled by 1/sqrt(D))
    rope_k<<<(M0*HH*32 + 255)/256, 256>>>(qkv16, rc, rs);
    // 4) causal flash attention
    fattn_k<<<dim3(TT/64, HH, BB), 128>>>(qkv16, y16);
    // 5) output projection + residual (fp32 out)  <- ncu capture slot
    gemm16_k<<<dim3(CC/GBN, M0/GBM), 256, DSM_G>>>(y16, ow16, x2, nullptr, CC, CC,
                                                   x, nullptr, nullptr, nullptr, 0);
    // 6) ffn rmsnorm (fp32 for router + fp16 for experts)
    rmsnorm_k<<<M0, 256>>>(x2, fnw, hn, hn16);
    // 7) router + gather bookkeeping
    init_k<<<(MG + 255)/256, 256>>>(counts, perm, gatew);
    router_k<<<(M0*32 + 255)/256, 256>>>(hn, rw, idx2, wts2, counts);
    offsets_k<<<1, 32>>>(counts, poff, cursor);
    scatter_k<<<(M0 + 255)/256, 256>>>(idx2, wts2, cursor, poff, perm, gatew, tokrow);
    // 8) fused expert up-projection + silu*mul (fp16 out)
    moe13_k<<<dim3(HDIM/GBN, MG/GBM), 256, DSM_M>>>(hn16, w116, w316, gb16, perm, poff);
    //    down-projection with gate scaling
    gemm16_k<<<dim3(CC/GBN, MG/GBM), 256, DSM_G>>>(gb16, w216, ctr, nullptr, CC, HDIM,
                                                   nullptr, nullptr, poff, gatew, (long)CC*HDIM);
    // 9) combine
    final_k<<<(int)(((long)M0*CC + 255)/256), 256>>>(x2, ctr, tokrow, out);
}

// round 8
// speedup vs baseline: 6.5939x; 1.0249x over previous
#include <cuda_runtime.h>
#include <cuda_fp16.h>
#include <cstdint>
#include <stdint.h>
#include <math.h>

// ---------------- problem constants ----------------
#define BB 2
#define TT 2048
#define CC 1024
#define HH 16
#define DD 64
#define EE 8
#define HDIM 1536
#define M0 (BB*TT)
#define MG 9216
#define EPSV 1e-6f

#define N4C (CC*CC/4)
#define N4E (EE*HDIM*CC/4)
#define OFF_OW (3*CC*CC)
#define OFF_W1 (4*CC*CC)
#define OFF_W2 (OFF_W1 + EE*HDIM*CC)
#define OFF_W3 (OFF_W2 + EE*HDIM*CC)
#define W16TOT (OFF_W3 + EE*HDIM*CC)

// ---------------- device scratch ----------------
__device__ float  g_hn  [M0*CC];
__device__ __half g_h16 [M0*CC];
__device__ __half g_qkv16[M0*3*CC];
__device__ __half g_y16 [M0*CC];
__device__ __half g_hn16[M0*CC];
__device__ __half g_gb16[MG*HDIM];
__device__ __half g_w16all[W16TOT];
__device__ int    g_counts[EE];
__device__ int    g_cursor[EE];
__device__ int    g_poff[EE+1];
__device__ int    g_perm[MG];
__device__ float  g_gatew[MG];
__device__ int    g_idx2[M0*2];
__device__ float  g_wts2[M0*2];

// ---------------- PTX helpers ----------------
__device__ __forceinline__ unsigned s2u(const void* p) {
    unsigned a;
    asm("{ .reg .u64 t; cvta.to.shared.u64 t, %1; cvt.u32.u64 %0, t; }" : "=r"(a) : "l"(p));
    return a;
}
__device__ __forceinline__ void ldm_x4(unsigned& r0, unsigned& r1, unsigned& r2, unsigned& r3, unsigned a) {
    asm volatile("ldmatrix.sync.aligned.m8n8.x4.shared.b16 {%0,%1,%2,%3}, [%4];"
                 : "=r"(r0), "=r"(r1), "=r"(r2), "=r"(r3) : "r"(a));
}
__device__ __forceinline__ void ldm_x4t(unsigned& r0, unsigned& r1, unsigned& r2, unsigned& r3, unsigned a) {
    asm volatile("ldmatrix.sync.aligned.m8n8.x4.trans.shared.b16 {%0,%1,%2,%3}, [%4];"
                 : "=r"(r0), "=r"(r1), "=r"(r2), "=r"(r3) : "r"(a));
}
__device__ __forceinline__ void mma16816(float& d0, float& d1, float& d2, float& d3,
                                         unsigned a0, unsigned a1, unsigned a2, unsigned a3,
                                         unsigned b0, unsigned b1) {
    asm volatile("mma.sync.aligned.m16n8k16.row.col.f32.f16.f16.f32 "
                 "{%0,%1,%2,%3}, {%4,%5,%6,%7}, {%8,%9}, {%0,%1,%2,%3};"
                 : "+f"(d0), "+f"(d1), "+f"(d2), "+f"(d3)
                 : "r"(a0), "r"(a1), "r"(a2), "r"(a3), "r"(b0), "r"(b1));
}
#define CPA16(dst, src) asm volatile("cp.async.cg.shared.global [%0], [%1], 16;" :: "r"(dst), "l"(src))

// ---------------- fused weight conversion ----------------
__global__ void convw_k(const float4* __restrict__ q, const float4* __restrict__ k,
                        const float4* __restrict__ v, const float4* __restrict__ o,
                        const float4* __restrict__ w1, const float4* __restrict__ w2,
                        const float4* __restrict__ w3, __half2* __restrict__ dst) {
    int i = blockIdx.x*blockDim.x + threadIdx.x;
    if (i >= 4*N4C + 3*N4E) return;
    const float4* s;
    long base;
    if (i < 4*N4C) {
        int seg = i / N4C, off = i - seg*N4C;
        s = (seg == 0 ? q : seg == 1 ? k : seg == 2 ? v : o) + off;
        base = (long)seg*N4C + off;
    } else {
        int j = i - 4*N4C;
        int seg = j / N4E, off = j - seg*N4E;
        s = (seg == 0 ? w1 : seg == 1 ? w2 : w3) + off;
        base = (long)4*N4C + (long)seg*N4E + off;
    }
    float4 val = *s;
    dst[base*2]   = __floats2half2_rn(val.x, val.y);
    dst[base*2+1] = __floats2half2_rn(val.z, val.w);
}

// ---------------- RMSNorm ----------------
__global__ void rmsnorm_k(const float* __restrict__ x, const float* __restrict__ w,
                          float* __restrict__ o32, __half* __restrict__ o16) {
    int row = blockIdx.x;
    const float* xr = x + (long)row*CC;
    __shared__ float red[256];
    float s = 0.f;
    for (int c = threadIdx.x; c < CC; c += 256) { float v = xr[c]; s += v*v; }
    red[threadIdx.x] = s; __syncthreads();
    for (int st = 128; st > 0; st >>= 1) {
        if (threadIdx.x < st) red[threadIdx.x] += red[threadIdx.x+st];
        __syncthreads();
    }
    float inv = rsqrtf(red[0]/(float)CC + EPSV);
    for (int c = threadIdx.x; c < CC; c += 256) {
        float v = w[c]*xr[c]*inv;
        if (o32) o32[(long)row*CC + c] = v;
        o16[(long)row*CC + c] = __float2half(v);
    }
}

// ---------------- HMMA fp16 GEMM, 3-stage; optional scatter-atomic epilogue ----------------
#define GBM 128
#define GBN 128
#define GBK 32
#define LDP 40
#define DSM_G (6*GBM*LDP*2)
__global__ __launch_bounds__(256)
void gemm16_k(const __half* __restrict__ A, const __half* __restrict__ Wb,
              float* __restrict__ Cout, __half* __restrict__ Cout16,
              int N, int K,
              const float* __restrict__ R,
              const int* __restrict__ perm,
              const int* __restrict__ poff,
              const float* __restrict__ rowscale,
              long wstride,
              const int* __restrict__ sperm) {
    extern __shared__ __half gsm[];
    __shared__ int rowsrc[GBM];

    int tid = threadIdx.x, wid = tid >> 5, lane = tid & 31;
    int tileN = blockIdx.x, tileM = blockIdx.y;
    int row0 = tileM*GBM;

    const __half* W = Wb;
    if (poff) {
        int e = 0;
        #pragma unroll
        for (int q2 = 1; q2 < EE; q2++) if (row0 >= poff[q2]) e = q2;
        W += (long)e * wstride;
    }
    if (tid < GBM) rowsrc[tid] = perm ? perm[row0 + tid] : (row0 + tid);
    __syncthreads();

    int warp_m = (wid >> 2) * 64;
    int warp_n = (wid & 3) * 32;

    unsigned sA[3], sB[3];
    #pragma unroll
    for (int i = 0; i < 3; i++) {
        sA[i] = s2u(gsm + i*GBM*LDP);
        sB[i] = s2u(gsm + (3 + i)*GBM*LDP);
    }

    auto load_stage = [&](int s) {
        int b = s % 3;
        long k0 = (long)s * GBK;
        #pragma unroll
        for (int c = 0; c < 2; c++) {
            int id = tid + c*256;
            int r = id >> 2, ch = id & 3;
            CPA16(sA[b] + (r*LDP + ch*8)*2, A + (long)rowsrc[r]*K + k0 + ch*8);
            CPA16(sB[b] + (r*LDP + ch*8)*2, W + (long)(tileN*GBN + r)*K + k0 + ch*8);
        }
        asm volatile("cp.async.commit_group;");
    };

    float acc[4][4][4] = {};
    int ns = K / GBK;
    load_stage(0);
    load_stage(1);

    for (int s = 0; s < ns; s++) {
        if (s + 1 < ns) asm volatile("cp.async.wait_group 1;");
        else            asm volatile("cp.async.wait_group 0;");
        __syncthreads();
        if (s + 2 < ns) load_stage(s + 2);
        int b = s % 3;
        #pragma unroll
        for (int kk = 0; kk < 2; kk++) {
            unsigned af[4][4], bf[2][4];
            #pragma unroll
            for (int mi = 0; mi < 4; mi++) {
                int r = warp_m + mi*16 + (lane & 15);
                int cH = kk*16 + ((lane >> 4) << 3);
                ldm_x4(af[mi][0], af[mi][1], af[mi][2], af[mi][3], sA[b] + (r*LDP + cH)*2);
            }
            #pragma unroll
            for (int pj = 0; pj < 2; pj++) {
                int n = warp_n + pj*16 + (lane & 7) + ((lane >> 4) << 3);
                int cH = kk*16 + (((lane >> 3) & 1) << 3);
                ldm_x4(bf[pj][0], bf[pj][1], bf[pj][2], bf[pj][3], sB[b] + (n*LDP + cH)*2);
            }
            #pragma unroll
            for (int mi = 0; mi < 4; mi++)
                #pragma unroll
                for (int nj = 0; nj < 4; nj++)
                    mma16816(acc[mi][nj][0], acc[mi][nj][1], acc[mi][nj][2], acc[mi][nj][3],
                             af[mi][0], af[mi][1], af[mi][2], af[mi][3],
                             bf[nj >> 1][(nj & 1)*2], bf[nj >> 1][(nj & 1)*2 + 1]);
        }
    }

    int lrow = lane >> 2;
    int lcol = (lane & 3) * 2;
    #pragma unroll
    for (int mi = 0; mi < 4; mi++) {
        #pragma unroll
        for (int half = 0; half < 2; half++) {
            int grow = row0 + warp_m + mi*16 + lrow + half*8;
            float sc = rowscale ? rowscale[grow] : 1.f;
            if (sperm) {
                if (sc != 0.f) {
                    int token = sperm[grow];
                    long obase = (long)token*N + tileN*GBN + warp_n;
                    #pragma unroll
                    for (int nj = 0; nj < 4; nj++) {
                        long off = obase + nj*8 + lcol;
                        atomicAdd(&Cout[off],     acc[mi][nj][half*2 + 0] * sc);
                        atomicAdd(&Cout[off + 1], acc[mi][nj][half*2 + 1] * sc);
                    }
                }
            } else {
                long obase = (long)grow*N + tileN*GBN + warp_n;
                #pragma unroll
                for (int nj = 0; nj < 4; nj++) {
                    float vx = acc[mi][nj][half*2 + 0] * sc;
                    float vy = acc[mi][nj][half*2 + 1] * sc;
                    long off = obase + nj*8 + lcol;
                    if (Cout16) {
                        *(__half2*)(Cout16 + off) = __floats2half2_rn(vx, vy);
                    } else {
                        if (R) {
                            const float2 rv = *(const float2*)(R + off);
                            vx += rv.x; vy += rv.y;
                        }
                        float2 vv = { vx, vy };
                        *(float2*)(Cout + off) = vv;
                    }
                }
            }
        }
    }
}

// ---------------- fused MoE w1/w3 GEMM + silu*mul -> fp16, 3-stage ----------------
#define DSM_M (9*GBM*LDP*2)
__global__ __launch_bounds__(256)
void moe13_k(const __half* __restrict__ A, const __half* __restrict__ W1b,
             const __half* __restrict__ W3b, __half* __restrict__ G,
             const int* __restrict__ perm, const int* __restrict__ poff) {
    extern __shared__ __half sm[];
    __shared__ int rowsrc[GBM];

    int tid = threadIdx.x, wid = tid >> 5, lane = tid & 31;
    int tileN = blockIdx.x, tileM = blockIdx.y;
    int row0 = tileM*GBM;
    const int K = CC;

    int e = 0;
    #pragma unroll
    for (int q2 = 1; q2 < EE; q2++) if (row0 >= poff[q2]) e = q2;
    const __half* W1 = W1b + (long)e*HDIM*CC;
    const __half* W3 = W3b + (long)e*HDIM*CC;

    if (tid < GBM) rowsrc[tid] = perm[row0 + tid];
    __syncthreads();

    int warp_m = (wid >> 2) * 64;
    int warp_n = (wid & 3) * 32;

    unsigned sA[3], sB1[3], sB3[3];
    #pragma unroll
    for (int i = 0; i < 3; i++) {
        sA[i]  = s2u(sm + i*GBM*LDP);
        sB1[i] = s2u(sm + (3 + i)*GBM*LDP);
        sB3[i] = s2u(sm + (6 + i)*GBM*LDP);
    }

    auto load_stage = [&](int s) {
        int b = s % 3;
        long k0 = (long)s * GBK;
        #pragma unroll
        for (int c = 0; c < 2; c++) {
            int id = tid + c*256;
            int r = id >> 2, ch = id & 3;
            CPA16(sA[b]  + (r*LDP + ch*8)*2, A  + (long)rowsrc[r]*K + k0 + ch*8);
            CPA16(sB1[b] + (r*LDP + ch*8)*2, W1 + (long)(tileN*GBN + r)*K + k0 + ch*8);
            CPA16(sB3[b] + (r*LDP + ch*8)*2, W3 + (long)(tileN*GBN + r)*K + k0 + ch*8);
        }
        asm volatile("cp.async.commit_group;");
    };

    float a1[4][4][4] = {};
    float a3[4][4][4] = {};
    int ns = K / GBK;
    load_stage(0);
    load_stage(1);

    for (int s = 0; s < ns; s++) {
        if (s + 1 < ns) asm volatile("cp.async.wait_group 1;");
        else            asm volatile("cp.async.wait_group 0;");
        __syncthreads();
        if (s + 2 < ns) load_stage(s + 2);
        int b = s % 3;
        #pragma unroll
        for (int kk = 0; kk < 2; kk++) {
            unsigned af[4][4], b1f[2][4], b3f[2][4];
            #pragma unroll
            for (int mi = 0; mi < 4; mi++) {
                int r = warp_m + mi*16 + (lane & 15);
                int cH = kk*16 + ((lane >> 4) << 3);
                ldm_x4(af[mi][0], af[mi][1], af[mi][2], af[mi][3], sA[b] + (r*LDP + cH)*2);
            }
            #pragma unroll
            for (int pj = 0; pj < 2; pj++) {
                int n = warp_n + pj*16 + (lane & 7) + ((lane >> 4) << 3);
                int cH = kk*16 + (((lane >> 3) & 1) << 3);
                ldm_x4(b1f[pj][0], b1f[pj][1], b1f[pj][2], b1f[pj][3], sB1[b] + (n*LDP + cH)*2);
                ldm_x4(b3f[pj][0], b3f[pj][1], b3f[pj][2], b3f[pj][3], sB3[b] + (n*LDP + cH)*2);
            }
            #pragma unroll
            for (int mi = 0; mi < 4; mi++)
                #pragma unroll
                for (int nj = 0; nj < 4; nj++) {
                    mma16816(a1[mi][nj][0], a1[mi][nj][1], a1[mi][nj][2], a1[mi][nj][3],
                             af[mi][0], af[mi][1], af[mi][2], af[mi][3],
                             b1f[nj >> 1][(nj & 1)*2], b1f[nj >> 1][(nj & 1)*2 + 1]);
                    mma16816(a3[mi][nj][0], a3[mi][nj][1], a3[mi][nj][2], a3[mi][nj][3],
                             af[mi][0], af[mi][1], af[mi][2], af[mi][3],
                             b3f[nj >> 1][(nj & 1)*2], b3f[nj >> 1][(nj & 1)*2 + 1]);
                }
        }
    }

    int lrow = lane >> 2;
    int lcol = (lane & 3) * 2;
    #pragma unroll
    for (int mi = 0; mi < 4; mi++) {
        #pragma unroll
        for (int half = 0; half < 2; half++) {
            int grow = row0 + warp_m + mi*16 + lrow + half*8;
            long obase = (long)grow*HDIM + tileN*GBN + warp_n;
            #pragma unroll
            for (int nj = 0; nj < 4; nj++) {
                float u0 = a1[mi][nj][half*2 + 0];
                float u1 = a1[mi][nj][half*2 + 1];
                float w0 = a3[mi][nj][half*2 + 0];
                float w1 = a3[mi][nj][half*2 + 1];
                float g0 = u0 / (1.f + __expf(-u0)) * w0;
                float g1 = u1 / (1.f + __expf(-u1)) * w1;
                *(__half2*)(G + obase + nj*8 + lcol) = __floats2half2_rn(g0, g1);
            }
        }
    }
}

// ---------------- RoPE in-place on packed fp16 qkv ----------------
__global__ void rope_k(__half* __restrict__ qkv,
                       const float* __restrict__ cs, const float* __restrict__ sn) {
    int idx = blockIdx.x*blockDim.x + threadIdx.x;
    if (idx >= M0*HH*32) return;
    int d  = idx & 31;
    int h  = (idx >> 5) & (HH-1);
    int bt = idx >> 9;
    int t  = bt & (TT-1);
    long base = (long)bt*(3*CC) + h*DD;
    float c1 = cs[t*DD + d], c2 = cs[t*DD + d + 32];
    float s1 = sn[t*DD + d], s2 = sn[t*DD + d + 32];
    float q1 = __half2float(qkv[base+d]), q2 = __half2float(qkv[base+d+32]);
    qkv[base+d]    = __float2half((q1*c1 - q2*s1) * 0.125f);
    qkv[base+d+32] = __float2half((q2*c2 + q1*s2) * 0.125f);
    float k1 = __half2float(qkv[base+CC+d]), k2 = __half2float(qkv[base+CC+d+32]);
    qkv[base+CC+d]    = __float2half(k1*c1 - k2*s1);
    qkv[base+CC+d+32] = __float2half(k2*c2 + k1*s2);
}

// ---------------- FlashAttention-2 HMMA causal attention, 128-query tiles ----------------
#define ASTR 72
#define QKVS (3*CC)
#define FQT 128
#define DSM_F ((FQT*ASTR + 4*64*ASTR)*2)
__global__ __launch_bounds__(256)
void fattn_k(const __half* __restrict__ qkv, __half* __restrict__ y) {
    extern __shared__ __half fsm[];
    int qb = (int)gridDim.x - 1 - (int)blockIdx.x;   // heavy diagonal blocks first
    int h = blockIdx.y, b = blockIdx.z;
    int tid = threadIdx.x, wid = tid >> 5, lane = tid & 31;

    unsigned uQ = s2u(fsm);
    unsigned uK[2] = { s2u(fsm + FQT*ASTR),              s2u(fsm + FQT*ASTR + 64*ASTR) };
    unsigned uV[2] = { s2u(fsm + FQT*ASTR + 2*64*ASTR),  s2u(fsm + FQT*ASTR + 3*64*ASTR) };

    long qbase = (long)(b*TT + qb*FQT)*QKVS + h*DD;
    #pragma unroll
    for (int c = 0; c < 4; c++) {
        int id = tid + c*256;
        int r = id >> 3, ch = id & 7;
        CPA16(uQ + (r*ASTR + ch*8)*2, qkv + qbase + (long)r*QKVS + ch*8);
    }
    asm volatile("cp.async.commit_group;");

    auto load_kv = [&](int s) {
        int bb = s & 1;
        long kvb = (long)(b*TT + s*64)*QKVS + h*DD + CC;
        #pragma unroll
        for (int c = 0; c < 2; c++) {
            int id = tid + c*256;
            int r = id >> 3, ch = id & 7;
            CPA16(uK[bb] + (r*ASTR + ch*8)*2, qkv + kvb + (long)r*QKVS + ch*8);
            CPA16(uV[bb] + (r*ASTR + ch*8)*2, qkv + kvb + CC + (long)r*QKVS + ch*8);
        }
        asm volatile("cp.async.commit_group;");
    };

    load_kv(0);
    asm volatile("cp.async.wait_group 0;");
    __syncthreads();

    unsigned qa[4][4];
    #pragma unroll
    for (int kk = 0; kk < 4; kk++) {
        int r = wid*16 + (lane & 15);
        int cH = kk*16 + ((lane >> 4) << 3);
        ldm_x4(qa[kk][0], qa[kk][1], qa[kk][2], qa[kk][3], uQ + (r*ASTR + cH)*2);
    }

    float m0 = -1e30f, m1 = -1e30f, l0 = 0.f, l1 = 0.f;
    float oa[8][4] = {};
    int nkt = 2*qb + 2;

    for (int kt = 0; kt < nkt; kt++) {
        if (kt + 1 < nkt) { load_kv(kt + 1); asm volatile("cp.async.wait_group 1;"); }
        else              { asm volatile("cp.async.wait_group 0;"); }
        __syncthreads();
        int bb = kt & 1;

        float sc[8][4] = {};
        #pragma unroll
        for (int kk = 0; kk < 4; kk++) {
            unsigned bf[4][4];
            #pragma unroll
            for (int pj = 0; pj < 4; pj++) {
                int n = pj*16 + (lane & 7) + ((lane >> 4) << 3);
                int cH = kk*16 + (((lane >> 3) & 1) << 3);
                ldm_x4(bf[pj][0], bf[pj][1], bf[pj][2], bf[pj][3], uK[bb] + (n*ASTR + cH)*2);
            }
            #pragma unroll
            for (int nj = 0; nj < 8; nj++)
                mma16816(sc[nj][0], sc[nj][1], sc[nj][2], sc[nj][3],
                         qa[kk][0], qa[kk][1], qa[kk][2], qa[kk][3],
                         bf[nj >> 1][(nj & 1)*2], bf[nj >> 1][(nj & 1)*2 + 1]);
        }

        if (kt >= 2*qb) {
            int rg = qb*FQT + wid*16 + (lane >> 2);
            #pragma unroll
            for (int nj = 0; nj < 8; nj++) {
                int cg = kt*64 + nj*8 + (lane & 3)*2;
                if (cg     > rg)   sc[nj][0] = -1e30f;
                if (cg + 1 > rg)   sc[nj][1] = -1e30f;
                if (cg     > rg+8) sc[nj][2] = -1e30f;
                if (cg + 1 > rg+8) sc[nj][3] = -1e30f;
            }
        }

        float rm0 = -1e30f, rm1 = -1e30f;
        #pragma unroll
        for (int nj = 0; nj < 8; nj++) {
            rm0 = fmaxf(rm0, fmaxf(sc[nj][0], sc[nj][1]));
            rm1 = fmaxf(rm1, fmaxf(sc[nj][2], sc[nj][3]));
        }
        rm0 = fmaxf(rm0, __shfl_xor_sync(0xffffffffu, rm0, 1));
        rm0 = fmaxf(rm0, __shfl_xor_sync(0xffffffffu, rm0, 2));
        rm1 = fmaxf(rm1, __shfl_xor_sync(0xffffffffu, rm1, 1));
        rm1 = fmaxf(rm1, __shfl_xor_sync(0xffffffffu, rm1, 2));
        float mn0 = fmaxf(m0, rm0), mn1 = fmaxf(m1, rm1);
        float corr0 = __expf(m0 - mn0), corr1 = __expf(m1 - mn1);
        m0 = mn0; m1 = mn1;

        unsigned pa[4][4];
        float ps0 = 0.f, ps1 = 0.f;
        #pragma unroll
        for (int j = 0; j < 4; j++) {
            float p00 = __expf(sc[2*j][0]   - m0), p01 = __expf(sc[2*j][1]   - m0);
            float p02 = __expf(sc[2*j][2]   - m1), p03 = __expf(sc[2*j][3]   - m1);
            float p10 = __expf(sc[2*j+1][0] - m0), p11 = __expf(sc[2*j+1][1] - m0);
            float p12 = __expf(sc[2*j+1][2] - m1), p13 = __expf(sc[2*j+1][3] - m1);
            ps0 += p00 + p01 + p10 + p11;
            ps1 += p02 + p03 + p12 + p13;
            __half2 h0 = __floats2half2_rn(p00, p01);
            __half2 h1 = __floats2half2_rn(p02, p03);
            __half2 h2 = __floats2half2_rn(p10, p11);
            __half2 h3 = __floats2half2_rn(p12, p13);
            pa[j][0] = *(unsigned*)&h0;
            pa[j][1] = *(unsigned*)&h1;
            pa[j][2] = *(unsigned*)&h2;
            pa[j][3] = *(unsigned*)&h3;
        }
        ps0 += __shfl_xor_sync(0xffffffffu, ps0, 1);
        ps0 += __shfl_xor_sync(0xffffffffu, ps0, 2);
        ps1 += __shfl_xor_sync(0xffffffffu, ps1, 1);
        ps1 += __shfl_xor_sync(0xffffffffu, ps1, 2);
        l0 = l0*corr0 + ps0;
        l1 = l1*corr1 + ps1;

        #pragma unroll
        for (int nj = 0; nj < 8; nj++) {
            oa[nj][0] *= corr0; oa[nj][1] *= corr0;
            oa[nj][2] *= corr1; oa[nj][3] *= corr1;
        }

        #pragma unroll
        for (int j = 0; j < 4; j++) {
            unsigned vf[4][4];
            #pragma unroll
            for (int pd = 0; pd < 4; pd++) {
                int r = j*16 + (lane & 15);
                int cH = pd*16 + ((lane >> 4) << 3);
                ldm_x4t(vf[pd][0], vf[pd][1], vf[pd][2], vf[pd][3], uV[bb] + (r*ASTR + cH)*2);
            }
            #pragma unroll
            for (int dn = 0; dn < 8; dn++)
                mma16816(oa[dn][0], oa[dn][1], oa[dn][2], oa[dn][3],
                         pa[j][0], pa[j][1], pa[j][2], pa[j][3],
                         vf[dn >> 1][(dn & 1)*2], vf[dn >> 1][(dn & 1)*2 + 1]);
        }
        __syncthreads();
    }

    float il0 = 1.f/l0, il1 = 1.f/l1;
    int r0 = qb*FQT + wid*16 + (lane >> 2);
    #pragma unroll
    for (int dn = 0; dn < 8; dn++) {
        int col = dn*8 + (lane & 3)*2;
        long o0 = ((long)(b*TT + r0)*HH + h)*DD + col;
        long o1 = ((long)(b*TT + r0 + 8)*HH + h)*DD + col;
        *(__half2*)(y + o0) = __floats2half2_rn(oa[dn][0]*il0, oa[dn][1]*il0);
        *(__half2*)(y + o1) = __floats2half2_rn(oa[dn][2]*il1, oa[dn][3]*il1);
    }
}

// ---------------- MoE router: cached-row single pass ----------------
__global__ void router_k(const float* __restrict__ hn, const float* __restrict__ rw,
                         int* __restrict__ idx2, float* __restrict__ wts2,
                         int* __restrict__ counts) {
    int warp = (blockIdx.x*blockDim.x + threadIdx.x) >> 5;
    int lane = threadIdx.x & 31;
    if (warp >= M0) return;
    float reg[32];
    #pragma unroll
    for (int i = 0; i < 32; i++) reg[i] = hn[(long)warp*CC + lane + i*32];
    float lg[EE];
    #pragma unroll
    for (int e = 0; e < EE; e++) {
        float s = 0.f;
        #pragma unroll
        for (int i = 0; i < 32; i++) s += reg[i]*rw[e*CC + lane + i*32];
        #pragma unroll
        for (int o = 16; o > 0; o >>= 1) s += __shfl_down_sync(0xffffffffu, s, o);
        lg[e] = __shfl_sync(0xffffffffu, s, 0);
    }
    if (lane == 0) {
        int i0 = 0;
        for (int e = 1; e < EE; e++) if (lg[e] > lg[i0]) i0 = e;
        int i1 = -1;
        for (int e = 0; e < EE; e++) {
            if (e == i0) continue;
            if (i1 < 0 || lg[e] > lg[i1]) i1 = e;
        }
        float e1 = __expf(lg[i1] - lg[i0]);
        float s  = 1.f + e1;
        idx2[warp*2]   = i0; idx2[warp*2+1] = i1;
        wts2[warp*2]   = 1.f/s; wts2[warp*2+1] = e1/s;
        atomicAdd(&counts[i0], 1); atomicAdd(&counts[i1], 1);
    }
}

__global__ void init_k(int* counts, int* perm, float* gatew) {
    int i = blockIdx.x*blockDim.x + threadIdx.x;
    if (i < EE) counts[i] = 0;
    if (i < MG) { perm[i] = 0; gatew[i] = 0.f; }
}

__global__ void offsets_k(const int* counts, int* poff, int* cursor) {
    if (threadIdx.x == 0 && blockIdx.x == 0) {
        int o = 0;
        for (int e = 0; e < EE; e++) {
            poff[e] = o; cursor[e] = 0;
            o += ((counts[e] + 127)/128)*128;
        }
        poff[EE] = o;
    }
}

__global__ void scatter_k(const int* __restrict__ idx2, const float* __restrict__ wts2,
                          int* __restrict__ cursor, const int* __restrict__ poff,
                          int* __restrict__ perm, float* __restrict__ gatew) {
    int t = blockIdx.x*blockDim.x + threadIdx.x;
    if (t >= M0) return;
    for (int kk = 0; kk < 2; kk++) {
        int e = idx2[t*2 + kk];
        int pos = atomicAdd(&cursor[e], 1);
        int r = poff[e] + pos;
        perm[r] = t; gatew[r] = wts2[t*2 + kk];
    }
}

// ---------------- launch ----------------
static void* sym(const void* s) { void* p = nullptr; cudaGetSymbolAddress(&p, s); return p; }

extern "C" void kernel_launch(void* const* d_in, const int* in_sizes, int n_in,
                              void* d_out, int out_size) {
    const float* x    = (const float*)d_in[0];
    const float* rc   = (const float*)d_in[1];
    const float* rs   = (const float*)d_in[2];
    const float* anw  = (const float*)d_in[3];
    const float* qw   = (const float*)d_in[4];
    const float* kw   = (const float*)d_in[5];
    const float* vw   = (const float*)d_in[6];
    const float* ow   = (const float*)d_in[7];
    const float* fnw  = (const float*)d_in[8];
    const float* rw   = (const float*)d_in[9];
    const float* w1   = (const float*)d_in[10];
    const float* w2   = (const float*)d_in[11];
    const float* w3   = (const float*)d_in[12];
    float* out = (float*)d_out;

    float*  hn    = (float*)sym(g_hn);
    __half* h16   = (__half*)sym(g_h16);
    __half* qkv16 = (__half*)sym(g_qkv16);
    __half* y16   = (__half*)sym(g_y16);
    __half* hn16  = (__half*)sym(g_hn16);
    __half* gb16  = (__half*)sym(g_gb16);
    __half* w16   = (__half*)sym(g_w16all);
    __half* wqkv16= w16;
    __half* ow16  = w16 + OFF_OW;
    __half* w116  = w16 + OFF_W1;
    __half* w216  = w16 + OFF_W2;
    __half* w316  = w16 + OFF_W3;
    int*   counts = (int*)sym(g_counts);
    int*   cursor = (int*)sym(g_cursor);
    int*   poff   = (int*)sym(g_poff);
    int*   perm   = (int*)sym(g_perm);
    float* gatew  = (float*)sym(g_gatew);
    int*   idx2   = (int*)sym(g_idx2);
    float* wts2   = (float*)sym(g_wts2);

    cudaFuncSetAttribute(gemm16_k, cudaFuncAttributeMaxDynamicSharedMemorySize, DSM_G);
    cudaFuncSetAttribute(moe13_k, cudaFuncAttributeMaxDynamicSharedMemorySize, DSM_M);
    cudaFuncSetAttribute(fattn_k, cudaFuncAttributeMaxDynamicSharedMemorySize, DSM_F);

    // 0) fused weight conversion
    int ncv = 4*N4C + 3*N4E;
    convw_k<<<(ncv + 255)/256, 256>>>((const float4*)qw, (const float4*)kw, (const float4*)vw,
                                      (const float4*)ow, (const float4*)w1, (const float4*)w2,
                                      (const float4*)w3, (__half2*)w16);
    // 1) attn rmsnorm (fp16 out)
    rmsnorm_k<<<M0, 256>>>(x, anw, nullptr, h16);
    // 2) fused QKV projection (fp16 out)
    gemm16_k<<<dim3(3*CC/GBN, M0/GBM), 256, DSM_G>>>(h16, wqkv16, nullptr, qkv16, 3*CC, CC,
                                                     nullptr, nullptr, nullptr, nullptr, 0, nullptr);
    // 3) RoPE in-place
    rope_k<<<(M0*HH*32 + 255)/256, 256>>>(qkv16, rc, rs);
    // 4) causal flash attention (128-query tiles)
    fattn_k<<<dim3(TT/FQT, HH, BB), 256, DSM_F>>>(qkv16, y16);
    // 5) output projection + residual -> out (d_out holds x2)
    gemm16_k<<<dim3(CC/GBN, M0/GBM), 256, DSM_G>>>(y16, ow16, out, nullptr, CC, CC,
                                                   x, nullptr, nullptr, nullptr, 0, nullptr);
    // 6) ffn rmsnorm reads out
    rmsnorm_k<<<M0, 256>>>(out, fnw, hn, hn16);
    // 7) router + gather bookkeeping
    init_k<<<(MG + 255)/256, 256>>>(counts, perm, gatew);
    router_k<<<(M0*32 + 255)/256, 256>>>(hn, rw, idx2, wts2, counts);
    offsets_k<<<1, 32>>>(counts, poff, cursor);
    scatter_k<<<(M0 + 255)/256, 256>>>(idx2, wts2, cursor, poff, perm, gatew);
    // 8) fused expert up-projection + silu*mul
    moe13_k<<<dim3(HDIM/GBN, MG/GBM), 256, DSM_M>>>(hn16, w116, w316, gb16, perm, poff);
    //    down-projection: gate-scaled atomic scatter into out
    gemm16_k<<<dim3(CC/GBN, MG/GBM), 256, DSM_G>>>(gb16, w216, out, nullptr, CC, HDIM,
                                                   nullptr, nullptr, poff, gatew, (long)CC*HDIM, perm);
}

// round 9
// speedup vs baseline: 6.9434x; 1.0530x over previous
#include <cuda_runtime.h>
#include <cuda_fp16.h>
#include <cstdint>
#include <stdint.h>
#include <math.h>

// ---------------- problem constants ----------------
#define BB 2
#define TT 2048
#define CC 1024
#define HH 16
#define DD 64
#define EE 8
#define HDIM 1536
#define M0 (BB*TT)
#define MG 9216
#define EPSV 1e-6f

#define N4C (CC*CC/4)
#define N4E (EE*HDIM*CC/4)
#define OFF_OW (3*CC*CC)
#define OFF_W1 (4*CC*CC)
#define OFF_W2 (OFF_W1 + EE*HDIM*CC)
#define OFF_W3 (OFF_W2 + EE*HDIM*CC)
#define W16TOT (OFF_W3 + EE*HDIM*CC)

// ---------------- device scratch ----------------
__device__ float  g_hn  [M0*CC];
__device__ __half g_h16 [M0*CC];
__device__ __half g_qkv16[M0*3*CC];
__device__ __half g_y16 [M0*CC];
__device__ __half g_hn16[M0*CC];
__device__ __half g_gb16[MG*HDIM];
__device__ __half g_w16all[W16TOT];
__device__ int    g_counts[EE];
__device__ int    g_cursor[EE];
__device__ int    g_poff[EE+1];
__device__ int    g_perm[MG];
__device__ float  g_gatew[MG];
__device__ int    g_idx2[M0*2];
__device__ float  g_wts2[M0*2];

// ---------------- PTX helpers ----------------
__device__ __forceinline__ unsigned s2u(const void* p) {
    unsigned a;
    asm("{ .reg .u64 t; cvta.to.shared.u64 t, %1; cvt.u32.u64 %0, t; }" : "=r"(a) : "l"(p));
    return a;
}
__device__ __forceinline__ void ldm_x4(unsigned& r0, unsigned& r1, unsigned& r2, unsigned& r3, unsigned a) {
    asm volatile("ldmatrix.sync.aligned.m8n8.x4.shared.b16 {%0,%1,%2,%3}, [%4];"
                 : "=r"(r0), "=r"(r1), "=r"(r2), "=r"(r3) : "r"(a));
}
__device__ __forceinline__ void ldm_x4t(unsigned& r0, unsigned& r1, unsigned& r2, unsigned& r3, unsigned a) {
    asm volatile("ldmatrix.sync.aligned.m8n8.x4.trans.shared.b16 {%0,%1,%2,%3}, [%4];"
                 : "=r"(r0), "=r"(r1), "=r"(r2), "=r"(r3) : "r"(a));
}
__device__ __forceinline__ void mma16816(float& d0, float& d1, float& d2, float& d3,
                                         unsigned a0, unsigned a1, unsigned a2, unsigned a3,
                                         unsigned b0, unsigned b1) {
    asm volatile("mma.sync.aligned.m16n8k16.row.col.f32.f16.f16.f32 "
                 "{%0,%1,%2,%3}, {%4,%5,%6,%7}, {%8,%9}, {%0,%1,%2,%3};"
                 : "+f"(d0), "+f"(d1), "+f"(d2), "+f"(d3)
                 : "r"(a0), "r"(a1), "r"(a2), "r"(a3), "r"(b0), "r"(b1));
}
#define CPA16(dst, src) asm volatile("cp.async.cg.shared.global [%0], [%1], 16;" :: "r"(dst), "l"(src))

// ---------------- fused weight conversion ----------------
__global__ void convw_k(const float4* __restrict__ q, const float4* __restrict__ k,
                        const float4* __restrict__ v, const float4* __restrict__ o,
                        const float4* __restrict__ w1, const float4* __restrict__ w2,
                        const float4* __restrict__ w3, __half2* __restrict__ dst) {
    int i = blockIdx.x*blockDim.x + threadIdx.x;
    if (i >= 4*N4C + 3*N4E) return;
    const float4* s;
    long base;
    if (i < 4*N4C) {
        int seg = i / N4C, off = i - seg*N4C;
        s = (seg == 0 ? q : seg == 1 ? k : seg == 2 ? v : o) + off;
        base = (long)seg*N4C + off;
    } else {
        int j = i - 4*N4C;
        int seg = j / N4E, off = j - seg*N4E;
        s = (seg == 0 ? w1 : seg == 1 ? w2 : w3) + off;
        base = (long)4*N4C + (long)seg*N4E + off;
    }
    float4 val = *s;
    dst[base*2]   = __floats2half2_rn(val.x, val.y);
    dst[base*2+1] = __floats2half2_rn(val.z, val.w);
}

// ---------------- RMSNorm ----------------
__global__ void rmsnorm_k(const float* __restrict__ x, const float* __restrict__ w,
                          float* __restrict__ o32, __half* __restrict__ o16) {
    int row = blockIdx.x;
    const float* xr = x + (long)row*CC;
    __shared__ float red[256];
    float s = 0.f;
    for (int c = threadIdx.x; c < CC; c += 256) { float v = xr[c]; s += v*v; }
    red[threadIdx.x] = s; __syncthreads();
    for (int st = 128; st > 0; st >>= 1) {
        if (threadIdx.x < st) red[threadIdx.x] += red[threadIdx.x+st];
        __syncthreads();
    }
    float inv = rsqrtf(red[0]/(float)CC + EPSV);
    for (int c = threadIdx.x; c < CC; c += 256) {
        float v = w[c]*xr[c]*inv;
        if (o32) o32[(long)row*CC + c] = v;
        o16[(long)row*CC + c] = __float2half(v);
    }
}

// ---------------- HMMA fp16 GEMM, 64x64 warp tiles, 3-stage pipeline ----------------
#define GBM 128
#define GBN 128
#define GBK 32
#define LDP 40
#define DSM_G (6*GBM*LDP*2)
__global__ __launch_bounds__(128)
void gemm16_k(const __half* __restrict__ A, const __half* __restrict__ Wb,
              float* __restrict__ Cout, __half* __restrict__ Cout16,
              int N, int K,
              const float* __restrict__ R,
              const int* __restrict__ perm,
              const int* __restrict__ poff,
              const float* __restrict__ rowscale,
              long wstride,
              const int* __restrict__ sperm) {
    extern __shared__ __half gsm[];
    __shared__ int rowsrc[GBM];

    int tid = threadIdx.x, wid = tid >> 5, lane = tid & 31;
    int tileN = blockIdx.x, tileM = blockIdx.y;
    int row0 = tileM*GBM;

    const __half* W = Wb;
    if (poff) {
        int e = 0;
        #pragma unroll
        for (int q2 = 1; q2 < EE; q2++) if (row0 >= poff[q2]) e = q2;
        W += (long)e * wstride;
    }
    if (tid < GBM) rowsrc[tid] = perm ? perm[row0 + tid] : (row0 + tid);
    __syncthreads();

    int warp_m = (wid & 1) * 64;
    int warp_n = (wid >> 1) * 64;

    unsigned sA[3], sB[3];
    #pragma unroll
    for (int i = 0; i < 3; i++) {
        sA[i] = s2u(gsm + i*GBM*LDP);
        sB[i] = s2u(gsm + (3 + i)*GBM*LDP);
    }

    auto load_stage = [&](int s) {
        int b = s % 3;
        long k0 = (long)s * GBK;
        #pragma unroll
        for (int c = 0; c < 4; c++) {
            int id = tid + c*128;
            int r = id >> 2, ch = id & 3;
            CPA16(sA[b] + (r*LDP + ch*8)*2, A + (long)rowsrc[r]*K + k0 + ch*8);
            CPA16(sB[b] + (r*LDP + ch*8)*2, W + (long)(tileN*GBN + r)*K + k0 + ch*8);
        }
        asm volatile("cp.async.commit_group;");
    };

    float acc[4][8][4] = {};
    int ns = K / GBK;
    load_stage(0);
    load_stage(1);

    for (int s = 0; s < ns; s++) {
        if (s + 1 < ns) asm volatile("cp.async.wait_group 1;");
        else            asm volatile("cp.async.wait_group 0;");
        __syncthreads();
        if (s + 2 < ns) load_stage(s + 2);
        int b = s % 3;
        #pragma unroll
        for (int kk = 0; kk < 2; kk++) {
            unsigned af[4][4], bf[4][4];
            #pragma unroll
            for (int mi = 0; mi < 4; mi++) {
                int r = warp_m + mi*16 + (lane & 15);
                int cH = kk*16 + ((lane >> 4) << 3);
                ldm_x4(af[mi][0], af[mi][1], af[mi][2], af[mi][3], sA[b] + (r*LDP + cH)*2);
            }
            #pragma unroll
            for (int pj = 0; pj < 4; pj++) {
                int n = warp_n + pj*16 + (lane & 7) + ((lane >> 4) << 3);
                int cH = kk*16 + (((lane >> 3) & 1) << 3);
                ldm_x4(bf[pj][0], bf[pj][1], bf[pj][2], bf[pj][3], sB[b] + (n*LDP + cH)*2);
            }
            #pragma unroll
            for (int mi = 0; mi < 4; mi++)
                #pragma unroll
                for (int nj = 0; nj < 8; nj++)
                    mma16816(acc[mi][nj][0], acc[mi][nj][1], acc[mi][nj][2], acc[mi][nj][3],
                             af[mi][0], af[mi][1], af[mi][2], af[mi][3],
                             bf[nj >> 1][(nj & 1)*2], bf[nj >> 1][(nj & 1)*2 + 1]);
        }
    }

    int lrow = lane >> 2;
    int lcol = (lane & 3) * 2;
    #pragma unroll
    for (int mi = 0; mi < 4; mi++) {
        #pragma unroll
        for (int half = 0; half < 2; half++) {
            int grow = row0 + warp_m + mi*16 + lrow + half*8;
            float sc = rowscale ? rowscale[grow] : 1.f;
            if (sperm) {
                if (sc != 0.f) {
                    int token = sperm[grow];
                    long obase = (long)token*N + tileN*GBN + warp_n;
                    #pragma unroll
                    for (int nj = 0; nj < 8; nj++) {
                        long off = obase + nj*8 + lcol;
                        atomicAdd(&Cout[off],     acc[mi][nj][half*2 + 0] * sc);
                        atomicAdd(&Cout[off + 1], acc[mi][nj][half*2 + 1] * sc);
                    }
                }
            } else {
                long obase = (long)grow*N + tileN*GBN + warp_n;
                #pragma unroll
                for (int nj = 0; nj < 8; nj++) {
                    float vx = acc[mi][nj][half*2 + 0] * sc;
                    float vy = acc[mi][nj][half*2 + 1] * sc;
                    long off = obase + nj*8 + lcol;
                    if (Cout16) {
                        *(__half2*)(Cout16 + off) = __floats2half2_rn(vx, vy);
                    } else {
                        if (R) {
                            const float2 rv = *(const float2*)(R + off);
                            vx += rv.x; vy += rv.y;
                        }
                        float2 vv = { vx, vy };
                        *(float2*)(Cout + off) = vv;
                    }
                }
            }
        }
    }
}

// ---------------- fused MoE w1/w3 GEMM + silu*mul -> fp16, 3-stage ----------------
#define DSM_M (9*GBM*LDP*2)
__global__ __launch_bounds__(256)
void moe13_k(const __half* __restrict__ A, const __half* __restrict__ W1b,
             const __half* __restrict__ W3b, __half* __restrict__ G,
             const int* __restrict__ perm, const int* __restrict__ poff) {
    extern __shared__ __half sm[];
    __shared__ int rowsrc[GBM];

    int tid = threadIdx.x, wid = tid >> 5, lane = tid & 31;
    int tileN = blockIdx.x, tileM = blockIdx.y;
    int row0 = tileM*GBM;
    const int K = CC;

    int e = 0;
    #pragma unroll
    for (int q2 = 1; q2 < EE; q2++) if (row0 >= poff[q2]) e = q2;
    const __half* W1 = W1b + (long)e*HDIM*CC;
    const __half* W3 = W3b + (long)e*HDIM*CC;

    if (tid < GBM) rowsrc[tid] = perm[row0 + tid];
    __syncthreads();

    int warp_m = (wid >> 2) * 64;
    int warp_n = (wid & 3) * 32;

    unsigned sA[3], sB1[3], sB3[3];
    #pragma unroll
    for (int i = 0; i < 3; i++) {
        sA[i]  = s2u(sm + i*GBM*LDP);
        sB1[i] = s2u(sm + (3 + i)*GBM*LDP);
        sB3[i] = s2u(sm + (6 + i)*GBM*LDP);
    }

    auto load_stage = [&](int s) {
        int b = s % 3;
        long k0 = (long)s * GBK;
        #pragma unroll
        for (int c = 0; c < 2; c++) {
            int id = tid + c*256;
            int r = id >> 2, ch = id & 3;
            CPA16(sA[b]  + (r*LDP + ch*8)*2, A  + (long)rowsrc[r]*K + k0 + ch*8);
            CPA16(sB1[b] + (r*LDP + ch*8)*2, W1 + (long)(tileN*GBN + r)*K + k0 + ch*8);
            CPA16(sB3[b] + (r*LDP + ch*8)*2, W3 + (long)(tileN*GBN + r)*K + k0 + ch*8);
        }
        asm volatile("cp.async.commit_group;");
    };

    float a1[4][4][4] = {};
    float a3[4][4][4] = {};
    int ns = K / GBK;
    load_stage(0);
    load_stage(1);

    for (int s = 0; s < ns; s++) {
        if (s + 1 < ns) asm volatile("cp.async.wait_group 1;");
        else            asm volatile("cp.async.wait_group 0;");
        __syncthreads();
        if (s + 2 < ns) load_stage(s + 2);
        int b = s % 3;
        #pragma unroll
        for (int kk = 0; kk < 2; kk++) {
            unsigned af[4][4], b1f[2][4], b3f[2][4];
            #pragma unroll
            for (int mi = 0; mi < 4; mi++) {
                int r = warp_m + mi*16 + (lane & 15);
                int cH = kk*16 + ((lane >> 4) << 3);
                ldm_x4(af[mi][0], af[mi][1], af[mi][2], af[mi][3], sA[b] + (r*LDP + cH)*2);
            }
            #pragma unroll
            for (int pj = 0; pj < 2; pj++) {
                int n = warp_n + pj*16 + (lane & 7) + ((lane >> 4) << 3);
                int cH = kk*16 + (((lane >> 3) & 1) << 3);
                ldm_x4(b1f[pj][0], b1f[pj][1], b1f[pj][2], b1f[pj][3], sB1[b] + (n*LDP + cH)*2);
                ldm_x4(b3f[pj][0], b3f[pj][1], b3f[pj][2], b3f[pj][3], sB3[b] + (n*LDP + cH)*2);
            }
            #pragma unroll
            for (int mi = 0; mi < 4; mi++)
                #pragma unroll
                for (int nj = 0; nj < 4; nj++) {
                    mma16816(a1[mi][nj][0], a1[mi][nj][1], a1[mi][nj][2], a1[mi][nj][3],
                             af[mi][0], af[mi][1], af[mi][2], af[mi][3],
                             b1f[nj >> 1][(nj & 1)*2], b1f[nj >> 1][(nj & 1)*2 + 1]);
                    mma16816(a3[mi][nj][0], a3[mi][nj][1], a3[mi][nj][2], a3[mi][nj][3],
                             af[mi][0], af[mi][1], af[mi][2], af[mi][3],
                             b3f[nj >> 1][(nj & 1)*2], b3f[nj >> 1][(nj & 1)*2 + 1]);
                }
        }
    }

    int lrow = lane >> 2;
    int lcol = (lane & 3) * 2;
    #pragma unroll
    for (int mi = 0; mi < 4; mi++) {
        #pragma unroll
        for (int half = 0; half < 2; half++) {
            int grow = row0 + warp_m + mi*16 + lrow + half*8;
            long obase = (long)grow*HDIM + tileN*GBN + warp_n;
            #pragma unroll
            for (int nj = 0; nj < 4; nj++) {
                float u0 = a1[mi][nj][half*2 + 0];
                float u1 = a1[mi][nj][half*2 + 1];
                float w0 = a3[mi][nj][half*2 + 0];
                float w1 = a3[mi][nj][half*2 + 1];
                float g0 = u0 / (1.f + __expf(-u0)) * w0;
                float g1 = u1 / (1.f + __expf(-u1)) * w1;
                *(__half2*)(G + obase + nj*8 + lcol) = __floats2half2_rn(g0, g1);
            }
        }
    }
}

// ---------------- RoPE in-place on packed fp16 qkv ----------------
__global__ void rope_k(__half* __restrict__ qkv,
                       const float* __restrict__ cs, const float* __restrict__ sn) {
    int idx = blockIdx.x*blockDim.x + threadIdx.x;
    if (idx >= M0*HH*32) return;
    int d  = idx & 31;
    int h  = (idx >> 5) & (HH-1);
    int bt = idx >> 9;
    int t  = bt & (TT-1);
    long base = (long)bt*(3*CC) + h*DD;
    float c1 = cs[t*DD + d], c2 = cs[t*DD + d + 32];
    float s1 = sn[t*DD + d], s2 = sn[t*DD + d + 32];
    float q1 = __half2float(qkv[base+d]), q2 = __half2float(qkv[base+d+32]);
    qkv[base+d]    = __float2half((q1*c1 - q2*s1) * 0.125f);
    qkv[base+d+32] = __float2half((q2*c2 + q1*s2) * 0.125f);
    float k1 = __half2float(qkv[base+CC+d]), k2 = __half2float(qkv[base+CC+d+32]);
    qkv[base+CC+d]    = __float2half(k1*c1 - k2*s1);
    qkv[base+CC+d+32] = __float2half(k2*c2 + k1*s2);
}

// ---------------- FlashAttention-2 HMMA causal attention, 128-query tiles ----------------
#define ASTR 72
#define QKVS (3*CC)
#define FQT 128
#define DSM_F ((FQT*ASTR + 4*64*ASTR)*2)
__global__ __launch_bounds__(256)
void fattn_k(const __half* __restrict__ qkv, __half* __restrict__ y) {
    extern __shared__ __half fsm[];
    int qb = (int)gridDim.x - 1 - (int)blockIdx.x;
    int h = blockIdx.y, b = blockIdx.z;
    int tid = threadIdx.x, wid = tid >> 5, lane = tid & 31;

    unsigned uQ = s2u(fsm);
    unsigned uK[2] = { s2u(fsm + FQT*ASTR),              s2u(fsm + FQT*ASTR + 64*ASTR) };
    unsigned uV[2] = { s2u(fsm + FQT*ASTR + 2*64*ASTR),  s2u(fsm + FQT*ASTR + 3*64*ASTR) };

    long qbase = (long)(b*TT + qb*FQT)*QKVS + h*DD;
    #pragma unroll
    for (int c = 0; c < 4; c++) {
        int id = tid + c*256;
        int r = id >> 3, ch = id & 7;
        CPA16(uQ + (r*ASTR + ch*8)*2, qkv + qbase + (long)r*QKVS + ch*8);
    }
    asm volatile("cp.async.commit_group;");

    auto load_kv = [&](int s) {
        int bb = s & 1;
        long kvb = (long)(b*TT + s*64)*QKVS + h*DD + CC;
        #pragma unroll
        for (int c = 0; c < 2; c++) {
            int id = tid + c*256;
            int r = id >> 3, ch = id & 7;
            CPA16(uK[bb] + (r*ASTR + ch*8)*2, qkv + kvb + (long)r*QKVS + ch*8);
            CPA16(uV[bb] + (r*ASTR + ch*8)*2, qkv + kvb + CC + (long)r*QKVS + ch*8);
        }
        asm volatile("cp.async.commit_group;");
    };

    load_kv(0);
    asm volatile("cp.async.wait_group 0;");
    __syncthreads();

    unsigned qa[4][4];
    #pragma unroll
    for (int kk = 0; kk < 4; kk++) {
        int r = wid*16 + (lane & 15);
        int cH = kk*16 + ((lane >> 4) << 3);
        ldm_x4(qa[kk][0], qa[kk][1], qa[kk][2], qa[kk][3], uQ + (r*ASTR + cH)*2);
    }

    float m0 = -1e30f, m1 = -1e30f, l0 = 0.f, l1 = 0.f;
    float oa[8][4] = {};
    int nkt = 2*qb + 2;

    for (int kt = 0; kt < nkt; kt++) {
        if (kt + 1 < nkt) { load_kv(kt + 1); asm volatile("cp.async.wait_group 1;"); }
        else              { asm volatile("cp.async.wait_group 0;"); }
        __syncthreads();
        int bb = kt & 1;

        float sc[8][4] = {};
        #pragma unroll
        for (int kk = 0; kk < 4; kk++) {
            unsigned bf[4][4];
            #pragma unroll
            for (int pj = 0; pj < 4; pj++) {
                int n = pj*16 + (lane & 7) + ((lane >> 4) << 3);
                int cH = kk*16 + (((lane >> 3) & 1) << 3);
                ldm_x4(bf[pj][0], bf[pj][1], bf[pj][2], bf[pj][3], uK[bb] + (n*ASTR + cH)*2);
            }
            #pragma unroll
            for (int nj = 0; nj < 8; nj++)
                mma16816(sc[nj][0], sc[nj][1], sc[nj][2], sc[nj][3],
                         qa[kk][0], qa[kk][1], qa[kk][2], qa[kk][3],
                         bf[nj >> 1][(nj & 1)*2], bf[nj >> 1][(nj & 1)*2 + 1]);
        }

        if (kt >= 2*qb) {
            int rg = qb*FQT + wid*16 + (lane >> 2);
            #pragma unroll
            for (int nj = 0; nj < 8; nj++) {
                int cg = kt*64 + nj*8 + (lane & 3)*2;
                if (cg     > rg)   sc[nj][0] = -1e30f;
                if (cg + 1 > rg)   sc[nj][1] = -1e30f;
                if (cg     > rg+8) sc[nj][2] = -1e30f;
                if (cg + 1 > rg+8) sc[nj][3] = -1e30f;
            }
        }

        float rm0 = -1e30f, rm1 = -1e30f;
        #pragma unroll
        for (int nj = 0; nj < 8; nj++) {
            rm0 = fmaxf(rm0, fmaxf(sc[nj][0], sc[nj][1]));
            rm1 = fmaxf(rm1, fmaxf(sc[nj][2], sc[nj][3]));
        }
        rm0 = fmaxf(rm0, __shfl_xor_sync(0xffffffffu, rm0, 1));
        rm0 = fmaxf(rm0, __shfl_xor_sync(0xffffffffu, rm0, 2));
        rm1 = fmaxf(rm1, __shfl_xor_sync(0xffffffffu, rm1, 1));
        rm1 = fmaxf(rm1, __shfl_xor_sync(0xffffffffu, rm1, 2));
        float mn0 = fmaxf(m0, rm0), mn1 = fmaxf(m1, rm1);
        float corr0 = __expf(m0 - mn0), corr1 = __expf(m1 - mn1);
        m0 = mn0; m1 = mn1;

        unsigned pa[4][4];
        float ps0 = 0.f, ps1 = 0.f;
        #pragma unroll
        for (int j = 0; j < 4; j++) {
            float p00 = __expf(sc[2*j][0]   - m0), p01 = __expf(sc[2*j][1]   - m0);
            float p02 = __expf(sc[2*j][2]   - m1), p03 = __expf(sc[2*j][3]   - m1);
            float p10 = __expf(sc[2*j+1][0] - m0), p11 = __expf(sc[2*j+1][1] - m0);
            float p12 = __expf(sc[2*j+1][2] - m1), p13 = __expf(sc[2*j+1][3] - m1);
            ps0 += p00 + p01 + p10 + p11;
            ps1 += p02 + p03 + p12 + p13;
            __half2 h0 = __floats2half2_rn(p00, p01);
            __half2 h1 = __floats2half2_rn(p02, p03);
            __half2 h2 = __floats2half2_rn(p10, p11);
            __half2 h3 = __floats2half2_rn(p12, p13);
            pa[j][0] = *(unsigned*)&h0;
            pa[j][1] = *(unsigned*)&h1;
            pa[j][2] = *(unsigned*)&h2;
            pa[j][3] = *(unsigned*)&h3;
        }
        ps0 += __shfl_xor_sync(0xffffffffu, ps0, 1);
        ps0 += __shfl_xor_sync(0xffffffffu, ps0, 2);
        ps1 += __shfl_xor_sync(0xffffffffu, ps1, 1);
        ps1 += __shfl_xor_sync(0xffffffffu, ps1, 2);
        l0 = l0*corr0 + ps0;
        l1 = l1*corr1 + ps1;

        #pragma unroll
        for (int nj = 0; nj < 8; nj++) {
            oa[nj][0] *= corr0; oa[nj][1] *= corr0;
            oa[nj][2] *= corr1; oa[nj][3] *= corr1;
        }

        #pragma unroll
        for (int j = 0; j < 4; j++) {
            unsigned vf[4][4];
            #pragma unroll
            for (int pd = 0; pd < 4; pd++) {
                int r = j*16 + (lane & 15);
                int cH = pd*16 + ((lane >> 4) << 3);
                ldm_x4t(vf[pd][0], vf[pd][1], vf[pd][2], vf[pd][3], uV[bb] + (r*ASTR + cH)*2);
            }
            #pragma unroll
            for (int dn = 0; dn < 8; dn++)
                mma16816(oa[dn][0], oa[dn][1], oa[dn][2], oa[dn][3],
                         pa[j][0], pa[j][1], pa[j][2], pa[j][3],
                         vf[dn >> 1][(dn & 1)*2], vf[dn >> 1][(dn & 1)*2 + 1]);
        }
        __syncthreads();
    }

    float il0 = 1.f/l0, il1 = 1.f/l1;
    int r0 = qb*FQT + wid*16 + (lane >> 2);
    #pragma unroll
    for (int dn = 0; dn < 8; dn++) {
        int col = dn*8 + (lane & 3)*2;
        long o0 = ((long)(b*TT + r0)*HH + h)*DD + col;
        long o1 = ((long)(b*TT + r0 + 8)*HH + h)*DD + col;
        *(__half2*)(y + o0) = __floats2half2_rn(oa[dn][0]*il0, oa[dn][1]*il0);
        *(__half2*)(y + o1) = __floats2half2_rn(oa[dn][2]*il1, oa[dn][3]*il1);
    }
}

// ---------------- MoE router: cached-row single pass ----------------
__global__ void router_k(const float* __restrict__ hn, const float* __restrict__ rw,
                         int* __restrict__ idx2, float* __restrict__ wts2,
                         int* __restrict__ counts) {
    int warp = (blockIdx.x*blockDim.x + threadIdx.x) >> 5;
    int lane = threadIdx.x & 31;
    if (warp >= M0) return;
    float reg[32];
    #pragma unroll
    for (int i = 0; i < 32; i++) reg[i] = hn[(long)warp*CC + lane + i*32];
    float lg[EE];
    #pragma unroll
    for (int e = 0; e < EE; e++) {
        float s = 0.f;
        #pragma unroll
        for (int i = 0; i < 32; i++) s += reg[i]*rw[e*CC + lane + i*32];
        #pragma unroll
        for (int o = 16; o > 0; o >>= 1) s += __shfl_down_sync(0xffffffffu, s, o);
        lg[e] = __shfl_sync(0xffffffffu, s, 0);
    }
    if (lane == 0) {
        int i0 = 0;
        for (int e = 1; e < EE; e++) if (lg[e] > lg[i0]) i0 = e;
        int i1 = -1;
        for (int e = 0; e < EE; e++) {
            if (e == i0) continue;
            if (i1 < 0 || lg[e] > lg[i1]) i1 = e;
        }
        float e1 = __expf(lg[i1] - lg[i0]);
        float s  = 1.f + e1;
        idx2[warp*2]   = i0; idx2[warp*2+1] = i1;
        wts2[warp*2]   = 1.f/s; wts2[warp*2+1] = e1/s;
        atomicAdd(&counts[i0], 1); atomicAdd(&counts[i1], 1);
    }
}

__global__ void init_k(int* counts, int* perm, float* gatew) {
    int i = blockIdx.x*blockDim.x + threadIdx.x;
    if (i < EE) counts[i] = 0;
    if (i < MG) { perm[i] = 0; gatew[i] = 0.f; }
}

__global__ void offsets_k(const int* counts, int* poff, int* cursor) {
    if (threadIdx.x == 0 && blockIdx.x == 0) {
        int o = 0;
        for (int e = 0; e < EE; e++) {
            poff[e] = o; cursor[e] = 0;
            o += ((counts[e] + 127)/128)*128;
        }
        poff[EE] = o;
    }
}

__global__ void scatter_k(const int* __restrict__ idx2, const float* __restrict__ wts2,
                          int* __restrict__ cursor, const int* __restrict__ poff,
                          int* __restrict__ perm, float* __restrict__ gatew) {
    int t = blockIdx.x*blockDim.x + threadIdx.x;
    if (t >= M0) return;
    for (int kk = 0; kk < 2; kk++) {
        int e = idx2[t*2 + kk];
        int pos = atomicAdd(&cursor[e], 1);
        int r = poff[e] + pos;
        perm[r] = t; gatew[r] = wts2[t*2 + kk];
    }
}

// ---------------- launch ----------------
static void* sym(const void* s) { void* p = nullptr; cudaGetSymbolAddress(&p, s); return p; }

extern "C" void kernel_launch(void* const* d_in, const int* in_sizes, int n_in,
                              void* d_out, int out_size) {
    const float* x    = (const float*)d_in[0];
    const float* rc   = (const float*)d_in[1];
    const float* rs   = (const float*)d_in[2];
    const float* anw  = (const float*)d_in[3];
    const float* qw   = (const float*)d_in[4];
    const float* kw   = (const float*)d_in[5];
    const float* vw   = (const float*)d_in[6];
    const float* ow   = (const float*)d_in[7];
    const float* fnw  = (const float*)d_in[8];
    const float* rw   = (const float*)d_in[9];
    const float* w1   = (const float*)d_in[10];
    const float* w2   = (const float*)d_in[11];
    const float* w3   = (const float*)d_in[12];
    float* out = (float*)d_out;

    float*  hn    = (float*)sym(g_hn);
    __half* h16   = (__half*)sym(g_h16);
    __half* qkv16 = (__half*)sym(g_qkv16);
    __half* y16   = (__half*)sym(g_y16);
    __half* hn16  = (__half*)sym(g_hn16);
    __half* gb16  = (__half*)sym(g_gb16);
    __half* w16   = (__half*)sym(g_w16all);
    __half* wqkv16= w16;
    __half* ow16  = w16 + OFF_OW;
    __half* w116  = w16 + OFF_W1;
    __half* w216  = w16 + OFF_W2;
    __half* w316  = w16 + OFF_W3;
    int*   counts = (int*)sym(g_counts);
    int*   cursor = (int*)sym(g_cursor);
    int*   poff   = (int*)sym(g_poff);
    int*   perm   = (int*)sym(g_perm);
    float* gatew  = (float*)sym(g_gatew);
    int*   idx2   = (int*)sym(g_idx2);
    float* wts2   = (float*)sym(g_wts2);

    cudaFuncSetAttribute(gemm16_k, cudaFuncAttributeMaxDynamicSharedMemorySize, DSM_G);
    cudaFuncSetAttribute(moe13_k, cudaFuncAttributeMaxDynamicSharedMemorySize, DSM_M);
    cudaFuncSetAttribute(fattn_k, cudaFuncAttributeMaxDynamicSharedMemorySize, DSM_F);

    // 0) fused weight conversion
    int ncv = 4*N4C + 3*N4E;
    convw_k<<<(ncv + 255)/256, 256>>>((const float4*)qw, (const float4*)kw, (const float4*)vw,
                                      (const float4*)ow, (const float4*)w1, (const float4*)w2,
                                      (const float4*)w3, (__half2*)w16);
    // 1) attn rmsnorm (fp16 out)
    rmsnorm_k<<<M0, 256>>>(x, anw, nullptr, h16);
    // 2) fused QKV projection (fp16 out)
    gemm16_k<<<dim3(3*CC/GBN, M0/GBM), 128, DSM_G>>>(h16, wqkv16, nullptr, qkv16, 3*CC, CC,
                                                     nullptr, nullptr, nullptr, nullptr, 0, nullptr);
    // 3) RoPE in-place
    rope_k<<<(M0*HH*32 + 255)/256, 256>>>(qkv16, rc, rs);
    // 4) causal flash attention (128-query tiles)
    fattn_k<<<dim3(TT/FQT, HH, BB), 256, DSM_F>>>(qkv16, y16);
    // 5) output projection + residual -> out
    gemm16_k<<<dim3(CC/GBN, M0/GBM), 128, DSM_G>>>(y16, ow16, out, nullptr, CC, CC,
                                                   x, nullptr, nullptr, nullptr, 0, nullptr);
    // 6) ffn rmsnorm reads out
    rmsnorm_k<<<M0, 256>>>(out, fnw, hn, hn16);
    // 7) router + gather bookkeeping
    init_k<<<(MG + 255)/256, 256>>>(counts, perm, gatew);
    router_k<<<(M0*32 + 255)/256, 256>>>(hn, rw, idx2, wts2, counts);
    offsets_k<<<1, 32>>>(counts, poff, cursor);
    scatter_k<<<(M0 + 255)/256, 256>>>(idx2, wts2, cursor, poff, perm, gatew);
    // 8) fused expert up-projection + silu*mul
    moe13_k<<<dim3(HDIM/GBN, MG/GBM), 256, DSM_M>>>(hn16, w116, w316, gb16, perm, poff);
    //    down-projection: gate-scaled atomic scatter into out
    gemm16_k<<<dim3(CC/GBN, MG/GBM), 128, DSM_G>>>(gb16, w216, out, nullptr, CC, HDIM,
                                                   nullptr, nullptr, poff, gatew, (long)CC*HDIM, perm);
}

// round 10
// speedup vs baseline: 7.0624x; 1.0171x over previous
#include <cuda_runtime.h>
#include <cuda_fp16.h>
#include <cstdint>
#include <stdint.h>
#include <math.h>

// ---------------- problem constants ----------------
#define BB 2
#define TT 2048
#define CC 1024
#define HH 16
#define DD 64
#define EE 8
#define HDIM 1536
#define M0 (BB*TT)
#define MG 9216
#define EPSV 1e-6f

#define N4C (CC*CC/4)
#define N4E (EE*HDIM*CC/4)
#define OFF_OW (3*CC*CC)
#define OFF_W1 (4*CC*CC)
#define OFF_W2 (OFF_W1 + EE*HDIM*CC)
#define OFF_W3 (OFF_W2 + EE*HDIM*CC)
#define W16TOT (OFF_W3 + EE*HDIM*CC)

// ---------------- device scratch ----------------
__device__ float  g_hn  [M0*CC];
__device__ __half g_h16 [M0*CC];
__device__ __half g_qkv16[M0*3*CC];
__device__ __half g_y16 [M0*CC];
__device__ __half g_hn16[M0*CC];
__device__ __half g_gb16[MG*HDIM];
__device__ __half g_w16all[W16TOT];
__device__ int    g_counts[EE];
__device__ int    g_cursor[EE];
__device__ int    g_poff[EE+1];
__device__ int    g_perm[MG];
__device__ float  g_gatew[MG];
__device__ int    g_idx2[M0*2];
__device__ float  g_wts2[M0*2];

// ---------------- PTX helpers ----------------
__device__ __forceinline__ unsigned s2u(const void* p) {
    unsigned a;
    asm("{ .reg .u64 t; cvta.to.shared.u64 t, %1; cvt.u32.u64 %0, t; }" : "=r"(a) : "l"(p));
    return a;
}
__device__ __forceinline__ void ldm_x4(unsigned& r0, unsigned& r1, unsigned& r2, unsigned& r3, unsigned a) {
    asm volatile("ldmatrix.sync.aligned.m8n8.x4.shared.b16 {%0,%1,%2,%3}, [%4];"
                 : "=r"(r0), "=r"(r1), "=r"(r2), "=r"(r3) : "r"(a));
}
__device__ __forceinline__ void ldm_x4t(unsigned& r0, unsigned& r1, unsigned& r2, unsigned& r3, unsigned a) {
    asm volatile("ldmatrix.sync.aligned.m8n8.x4.trans.shared.b16 {%0,%1,%2,%3}, [%4];"
                 : "=r"(r0), "=r"(r1), "=r"(r2), "=r"(r3) : "r"(a));
}
__device__ __forceinline__ void mma16816(float& d0, float& d1, float& d2, float& d3,
                                         unsigned a0, unsigned a1, unsigned a2, unsigned a3,
                                         unsigned b0, unsigned b1) {
    asm volatile("mma.sync.aligned.m16n8k16.row.col.f32.f16.f16.f32 "
                 "{%0,%1,%2,%3}, {%4,%5,%6,%7}, {%8,%9}, {%0,%1,%2,%3};"
                 : "+f"(d0), "+f"(d1), "+f"(d2), "+f"(d3)
                 : "r"(a0), "r"(a1), "r"(a2), "r"(a3), "r"(b0), "r"(b1));
}
#define CPA16(dst, src) asm volatile("cp.async.cg.shared.global [%0], [%1], 16;" :: "r"(dst), "l"(src))

// ---------------- fused weight conversion + MoE bookkeeping init ----------------
__global__ void convw_k(const float4* __restrict__ q, const float4* __restrict__ k,
                        const float4* __restrict__ v, const float4* __restrict__ o,
                        const float4* __restrict__ w1, const float4* __restrict__ w2,
                        const float4* __restrict__ w3, __half2* __restrict__ dst,
                        int* __restrict__ counts, int* __restrict__ perm,
                        float* __restrict__ gatew) {
    int i = blockIdx.x*blockDim.x + threadIdx.x;
    if (i < EE) counts[i] = 0;
    if (i < MG) { perm[i] = 0; gatew[i] = 0.f; }
    if (i >= 4*N4C + 3*N4E) return;
    const float4* s;
    long base;
    if (i < 4*N4C) {
        int seg = i / N4C, off = i - seg*N4C;
        s = (seg == 0 ? q : seg == 1 ? k : seg == 2 ? v : o) + off;
        base = (long)seg*N4C + off;
    } else {
        int j = i - 4*N4C;
        int seg = j / N4E, off = j - seg*N4E;
        s = (seg == 0 ? w1 : seg == 1 ? w2 : w3) + off;
        base = (long)4*N4C + (long)seg*N4E + off;
    }
    float4 val = *s;
    dst[base*2]   = __floats2half2_rn(val.x, val.y);
    dst[base*2+1] = __floats2half2_rn(val.z, val.w);
}

// ---------------- RMSNorm ----------------
__global__ void rmsnorm_k(const float* __restrict__ x, const float* __restrict__ w,
                          float* __restrict__ o32, __half* __restrict__ o16) {
    int row = blockIdx.x;
    const float* xr = x + (long)row*CC;
    __shared__ float red[256];
    float s = 0.f;
    for (int c = threadIdx.x; c < CC; c += 256) { float v = xr[c]; s += v*v; }
    red[threadIdx.x] = s; __syncthreads();
    for (int st = 128; st > 0; st >>= 1) {
        if (threadIdx.x < st) red[threadIdx.x] += red[threadIdx.x+st];
        __syncthreads();
    }
    float inv = rsqrtf(red[0]/(float)CC + EPSV);
    for (int c = threadIdx.x; c < CC; c += 256) {
        float v = w[c]*xr[c]*inv;
        if (o32) o32[(long)row*CC + c] = v;
        o16[(long)row*CC + c] = __float2half(v);
    }
}

// ---------------- HMMA fp16 GEMM, 64x64 warp tiles, 3-stage; rope-fused fp16 epilogue ----------------
#define GBM 128
#define GBN 128
#define GBK 32
#define LDP 40
#define DSM_G (6*GBM*LDP*2)
__global__ __launch_bounds__(128)
void gemm16_k(const __half* __restrict__ A, const __half* __restrict__ Wb,
              float* __restrict__ Cout, __half* __restrict__ Cout16,
              int N, int K,
              const float* __restrict__ R,
              const int* __restrict__ perm,
              const int* __restrict__ poff,
              const float* __restrict__ rowscale,
              long wstride,
              const int* __restrict__ sperm,
              const float* __restrict__ ropeC,
              const float* __restrict__ ropeS) {
    extern __shared__ __half gsm[];
    __shared__ int rowsrc[GBM];

    int tid = threadIdx.x, wid = tid >> 5, lane = tid & 31;
    int tileN = blockIdx.x, tileM = blockIdx.y;
    int row0 = tileM*GBM;

    const __half* W = Wb;
    if (poff) {
        if (row0 >= poff[EE]) return;      // padding tile: no real rows
        int e = 0;
        #pragma unroll
        for (int q2 = 1; q2 < EE; q2++) if (row0 >= poff[q2]) e = q2;
        W += (long)e * wstride;
    }
    if (tid < GBM) rowsrc[tid] = perm ? perm[row0 + tid] : (row0 + tid);
    __syncthreads();

    int warp_m = (wid & 1) * 64;
    int warp_n = (wid >> 1) * 64;

    unsigned sA[3], sB[3];
    #pragma unroll
    for (int i = 0; i < 3; i++) {
        sA[i] = s2u(gsm + i*GBM*LDP);
        sB[i] = s2u(gsm + (3 + i)*GBM*LDP);
    }

    auto load_stage = [&](int s) {
        int b = s % 3;
        long k0 = (long)s * GBK;
        #pragma unroll
        for (int c = 0; c < 4; c++) {
            int id = tid + c*128;
            int r = id >> 2, ch = id & 3;
            CPA16(sA[b] + (r*LDP + ch*8)*2, A + (long)rowsrc[r]*K + k0 + ch*8);
            CPA16(sB[b] + (r*LDP + ch*8)*2, W + (long)(tileN*GBN + r)*K + k0 + ch*8);
        }
        asm volatile("cp.async.commit_group;");
    };

    float acc[4][8][4] = {};
    int ns = K / GBK;
    load_stage(0);
    load_stage(1);

    for (int s = 0; s < ns; s++) {
        if (s + 1 < ns) asm volatile("cp.async.wait_group 1;");
        else            asm volatile("cp.async.wait_group 0;");
        __syncthreads();
        if (s + 2 < ns) load_stage(s + 2);
        int b = s % 3;
        #pragma unroll
        for (int kk = 0; kk < 2; kk++) {
            unsigned af[4][4], bf[4][4];
            #pragma unroll
            for (int mi = 0; mi < 4; mi++) {
                int r = warp_m + mi*16 + (lane & 15);
                int cH = kk*16 + ((lane >> 4) << 3);
                ldm_x4(af[mi][0], af[mi][1], af[mi][2], af[mi][3], sA[b] + (r*LDP + cH)*2);
            }
            #pragma unroll
            for (int pj = 0; pj < 4; pj++) {
                int n = warp_n + pj*16 + (lane & 7) + ((lane >> 4) << 3);
                int cH = kk*16 + (((lane >> 3) & 1) << 3);
                ldm_x4(bf[pj][0], bf[pj][1], bf[pj][2], bf[pj][3], sB[b] + (n*LDP + cH)*2);
            }
            #pragma unroll
            for (int mi = 0; mi < 4; mi++)
                #pragma unroll
                for (int nj = 0; nj < 8; nj++)
                    mma16816(acc[mi][nj][0], acc[mi][nj][1], acc[mi][nj][2], acc[mi][nj][3],
                             af[mi][0], af[mi][1], af[mi][2], af[mi][3],
                             bf[nj >> 1][(nj & 1)*2], bf[nj >> 1][(nj & 1)*2 + 1]);
        }
    }

    int lrow = lane >> 2;
    int lcol = (lane & 3) * 2;
    #pragma unroll
    for (int mi = 0; mi < 4; mi++) {
        #pragma unroll
        for (int half = 0; half < 2; half++) {
            int grow = row0 + warp_m + mi*16 + lrow + half*8;
            float sc = rowscale ? rowscale[grow] : 1.f;
            if (sperm) {
                if (sc != 0.f) {
                    int token = sperm[grow];
                    long obase = (long)token*N + tileN*GBN + warp_n;
                    #pragma unroll
                    for (int nj = 0; nj < 8; nj++) {
                        long off = obase + nj*8 + lcol;
                        atomicAdd(&Cout[off],     acc[mi][nj][half*2 + 0] * sc);
                        atomicAdd(&Cout[off + 1], acc[mi][nj][half*2 + 1] * sc);
                    }
                }
            } else if (ropeC) {
                // rope-fused fp16 epilogue: pair (d, d+32) = (nj, nj+4), d<=31
                int t = grow & (TT-1);
                long obase = (long)grow*N + tileN*GBN + warp_n;
                #pragma unroll
                for (int nj = 0; nj < 4; nj++) {
                    int colg = tileN*GBN + warp_n + nj*8 + lcol;
                    int seg = colg >> 10;            // 0=q,1=k,2=v
                    int d = colg & 63;               // 0..31 within head
                    float x1a = acc[mi][nj][half*2 + 0];
                    float x1b = acc[mi][nj][half*2 + 1];
                    float x2a = acc[mi][nj+4][half*2 + 0];
                    float x2b = acc[mi][nj+4][half*2 + 1];
                    if (seg < 2) {
                        const float* ct = ropeC + t*DD;
                        const float* st = ropeS + t*DD;
                        float c1a = ct[d],    c1b = ct[d+1];
                        float c2a = ct[d+32], c2b = ct[d+33];
                        float s1a = st[d],    s1b = st[d+1];
                        float s2a = st[d+32], s2b = st[d+33];
                        float o1a = x1a*c1a - x2a*s1a;
                        float o1b = x1b*c1b - x2b*s1b;
                        float o2a = x2a*c2a + x1a*s2a;
                        float o2b = x2b*c2b + x1b*s2b;
                        if (seg == 0) { o1a *= 0.125f; o1b *= 0.125f; o2a *= 0.125f; o2b *= 0.125f; }
                        x1a = o1a; x1b = o1b; x2a = o2a; x2b = o2b;
                    }
                    *(__half2*)(Cout16 + obase + nj*8 + lcol)        = __floats2half2_rn(x1a, x1b);
                    *(__half2*)(Cout16 + obase + (nj+4)*8 + lcol)    = __floats2half2_rn(x2a, x2b);
                }
            } else {
                long obase = (long)grow*N + tileN*GBN + warp_n;
                #pragma unroll
                for (int nj = 0; nj < 8; nj++) {
                    float vx = acc[mi][nj][half*2 + 0] * sc;
                    float vy = acc[mi][nj][half*2 + 1] * sc;
                    long off = obase + nj*8 + lcol;
                    if (Cout16) {
                        *(__half2*)(Cout16 + off) = __floats2half2_rn(vx, vy);
                    } else {
                        if (R) {
                            const float2 rv = *(const float2*)(R + off);
                            vx += rv.x; vy += rv.y;
                        }
                        float2 vv = { vx, vy };
                        *(float2*)(Cout + off) = vv;
                    }
                }
            }
        }
    }
}

// ---------------- fused MoE w1/w3 GEMM + silu*mul -> fp16, 3-stage ----------------
#define DSM_M (9*GBM*LDP*2)
__global__ __launch_bounds__(256)
void moe13_k(const __half* __restrict__ A, const __half* __restrict__ W1b,
             const __half* __restrict__ W3b, __half* __restrict__ G,
             const int* __restrict__ perm, const int* __restrict__ poff) {
    extern __shared__ __half sm[];
    __shared__ int rowsrc[GBM];

    int tid = threadIdx.x, wid = tid >> 5, lane = tid & 31;
    int tileN = blockIdx.x, tileM = blockIdx.y;
    int row0 = tileM*GBM;
    const int K = CC;

    if (row0 >= poff[EE]) return;          // padding tile: no real rows
    int e = 0;
    #pragma unroll
    for (int q2 = 1; q2 < EE; q2++) if (row0 >= poff[q2]) e = q2;
    const __half* W1 = W1b + (long)e*HDIM*CC;
    const __half* W3 = W3b + (long)e*HDIM*CC;

    if (tid < GBM) rowsrc[tid] = perm[row0 + tid];
    __syncthreads();

    int warp_m = (wid >> 2) * 64;
    int warp_n = (wid & 3) * 32;

    unsigned sA[3], sB1[3], sB3[3];
    #pragma unroll
    for (int i = 0; i < 3; i++) {
        sA[i]  = s2u(sm + i*GBM*LDP);
        sB1[i] = s2u(sm + (3 + i)*GBM*LDP);
        sB3[i] = s2u(sm + (6 + i)*GBM*LDP);
    }

    auto load_stage = [&](int s) {
        int b = s % 3;
        long k0 = (long)s * GBK;
        #pragma unroll
        for (int c = 0; c < 2; c++) {
            int id = tid + c*256;
            int r = id >> 2, ch = id & 3;
            CPA16(sA[b]  + (r*LDP + ch*8)*2, A  + (long)rowsrc[r]*K + k0 + ch*8);
            CPA16(sB1[b] + (r*LDP + ch*8)*2, W1 + (long)(tileN*GBN + r)*K + k0 + ch*8);
            CPA16(sB3[b] + (r*LDP + ch*8)*2, W3 + (long)(tileN*GBN + r)*K + k0 + ch*8);
        }
        asm volatile("cp.async.commit_group;");
    };

    float a1[4][4][4] = {};
    float a3[4][4][4] = {};
    int ns = K / GBK;
    load_stage(0);
    load_stage(1);

    for (int s = 0; s < ns; s++) {
        if (s + 1 < ns) asm volatile("cp.async.wait_group 1;");
        else            asm volatile("cp.async.wait_group 0;");
        __syncthreads();
        if (s + 2 < ns) load_stage(s + 2);
        int b = s % 3;
        #pragma unroll
        for (int kk = 0; kk < 2; kk++) {
            unsigned af[4][4], b1f[2][4], b3f[2][4];
            #pragma unroll
            for (int mi = 0; mi < 4; mi++) {
                int r = warp_m + mi*16 + (lane & 15);
                int cH = kk*16 + ((lane >> 4) << 3);
                ldm_x4(af[mi][0], af[mi][1], af[mi][2], af[mi][3], sA[b] + (r*LDP + cH)*2);
            }
            #pragma unroll
            for (int pj = 0; pj < 2; pj++) {
                int n = warp_n + pj*16 + (lane & 7) + ((lane >> 4) << 3);
                int cH = kk*16 + (((lane >> 3) & 1) << 3);
                ldm_x4(b1f[pj][0], b1f[pj][1], b1f[pj][2], b1f[pj][3], sB1[b] + (n*LDP + cH)*2);
                ldm_x4(b3f[pj][0], b3f[pj][1], b3f[pj][2], b3f[pj][3], sB3[b] + (n*LDP + cH)*2);
            }
            #pragma unroll
            for (int mi = 0; mi < 4; mi++)
                #pragma unroll
                for (int nj = 0; nj < 4; nj++) {
                    mma16816(a1[mi][nj][0], a1[mi][nj][1], a1[mi][nj][2], a1[mi][nj][3],
                             af[mi][0], af[mi][1], af[mi][2], af[mi][3],
                             b1f[nj >> 1][(nj & 1)*2], b1f[nj >> 1][(nj & 1)*2 + 1]);
                    mma16816(a3[mi][nj][0], a3[mi][nj][1], a3[mi][nj][2], a3[mi][nj][3],
                             af[mi][0], af[mi][1], af[mi][2], af[mi][3],
                             b3f[nj >> 1][(nj & 1)*2], b3f[nj >> 1][(nj & 1)*2 + 1]);
                }
        }
    }

    int lrow = lane >> 2;
    int lcol = (lane & 3) * 2;
    #pragma unroll
    for (int mi = 0; mi < 4; mi++) {
        #pragma unroll
        for (int half = 0; half < 2; half++) {
            int grow = row0 + warp_m + mi*16 + lrow + half*8;
            long obase = (long)grow*HDIM + tileN*GBN + warp_n;
            #pragma unroll
            for (int nj = 0; nj < 4; nj++) {
                float u0 = a1[mi][nj][half*2 + 0];
                float u1 = a1[mi][nj][half*2 + 1];
                float w0 = a3[mi][nj][half*2 + 0];
                float w1 = a3[mi][nj][half*2 + 1];
                float g0 = u0 / (1.f + __expf(-u0)) * w0;
                float g1 = u1 / (1.f + __expf(-u1)) * w1;
                *(__half2*)(G + obase + nj*8 + lcol) = __floats2half2_rn(g0, g1);
            }
        }
    }
}

// ---------------- FlashAttention-2 HMMA causal attention, 128-query tiles ----------------
#define ASTR 72
#define QKVS (3*CC)
#define FQT 128
#define DSM_F ((FQT*ASTR + 4*64*ASTR)*2)
__global__ __launch_bounds__(256)
void fattn_k(const __half* __restrict__ qkv, __half* __restrict__ y) {
    extern __shared__ __half fsm[];
    int qb = (int)gridDim.x - 1 - (int)blockIdx.x;
    int h = blockIdx.y, b = blockIdx.z;
    int tid = threadIdx.x, wid = tid >> 5, lane = tid & 31;

    unsigned uQ = s2u(fsm);
    unsigned uK[2] = { s2u(fsm + FQT*ASTR),              s2u(fsm + FQT*ASTR + 64*ASTR) };
    unsigned uV[2] = { s2u(fsm + FQT*ASTR + 2*64*ASTR),  s2u(fsm + FQT*ASTR + 3*64*ASTR) };

    long qbase = (long)(b*TT + qb*FQT)*QKVS + h*DD;
    #pragma unroll
    for (int c = 0; c < 4; c++) {
        int id = tid + c*256;
        int r = id >> 3, ch = id & 7;
        CPA16(uQ + (r*ASTR + ch*8)*2, qkv + qbase + (long)r*QKVS + ch*8);
    }
    asm volatile("cp.async.commit_group;");

    auto load_kv = [&](int s) {
        int bb = s & 1;
        long kvb = (long)(b*TT + s*64)*QKVS + h*DD + CC;
        #pragma unroll
        for (int c = 0; c < 2; c++) {
            int id = tid + c*256;
            int r = id >> 3, ch = id & 7;
            CPA16(uK[bb] + (r*ASTR + ch*8)*2, qkv + kvb + (long)r*QKVS + ch*8);
            CPA16(uV[bb] + (r*ASTR + ch*8)*2, qkv + kvb + CC + (long)r*QKVS + ch*8);
        }
        asm volatile("cp.async.commit_group;");
    };

    load_kv(0);
    asm volatile("cp.async.wait_group 0;");
    __syncthreads();

    unsigned qa[4][4];
    #pragma unroll
    for (int kk = 0; kk < 4; kk++) {
        int r = wid*16 + (lane & 15);
        int cH = kk*16 + ((lane >> 4) << 3);
        ldm_x4(qa[kk][0], qa[kk][1], qa[kk][2], qa[kk][3], uQ + (r*ASTR + cH)*2);
    }

    float m0 = -1e30f, m1 = -1e30f, l0 = 0.f, l1 = 0.f;
    float oa[8][4] = {};
    int nkt = 2*qb + 2;

    for (int kt = 0; kt < nkt; kt++) {
        if (kt + 1 < nkt) { load_kv(kt + 1); asm volatile("cp.async.wait_group 1;"); }
        else              { asm volatile("cp.async.wait_group 0;"); }
        __syncthreads();
        int bb = kt & 1;

        float sc[8][4] = {};
        #pragma unroll
        for (int kk = 0; kk < 4; kk++) {
            unsigned bf[4][4];
            #pragma unroll
            for (int pj = 0; pj < 4; pj++) {
                int n = pj*16 + (lane & 7) + ((lane >> 4) << 3);
                int cH = kk*16 + (((lane >> 3) & 1) << 3);
                ldm_x4(bf[pj][0], bf[pj][1], bf[pj][2], bf[pj][3], uK[bb] + (n*ASTR + cH)*2);
            }
            #pragma unroll
            for (int nj = 0; nj < 8; nj++)
                mma16816(sc[nj][0], sc[nj][1], sc[nj][2], sc[nj][3],
                         qa[kk][0], qa[kk][1], qa[kk][2], qa[kk][3],
                         bf[nj >> 1][(nj & 1)*2], bf[nj >> 1][(nj & 1)*2 + 1]);
        }

        if (kt >= 2*qb) {
            int rg = qb*FQT + wid*16 + (lane >> 2);
            #pragma unroll
            for (int nj = 0; nj < 8; nj++) {
                int cg = kt*64 + nj*8 + (lane & 3)*2;
                if (cg     > rg)   sc[nj][0] = -1e30f;
                if (cg + 1 > rg)   sc[nj][1] = -1e30f;
                if (cg     > rg+8) sc[nj][2] = -1e30f;
                if (cg + 1 > rg+8) sc[nj][3] = -1e30f;
            }
        }

        float rm0 = -1e30f, rm1 = -1e30f;
        #pragma unroll
        for (int nj = 0; nj < 8; nj++) {
            rm0 = fmaxf(rm0, fmaxf(sc[nj][0], sc[nj][1]));
            rm1 = fmaxf(rm1, fmaxf(sc[nj][2], sc[nj][3]));
        }
        rm0 = fmaxf(rm0, __shfl_xor_sync(0xffffffffu, rm0, 1));
        rm0 = fmaxf(rm0, __shfl_xor_sync(0xffffffffu, rm0, 2));
        rm1 = fmaxf(rm1, __shfl_xor_sync(0xffffffffu, rm1, 1));
        rm1 = fmaxf(rm1, __shfl_xor_sync(0xffffffffu, rm1, 2));
        float mn0 = fmaxf(m0, rm0), mn1 = fmaxf(m1, rm1);
        float corr0 = __expf(m0 - mn0), corr1 = __expf(m1 - mn1);
        m0 = mn0; m1 = mn1;

        unsigned pa[4][4];
        float ps0 = 0.f, ps1 = 0.f;
        #pragma unroll
        for (int j = 0; j < 4; j++) {
            float p00 = __expf(sc[2*j][0]   - m0), p01 = __expf(sc[2*j][1]   - m0);
            float p02 = __expf(sc[2*j][2]   - m1), p03 = __expf(sc[2*j][3]   - m1);
            float p10 = __expf(sc[2*j+1][0] - m0), p11 = __expf(sc[2*j+1][1] - m0);
            float p12 = __expf(sc[2*j+1][2] - m1), p13 = __expf(sc[2*j+1][3] - m1);
            ps0 += p00 + p01 + p10 + p11;
            ps1 += p02 + p03 + p12 + p13;
            __half2 h0 = __floats2half2_rn(p00, p01);
            __half2 h1 = __floats2half2_rn(p02, p03);
            __half2 h2 = __floats2half2_rn(p10, p11);
            __half2 h3 = __floats2half2_rn(p12, p13);
            pa[j][0] = *(unsigned*)&h0;
            pa[j][1] = *(unsigned*)&h1;
            pa[j][2] = *(unsigned*)&h2;
            pa[j][3] = *(unsigned*)&h3;
        }
        ps0 += __shfl_xor_sync(0xffffffffu, ps0, 1);
        ps0 += __shfl_xor_sync(0xffffffffu, ps0, 2);
        ps1 += __shfl_xor_sync(0xffffffffu, ps1, 1);
        ps1 += __shfl_xor_sync(0xffffffffu, ps1, 2);
        l0 = l0*corr0 + ps0;
        l1 = l1*corr1 + ps1;

        #pragma unroll
        for (int nj = 0; nj < 8; nj++) {
            oa[nj][0] *= corr0; oa[nj][1] *= corr0;
            oa[nj][2] *= corr1; oa[nj][3] *= corr1;
        }

        #pragma unroll
        for (int j = 0; j < 4; j++) {
            unsigned vf[4][4];
            #pragma unroll
            for (int pd = 0; pd < 4; pd++) {
                int r = j*16 + (lane & 15);
                int cH = pd*16 + ((lane >> 4) << 3);
                ldm_x4t(vf[pd][0], vf[pd][1], vf[pd][2], vf[pd][3], uV[bb] + (r*ASTR + cH)*2);
            }
            #pragma unroll
            for (int dn = 0; dn < 8; dn++)
                mma16816(oa[dn][0], oa[dn][1], oa[dn][2], oa[dn][3],
                         pa[j][0], pa[j][1], pa[j][2], pa[j][3],
                         vf[dn >> 1][(dn & 1)*2], vf[dn >> 1][(dn & 1)*2 + 1]);
        }
        __syncthreads();
    }

    float il0 = 1.f/l0, il1 = 1.f/l1;
    int r0 = qb*FQT + wid*16 + (lane >> 2);
    #pragma unroll
    for (int dn = 0; dn < 8; dn++) {
        int col = dn*8 + (lane & 3)*2;
        long o0 = ((long)(b*TT + r0)*HH + h)*DD + col;
        long o1 = ((long)(b*TT + r0 + 8)*HH + h)*DD + col;
        *(__half2*)(y + o0) = __floats2half2_rn(oa[dn][0]*il0, oa[dn][1]*il0);
        *(__half2*)(y + o1) = __floats2half2_rn(oa[dn][2]*il1, oa[dn][3]*il1);
    }
}

// ---------------- MoE router: cached-row single pass ----------------
__global__ void router_k(const float* __restrict__ hn, const float* __restrict__ rw,
                         int* __restrict__ idx2, float* __restrict__ wts2,
                         int* __restrict__ counts) {
    int warp = (blockIdx.x*blockDim.x + threadIdx.x) >> 5;
    int lane = threadIdx.x & 31;
    if (warp >= M0) return;
    float reg[32];
    #pragma unroll
    for (int i = 0; i < 32; i++) reg[i] = hn[(long)warp*CC + lane + i*32];
    float lg[EE];
    #pragma unroll
    for (int e = 0; e < EE; e++) {
        float s = 0.f;
        #pragma unroll
        for (int i = 0; i < 32; i++) s += reg[i]*rw[e*CC + lane + i*32];
        #pragma unroll
        for (int o = 16; o > 0; o >>= 1) s += __shfl_down_sync(0xffffffffu, s, o);
        lg[e] = __shfl_sync(0xffffffffu, s, 0);
    }
    if (lane == 0) {
        int i0 = 0;
        for (int e = 1; e < EE; e++) if (lg[e] > lg[i0]) i0 = e;
        int i1 = -1;
        for (int e = 0; e < EE; e++) {
            if (e == i0) continue;
            if (i1 < 0 || lg[e] > lg[i1]) i1 = e;
        }
        float e1 = __expf(lg[i1] - lg[i0]);
        float s  = 1.f + e1;
        idx2[warp*2]   = i0; idx2[warp*2+1] = i1;
        wts2[warp*2]   = 1.f/s; wts2[warp*2+1] = e1/s;
        atomicAdd(&counts[i0], 1); atomicAdd(&counts[i1], 1);
    }
}

__global__ void offsets_k(const int* counts, int* poff, int* cursor) {
    if (threadIdx.x == 0 && blockIdx.x == 0) {
        int o = 0;
        for (int e = 0; e < EE; e++) {
            poff[e] = o; cursor[e] = 0;
            o += ((counts[e] + 127)/128)*128;
        }
        poff[EE] = o;
    }
}

__global__ void scatter_k(const int* __restrict__ idx2, const float* __restrict__ wts2,
                          int* __restrict__ cursor, const int* __restrict__ poff,
                          int* __restrict__ perm, float* __restrict__ gatew) {
    int t = blockIdx.x*blockDim.x + threadIdx.x;
    if (t >= M0) return;
    for (int kk = 0; kk < 2; kk++) {
        int e = idx2[t*2 + kk];
        int pos = atomicAdd(&cursor[e], 1);
        int r = poff[e] + pos;
        perm[r] = t; gatew[r] = wts2[t*2 + kk];
    }
}

// ---------------- launch ----------------
static void* sym(const void* s) { void* p = nullptr; cudaGetSymbolAddress(&p, s); return p; }

extern "C" void kernel_launch(void* const* d_in, const int* in_sizes, int n_in,
                              void* d_out, int out_size) {
    const float* x    = (const float*)d_in[0];
    const float* rc   = (const float*)d_in[1];
    const float* rs   = (const float*)d_in[2];
    const float* anw  = (const float*)d_in[3];
    const float* qw   = (const float*)d_in[4];
    const float* kw   = (const float*)d_in[5];
    const float* vw   = (const float*)d_in[6];
    const float* ow   = (const float*)d_in[7];
    const float* fnw  = (const float*)d_in[8];
    const float* rw   = (const float*)d_in[9];
    const float* w1   = (const float*)d_in[10];
    const float* w2   = (const float*)d_in[11];
    const float* w3   = (const float*)d_in[12];
    float* out = (float*)d_out;

    float*  hn    = (float*)sym(g_hn);
    __half* h16   = (__half*)sym(g_h16);
    __half* qkv16 = (__half*)sym(g_qkv16);
    __half* y16   = (__half*)sym(g_y16);
    __half* hn16  = (__half*)sym(g_hn16);
    __half* gb16  = (__half*)sym(g_gb16);
    __half* w16   = (__half*)sym(g_w16all);
    __half* wqkv16= w16;
    __half* ow16  = w16 + OFF_OW;
    __half* w116  = w16 + OFF_W1;
    __half* w216  = w16 + OFF_W2;
    __half* w316  = w16 + OFF_W3;
    int*   counts = (int*)sym(g_counts);
    int*   cursor = (int*)sym(g_cursor);
    int*   poff   = (int*)sym(g_poff);
    int*   perm   = (int*)sym(g_perm);
    float* gatew  = (float*)sym(g_gatew);
    int*   idx2   = (int*)sym(g_idx2);
    float* wts2   = (float*)sym(g_wts2);

    cudaFuncSetAttribute(gemm16_k, cudaFuncAttributeMaxDynamicSharedMemorySize, DSM_G);
    cudaFuncSetAttribute(moe13_k, cudaFuncAttributeMaxDynamicSharedMemorySize, DSM_M);
    cudaFuncSetAttribute(fattn_k, cudaFuncAttributeMaxDynamicSharedMemorySize, DSM_F);

    // 0) fused weight conversion + MoE bookkeeping init
    int ncv = 4*N4C + 3*N4E;
    convw_k<<<(ncv + 255)/256, 256>>>((const float4*)qw, (const float4*)kw, (const float4*)vw,
                                      (const float4*)ow, (const float4*)w1, (const float4*)w2,
                                      (const float4*)w3, (__half2*)w16, counts, perm, gatew);
    // 1) attn rmsnorm (fp16 out)
    rmsnorm_k<<<M0, 256>>>(x, anw, nullptr, h16);
    // 2) fused QKV projection with rope applied in epilogue (fp16 out)
    gemm16_k<<<dim3(3*CC/GBN, M0/GBM), 128, DSM_G>>>(h16, wqkv16, nullptr, qkv16, 3*CC, CC,
                                                     nullptr, nullptr, nullptr, nullptr, 0, nullptr, rc, rs);
    // 3) causal flash attention (128-query tiles)
    fattn_k<<<dim3(TT/FQT, HH, BB), 256, DSM_F>>>(qkv16, y16);
    // 4) output projection + residual -> out
    gemm16_k<<<dim3(CC/GBN, M0/GBM), 128, DSM_G>>>(y16, ow16, out, nullptr, CC, CC,
                                                   x, nullptr, nullptr, nullptr, 0, nullptr, nullptr, nullptr);
    // 5) ffn rmsnorm reads out
    rmsnorm_k<<<M0, 256>>>(out, fnw, hn, hn16);
    // 6) router + gather bookkeeping
    router_k<<<(M0*32 + 255)/256, 256>>>(hn, rw, idx2, wts2, counts);
    offsets_k<<<1, 32>>>(counts, poff, cursor);
    scatter_k<<<(M0 + 255)/256, 256>>>(idx2, wts2, cursor, poff, perm, gatew);
    // 7) fused expert up-projection + silu*mul (padding tiles early-exit)
    moe13_k<<<dim3(HDIM/GBN, MG/GBM), 256, DSM_M>>>(hn16, w116, w316, gb16, perm, poff);
    //    down-projection: gate-scaled atomic scatter into out (padding tiles early-exit)
    gemm16_k<<<dim3(CC/GBN, MG/GBM), 128, DSM_G>>>(gb16, w216, out, nullptr, CC, HDIM,
                                                   nullptr, nullptr, poff, gatew, (long)CC*HDIM, perm, nullptr, nullptr);
}

// round 11
// speedup vs baseline: 7.2706x; 1.0295x over previous
#include <cuda_runtime.h>
#include <cuda_fp16.h>
#include <cstdint>
#include <stdint.h>
#include <math.h>

// ---------------- problem constants ----------------
#define BB 2
#define TT 2048
#define CC 1024
#define HH 16
#define DD 64
#define EE 8
#define HDIM 1536
#define M0 (BB*TT)
#define MG 9216
#define EPSV 1e-6f

#define N4C (CC*CC/4)
#define N4E (EE*HDIM*CC/4)
#define OFF_OW (3*CC*CC)
#define OFF_W1 (4*CC*CC)
#define OFF_W2 (OFF_W1 + EE*HDIM*CC)
#define OFF_W3 (OFF_W2 + EE*HDIM*CC)
#define W16TOT (OFF_W3 + EE*HDIM*CC)

// ---------------- device scratch ----------------
__device__ __half g_h16 [M0*CC];
__device__ __half g_qkv16[M0*3*CC];
__device__ __half g_y16 [M0*CC];
__device__ __half g_hn16[M0*CC];
__device__ __half g_gb16[MG*HDIM];
__device__ __half g_w16all[W16TOT];
__device__ int    g_counts[EE];
__device__ int    g_cursor[EE];
__device__ int    g_poff[EE+1];
__device__ int    g_perm[MG];
__device__ float  g_gatew[MG];
__device__ int    g_idx2[M0*2];
__device__ float  g_wts2[M0*2];

// ---------------- PTX helpers ----------------
__device__ __forceinline__ unsigned s2u(const void* p) {
    unsigned a;
    asm("{ .reg .u64 t; cvta.to.shared.u64 t, %1; cvt.u32.u64 %0, t; }" : "=r"(a) : "l"(p));
    return a;
}
__device__ __forceinline__ void ldm_x4(unsigned& r0, unsigned& r1, unsigned& r2, unsigned& r3, unsigned a) {
    asm volatile("ldmatrix.sync.aligned.m8n8.x4.shared.b16 {%0,%1,%2,%3}, [%4];"
                 : "=r"(r0), "=r"(r1), "=r"(r2), "=r"(r3) : "r"(a));
}
__device__ __forceinline__ void ldm_x4t(unsigned& r0, unsigned& r1, unsigned& r2, unsigned& r3, unsigned a) {
    asm volatile("ldmatrix.sync.aligned.m8n8.x4.trans.shared.b16 {%0,%1,%2,%3}, [%4];"
                 : "=r"(r0), "=r"(r1), "=r"(r2), "=r"(r3) : "r"(a));
}
__device__ __forceinline__ void mma16816(float& d0, float& d1, float& d2, float& d3,
                                         unsigned a0, unsigned a1, unsigned a2, unsigned a3,
                                         unsigned b0, unsigned b1) {
    asm volatile("mma.sync.aligned.m16n8k16.row.col.f32.f16.f16.f32 "
                 "{%0,%1,%2,%3}, {%4,%5,%6,%7}, {%8,%9}, {%0,%1,%2,%3};"
                 : "+f"(d0), "+f"(d1), "+f"(d2), "+f"(d3)
                 : "r"(a0), "r"(a1), "r"(a2), "r"(a3), "r"(b0), "r"(b1));
}
#define CPA16(dst, src) asm volatile("cp.async.cg.shared.global [%0], [%1], 16;" :: "r"(dst), "l"(src))

#define QSCALE (0.125f * 1.4426950408889634f)   // 1/sqrt(D) * log2(e)

// ---------------- fused weight conversion + MoE bookkeeping init ----------------
__global__ void convw_k(const float4* __restrict__ q, const float4* __restrict__ k,
                        const float4* __restrict__ v, const float4* __restrict__ o,
                        const float4* __restrict__ w1, const float4* __restrict__ w2,
                        const float4* __restrict__ w3, __half2* __restrict__ dst,
                        int* __restrict__ counts, int* __restrict__ perm,
                        float* __restrict__ gatew) {
    int i = blockIdx.x*blockDim.x + threadIdx.x;
    if (i < EE) counts[i] = 0;
    if (i < MG) { perm[i] = 0; gatew[i] = 0.f; }
    if (i >= 4*N4C + 3*N4E) return;
    const float4* s;
    long base;
    if (i < 4*N4C) {
        int seg = i / N4C, off = i - seg*N4C;
        s = (seg == 0 ? q : seg == 1 ? k : seg == 2 ? v : o) + off;
        base = (long)seg*N4C + off;
    } else {
        int j = i - 4*N4C;
        int seg = j / N4E, off = j - seg*N4E;
        s = (seg == 0 ? w1 : seg == 1 ? w2 : w3) + off;
        base = (long)4*N4C + (long)seg*N4E + off;
    }
    float4 val = *s;
    dst[base*2]   = __floats2half2_rn(val.x, val.y);
    dst[base*2+1] = __floats2half2_rn(val.z, val.w);
}

// ---------------- RMSNorm (fp16 out) ----------------
__global__ void rmsnorm_k(const float* __restrict__ x, const float* __restrict__ w,
                          __half* __restrict__ o16) {
    int row = blockIdx.x;
    const float* xr = x + (long)row*CC;
    __shared__ float red[256];
    float s = 0.f;
    for (int c = threadIdx.x; c < CC; c += 256) { float v = xr[c]; s += v*v; }
    red[threadIdx.x] = s; __syncthreads();
    for (int st = 128; st > 0; st >>= 1) {
        if (threadIdx.x < st) red[threadIdx.x] += red[threadIdx.x+st];
        __syncthreads();
    }
    float inv = rsqrtf(red[0]/(float)CC + EPSV);
    for (int c = threadIdx.x; c < CC; c += 256)
        o16[(long)row*CC + c] = __float2half(w[c]*xr[c]*inv);
}

// ---------------- fused ffn RMSNorm + router (per-row block) ----------------
__global__ void rmsnorm_router_k(const float* __restrict__ x, const float* __restrict__ w,
                                 __half* __restrict__ o16, const float* __restrict__ rw,
                                 int* __restrict__ idx2, float* __restrict__ wts2,
                                 int* __restrict__ counts) {
    int row = blockIdx.x;
    int tid = threadIdx.x, wid = tid >> 5, lane = tid & 31;
    const float* xr = x + (long)row*CC;
    __shared__ float sv[CC];
    __shared__ float red[256];
    __shared__ float lg[EE];
    float s = 0.f;
    #pragma unroll
    for (int j = 0; j < 4; j++) { float v = xr[tid + j*256]; s += v*v; }
    red[tid] = s; __syncthreads();
    for (int st = 128; st > 0; st >>= 1) {
        if (tid < st) red[tid] += red[tid+st];
        __syncthreads();
    }
    float inv = rsqrtf(red[0]/(float)CC + EPSV);
    #pragma unroll
    for (int j = 0; j < 4; j++) {
        int c = tid + j*256;
        float v = w[c]*xr[c]*inv;
        sv[c] = v;
        o16[(long)row*CC + c] = __float2half(v);
    }
    __syncthreads();
    // warp wid computes logit for expert wid
    {
        const float* rwe = rw + wid*CC;
        float acc = 0.f;
        #pragma unroll
        for (int i = 0; i < 32; i++) acc += sv[lane + i*32]*rwe[lane + i*32];
        #pragma unroll
        for (int o = 16; o > 0; o >>= 1) acc += __shfl_down_sync(0xffffffffu, acc, o);
        if (lane == 0) lg[wid] = acc;
    }
    __syncthreads();
    if (tid == 0) {
        int i0 = 0;
        #pragma unroll
        for (int e = 1; e < EE; e++) if (lg[e] > lg[i0]) i0 = e;
        int i1 = -1;
        #pragma unroll
        for (int e = 0; e < EE; e++) {
            if (e == i0) continue;
            if (i1 < 0 || lg[e] > lg[i1]) i1 = e;
        }
        float e1 = __expf(lg[i1] - lg[i0]);
        float sm = 1.f + e1;
        idx2[row*2]   = i0; idx2[row*2+1] = i1;
        wts2[row*2]   = 1.f/sm; wts2[row*2+1] = e1/sm;
        atomicAdd(&counts[i0], 1); atomicAdd(&counts[i1], 1);
    }
}

// ---------------- HMMA fp16 GEMM, 64x64 warp tiles, 3-stage; rope-fused fp16 epilogue ----------------
#define GBM 128
#define GBN 128
#define GBK 32
#define LDP 40
#define DSM_G (6*GBM*LDP*2)
__global__ __launch_bounds__(128)
void gemm16_k(const __half* __restrict__ A, const __half* __restrict__ Wb,
              float* __restrict__ Cout, __half* __restrict__ Cout16,
              int N, int K,
              const float* __restrict__ R,
              const int* __restrict__ perm,
              const int* __restrict__ poff,
              const float* __restrict__ rowscale,
              long wstride,
              const int* __restrict__ sperm,
              const float* __restrict__ ropeC,
              const float* __restrict__ ropeS) {
    extern __shared__ __half gsm[];
    __shared__ int rowsrc[GBM];

    int tid = threadIdx.x, wid = tid >> 5, lane = tid & 31;
    int tileN = blockIdx.x, tileM = blockIdx.y;
    int row0 = tileM*GBM;

    const __half* W = Wb;
    if (poff) {
        if (row0 >= poff[EE]) return;
        int e = 0;
        #pragma unroll
        for (int q2 = 1; q2 < EE; q2++) if (row0 >= poff[q2]) e = q2;
        W += (long)e * wstride;
    }
    if (tid < GBM) rowsrc[tid] = perm ? perm[row0 + tid] : (row0 + tid);
    __syncthreads();

    int warp_m = (wid & 1) * 64;
    int warp_n = (wid >> 1) * 64;

    unsigned sA[3], sB[3];
    #pragma unroll
    for (int i = 0; i < 3; i++) {
        sA[i] = s2u(gsm + i*GBM*LDP);
        sB[i] = s2u(gsm + (3 + i)*GBM*LDP);
    }

    auto load_stage = [&](int s) {
        int b = s % 3;
        long k0 = (long)s * GBK;
        #pragma unroll
        for (int c = 0; c < 4; c++) {
            int id = tid + c*128;
            int r = id >> 2, ch = id & 3;
            CPA16(sA[b] + (r*LDP + ch*8)*2, A + (long)rowsrc[r]*K + k0 + ch*8);
            CPA16(sB[b] + (r*LDP + ch*8)*2, W + (long)(tileN*GBN + r)*K + k0 + ch*8);
        }
        asm volatile("cp.async.commit_group;");
    };

    float acc[4][8][4] = {};
    int ns = K / GBK;
    load_stage(0);
    load_stage(1);

    for (int s = 0; s < ns; s++) {
        if (s + 1 < ns) asm volatile("cp.async.wait_group 1;");
        else            asm volatile("cp.async.wait_group 0;");
        __syncthreads();
        if (s + 2 < ns) load_stage(s + 2);
        int b = s % 3;
        #pragma unroll
        for (int kk = 0; kk < 2; kk++) {
            unsigned af[4][4], bf[4][4];
            #pragma unroll
            for (int mi = 0; mi < 4; mi++) {
                int r = warp_m + mi*16 + (lane & 15);
                int cH = kk*16 + ((lane >> 4) << 3);
                ldm_x4(af[mi][0], af[mi][1], af[mi][2], af[mi][3], sA[b] + (r*LDP + cH)*2);
            }
            #pragma unroll
            for (int pj = 0; pj < 4; pj++) {
                int n = warp_n + pj*16 + (lane & 7) + ((lane >> 4) << 3);
                int cH = kk*16 + (((lane >> 3) & 1) << 3);
                ldm_x4(bf[pj][0], bf[pj][1], bf[pj][2], bf[pj][3], sB[b] + (n*LDP + cH)*2);
            }
            #pragma unroll
            for (int mi = 0; mi < 4; mi++)
                #pragma unroll
                for (int nj = 0; nj < 8; nj++)
                    mma16816(acc[mi][nj][0], acc[mi][nj][1], acc[mi][nj][2], acc[mi][nj][3],
                             af[mi][0], af[mi][1], af[mi][2], af[mi][3],
                             bf[nj >> 1][(nj & 1)*2], bf[nj >> 1][(nj & 1)*2 + 1]);
        }
    }

    int lrow = lane >> 2;
    int lcol = (lane & 3) * 2;
    #pragma unroll
    for (int mi = 0; mi < 4; mi++) {
        #pragma unroll
        for (int half = 0; half < 2; half++) {
            int grow = row0 + warp_m + mi*16 + lrow + half*8;
            float sc = rowscale ? rowscale[grow] : 1.f;
            if (sperm) {
                if (sc != 0.f) {
                    int token = sperm[grow];
                    long obase = (long)token*N + tileN*GBN + warp_n;
                    #pragma unroll
                    for (int nj = 0; nj < 8; nj++) {
                        long off = obase + nj*8 + lcol;
                        atomicAdd(&Cout[off],     acc[mi][nj][half*2 + 0] * sc);
                        atomicAdd(&Cout[off + 1], acc[mi][nj][half*2 + 1] * sc);
                    }
                }
            } else if (ropeC) {
                // rope-fused fp16 epilogue; q additionally scaled by 1/sqrt(D)*log2e for exp2 softmax
                int t = grow & (TT-1);
                long obase = (long)grow*N + tileN*GBN + warp_n;
                #pragma unroll
                for (int nj = 0; nj < 4; nj++) {
                    int colg = tileN*GBN + warp_n + nj*8 + lcol;
                    int seg = colg >> 10;            // 0=q,1=k,2=v
                    int d = colg & 63;               // 0..31 within head
                    float x1a = acc[mi][nj][half*2 + 0];
                    float x1b = acc[mi][nj][half*2 + 1];
                    float x2a = acc[mi][nj+4][half*2 + 0];
                    float x2b = acc[mi][nj+4][half*2 + 1];
                    if (seg < 2) {
                        const float* ct = ropeC + t*DD;
                        const float* st = ropeS + t*DD;
                        float c1a = ct[d],    c1b = ct[d+1];
                        float c2a = ct[d+32], c2b = ct[d+33];
                        float s1a = st[d],    s1b = st[d+1];
                        float s2a = st[d+32], s2b = st[d+33];
                        float o1a = x1a*c1a - x2a*s1a;
                        float o1b = x1b*c1b - x2b*s1b;
                        float o2a = x2a*c2a + x1a*s2a;
                        float o2b = x2b*c2b + x1b*s2b;
                        if (seg == 0) { o1a *= QSCALE; o1b *= QSCALE; o2a *= QSCALE; o2b *= QSCALE; }
                        x1a = o1a; x1b = o1b; x2a = o2a; x2b = o2b;
                    }
                    *(__half2*)(Cout16 + obase + nj*8 + lcol)        = __floats2half2_rn(x1a, x1b);
                    *(__half2*)(Cout16 + obase + (nj+4)*8 + lcol)    = __floats2half2_rn(x2a, x2b);
                }
            } else {
                long obase = (long)grow*N + tileN*GBN + warp_n;
                #pragma unroll
                for (int nj = 0; nj < 8; nj++) {
                    float vx = acc[mi][nj][half*2 + 0] * sc;
                    float vy = acc[mi][nj][half*2 + 1] * sc;
                    long off = obase + nj*8 + lcol;
                    if (Cout16) {
                        *(__half2*)(Cout16 + off) = __floats2half2_rn(vx, vy);
                    } else {
                        if (R) {
                            const float2 rv = *(const float2*)(R + off);
                            vx += rv.x; vy += rv.y;
                        }
                        float2 vv = { vx, vy };
                        *(float2*)(Cout + off) = vv;
                    }
                }
            }
        }
    }
}

// ---------------- fused MoE w1/w3 GEMM + silu*mul -> fp16, 3-stage ----------------
#define DSM_M (9*GBM*LDP*2)
__global__ __launch_bounds__(256)
void moe13_k(const __half* __restrict__ A, const __half* __restrict__ W1b,
             const __half* __restrict__ W3b, __half* __restrict__ G,
             const int* __restrict__ perm, const int* __restrict__ poff) {
    extern __shared__ __half sm[];
    __shared__ int rowsrc[GBM];

    int tid = threadIdx.x, wid = tid >> 5, lane = tid & 31;
    int tileN = blockIdx.x, tileM = blockIdx.y;
    int row0 = tileM*GBM;
    const int K = CC;

    if (row0 >= poff[EE]) return;
    int e = 0;
    #pragma unroll
    for (int q2 = 1; q2 < EE; q2++) if (row0 >= poff[q2]) e = q2;
    const __half* W1 = W1b + (long)e*HDIM*CC;
    const __half* W3 = W3b + (long)e*HDIM*CC;

    if (tid < GBM) rowsrc[tid] = perm[row0 + tid];
    __syncthreads();

    int warp_m = (wid >> 2) * 64;
    int warp_n = (wid & 3) * 32;

    unsigned sA[3], sB1[3], sB3[3];
    #pragma unroll
    for (int i = 0; i < 3; i++) {
        sA[i]  = s2u(sm + i*GBM*LDP);
        sB1[i] = s2u(sm + (3 + i)*GBM*LDP);
        sB3[i] = s2u(sm + (6 + i)*GBM*LDP);
    }

    auto load_stage = [&](int s) {
        int b = s % 3;
        long k0 = (long)s * GBK;
        #pragma unroll
        for (int c = 0; c < 2; c++) {
            int id = tid + c*256;
            int r = id >> 2, ch = id & 3;
            CPA16(sA[b]  + (r*LDP + ch*8)*2, A  + (long)rowsrc[r]*K + k0 + ch*8);
            CPA16(sB1[b] + (r*LDP + ch*8)*2, W1 + (long)(tileN*GBN + r)*K + k0 + ch*8);
            CPA16(sB3[b] + (r*LDP + ch*8)*2, W3 + (long)(tileN*GBN + r)*K + k0 + ch*8);
        }
        asm volatile("cp.async.commit_group;");
    };

    float a1[4][4][4] = {};
    float a3[4][4][4] = {};
    int ns = K / GBK;
    load_stage(0);
    load_stage(1);

    for (int s = 0; s < ns; s++) {
        if (s + 1 < ns) asm volatile("cp.async.wait_group 1;");
        else            asm volatile("cp.async.wait_group 0;");
        __syncthreads();
        if (s + 2 < ns) load_stage(s + 2);
        int b = s % 3;
        #pragma unroll
        for (int kk = 0; kk < 2; kk++) {
            unsigned af[4][4], b1f[2][4], b3f[2][4];
            #pragma unroll
            for (int mi = 0; mi < 4; mi++) {
                int r = warp_m + mi*16 + (lane & 15);
                int cH = kk*16 + ((lane >> 4) << 3);
                ldm_x4(af[mi][0], af[mi][1], af[mi][2], af[mi][3], sA[b] + (r*LDP + cH)*2);
            }
            #pragma unroll
            for (int pj = 0; pj < 2; pj++) {
                int n = warp_n + pj*16 + (lane & 7) + ((lane >> 4) << 3);
                int cH = kk*16 + (((lane >> 3) & 1) << 3);
                ldm_x4(b1f[pj][0], b1f[pj][1], b1f[pj][2], b1f[pj][3], sB1[b] + (n*LDP + cH)*2);
                ldm_x4(b3f[pj][0], b3f[pj][1], b3f[pj][2], b3f[pj][3], sB3[b] + (n*LDP + cH)*2);
            }
            #pragma unroll
            for (int mi = 0; mi < 4; mi++)
                #pragma unroll
                for (int nj = 0; nj < 4; nj++) {
                    mma16816(a1[mi][nj][0], a1[mi][nj][1], a1[mi][nj][2], a1[mi][nj][3],
                             af[mi][0], af[mi][1], af[mi][2], af[mi][3],
                             b1f[nj >> 1][(nj & 1)*2], b1f[nj >> 1][(nj & 1)*2 + 1]);
                    mma16816(a3[mi][nj][0], a3[mi][nj][1], a3[mi][nj][2], a3[mi][nj][3],
                             af[mi][0], af[mi][1], af[mi][2], af[mi][3],
                             b3f[nj >> 1][(nj & 1)*2], b3f[nj >> 1][(nj & 1)*2 + 1]);
                }
        }
    }

    int lrow = lane >> 2;
    int lcol = (lane & 3) * 2;
    #pragma unroll
    for (int mi = 0; mi < 4; mi++) {
        #pragma unroll
        for (int half = 0; half < 2; half++) {
            int grow = row0 + warp_m + mi*16 + lrow + half*8;
            long obase = (long)grow*HDIM + tileN*GBN + warp_n;
            #pragma unroll
            for (int nj = 0; nj < 4; nj++) {
                float u0 = a1[mi][nj][half*2 + 0];
                float u1 = a1[mi][nj][half*2 + 1];
                float w0 = a3[mi][nj][half*2 + 0];
                float w1 = a3[mi][nj][half*2 + 1];
                float g0 = u0 / (1.f + __expf(-u0)) * w0;
                float g1 = u1 / (1.f + __expf(-u1)) * w1;
                *(__half2*)(G + obase + nj*8 + lcol) = __floats2half2_rn(g0, g1);
            }
        }
    }
}

// ---------------- FlashAttention-2 HMMA causal attention, 128-query tiles, exp2 softmax ----------------
#define ASTR 72
#define QKVS (3*CC)
#define FQT 128
#define DSM_F ((FQT*ASTR + 4*64*ASTR)*2)
__global__ __launch_bounds__(256)
void fattn_k(const __half* __restrict__ qkv, __half* __restrict__ y) {
    extern __shared__ __half fsm[];
    int qb = (int)gridDim.x - 1 - (int)blockIdx.x;
    int h = blockIdx.y, b = blockIdx.z;
    int tid = threadIdx.x, wid = tid >> 5, lane = tid & 31;

    unsigned uQ = s2u(fsm);
    unsigned uK[2] = { s2u(fsm + FQT*ASTR),              s2u(fsm + FQT*ASTR + 64*ASTR) };
    unsigned uV[2] = { s2u(fsm + FQT*ASTR + 2*64*ASTR),  s2u(fsm + FQT*ASTR + 3*64*ASTR) };

    long qbase = (long)(b*TT + qb*FQT)*QKVS + h*DD;
    #pragma unroll
    for (int c = 0; c < 4; c++) {
        int id = tid + c*256;
        int r = id >> 3, ch = id & 7;
        CPA16(uQ + (r*ASTR + ch*8)*2, qkv + qbase + (long)r*QKVS + ch*8);
    }
    asm volatile("cp.async.commit_group;");

    auto load_kv = [&](int s) {
        int bb = s & 1;
        long kvb = (long)(b*TT + s*64)*QKVS + h*DD + CC;
        #pragma unroll
        for (int c = 0; c < 2; c++) {
            int id = tid + c*256;
            int r = id >> 3, ch = id & 7;
            CPA16(uK[bb] + (r*ASTR + ch*8)*2, qkv + kvb + (long)r*QKVS + ch*8);
            CPA16(uV[bb] + (r*ASTR + ch*8)*2, qkv + kvb + CC + (long)r*QKVS + ch*8);
        }
        asm volatile("cp.async.commit_group;");
    };

    load_kv(0);
    asm volatile("cp.async.wait_group 0;");
    __syncthreads();

    unsigned qa[4][4];
    #pragma unroll
    for (int kk = 0; kk < 4; kk++) {
        int r = wid*16 + (lane & 15);
        int cH = kk*16 + ((lane >> 4) << 3);
        ldm_x4(qa[kk][0], qa[kk][1], qa[kk][2], qa[kk][3], uQ + (r*ASTR + cH)*2);
    }

    float m0 = -1e30f, m1 = -1e30f, l0 = 0.f, l1 = 0.f;
    float oa[8][4] = {};
    int nkt = 2*qb + 2;

    for (int kt = 0; kt < nkt; kt++) {
        if (kt + 1 < nkt) { load_kv(kt + 1); asm volatile("cp.async.wait_group 1;"); }
        else              { asm volatile("cp.async.wait_group 0;"); }
        __syncthreads();
        int bb = kt & 1;

        float sc[8][4] = {};
        #pragma unroll
        for (int kk = 0; kk < 4; kk++) {
            unsigned bf[4][4];
            #pragma unroll
            for (int pj = 0; pj < 4; pj++) {
                int n = pj*16 + (lane & 7) + ((lane >> 4) << 3);
                int cH = kk*16 + (((lane >> 3) & 1) << 3);
                ldm_x4(bf[pj][0], bf[pj][1], bf[pj][2], bf[pj][3], uK[bb] + (n*ASTR + cH)*2);
            }
            #pragma unroll
            for (int nj = 0; nj < 8; nj++)
                mma16816(sc[nj][0], sc[nj][1], sc[nj][2], sc[nj][3],
                         qa[kk][0], qa[kk][1], qa[kk][2], qa[kk][3],
                         bf[nj >> 1][(nj & 1)*2], bf[nj >> 1][(nj & 1)*2 + 1]);
        }

        if (kt >= 2*qb) {
            int rg = qb*FQT + wid*16 + (lane >> 2);
            #pragma unroll
            for (int nj = 0; nj < 8; nj++) {
                int cg = kt*64 + nj*8 + (lane & 3)*2;
                if (cg     > rg)   sc[nj][0] = -1e30f;
                if (cg + 1 > rg)   sc[nj][1] = -1e30f;
                if (cg     > rg+8) sc[nj][2] = -1e30f;
                if (cg + 1 > rg+8) sc[nj][3] = -1e30f;
            }
        }

        float rm0 = -1e30f, rm1 = -1e30f;
        #pragma unroll
        for (int nj = 0; nj < 8; nj++) {
            rm0 = fmaxf(rm0, fmaxf(sc[nj][0], sc[nj][1]));
            rm1 = fmaxf(rm1, fmaxf(sc[nj][2], sc[nj][3]));
        }
        rm0 = fmaxf(rm0, __shfl_xor_sync(0xffffffffu, rm0, 1));
        rm0 = fmaxf(rm0, __shfl_xor_sync(0xffffffffu, rm0, 2));
        rm1 = fmaxf(rm1, __shfl_xor_sync(0xffffffffu, rm1, 1));
        rm1 = fmaxf(rm1, __shfl_xor_sync(0xffffffffu, rm1, 2));
        float mn0 = fmaxf(m0, rm0), mn1 = fmaxf(m1, rm1);
        float corr0 = exp2f(m0 - mn0), corr1 = exp2f(m1 - mn1);
        m0 = mn0; m1 = mn1;

        unsigned pa[4][4];
        float ps0 = 0.f, ps1 = 0.f;
        #pragma unroll
        for (int j = 0; j < 4; j++) {
            float p00 = exp2f(sc[2*j][0]   - m0), p01 = exp2f(sc[2*j][1]   - m0);
            float p02 = exp2f(sc[2*j][2]   - m1), p03 = exp2f(sc[2*j][3]   - m1);
            float p10 = exp2f(sc[2*j+1][0] - m0), p11 = exp2f(sc[2*j+1][1] - m0);
            float p12 = exp2f(sc[2*j+1][2] - m1), p13 = exp2f(sc[2*j+1][3] - m1);
            ps0 += p00 + p01 + p10 + p11;
            ps1 += p02 + p03 + p12 + p13;
            __half2 h0 = __floats2half2_rn(p00, p01);
            __half2 h1 = __floats2half2_rn(p02, p03);
            __half2 h2 = __floats2half2_rn(p10, p11);
            __half2 h3 = __floats2half2_rn(p12, p13);
            pa[j][0] = *(unsigned*)&h0;
            pa[j][1] = *(unsigned*)&h1;
            pa[j][2] = *(unsigned*)&h2;
            pa[j][3] = *(unsigned*)&h3;
        }
        ps0 += __shfl_xor_sync(0xffffffffu, ps0, 1);
        ps0 += __shfl_xor_sync(0xffffffffu, ps0, 2);
        ps1 += __shfl_xor_sync(0xffffffffu, ps1, 1);
        ps1 += __shfl_xor_sync(0xffffffffu, ps1, 2);
        l0 = l0*corr0 + ps0;
        l1 = l1*corr1 + ps1;

        #pragma unroll
        for (int nj = 0; nj < 8; nj++) {
            oa[nj][0] *= corr0; oa[nj][1] *= corr0;
            oa[nj][2] *= corr1; oa[nj][3] *= corr1;
        }

        #pragma unroll
        for (int j = 0; j < 4; j++) {
            unsigned vf[4][4];
            #pragma unroll
            for (int pd = 0; pd < 4; pd++) {
                int r = j*16 + (lane & 15);
                int cH = pd*16 + ((lane >> 4) << 3);
                ldm_x4t(vf[pd][0], vf[pd][1], vf[pd][2], vf[pd][3], uV[bb] + (r*ASTR + cH)*2);
            }
            #pragma unroll
            for (int dn = 0; dn < 8; dn++)
                mma16816(oa[dn][0], oa[dn][1], oa[dn][2], oa[dn][3],
                         pa[j][0], pa[j][1], pa[j][2], pa[j][3],
                         vf[dn >> 1][(dn & 1)*2], vf[dn >> 1][(dn & 1)*2 + 1]);
        }
        __syncthreads();
    }

    float il0 = 1.f/l0, il1 = 1.f/l1;
    int r0 = qb*FQT + wid*16 + (lane >> 2);
    #pragma unroll
    for (int dn = 0; dn < 8; dn++) {
        int col = dn*8 + (lane & 3)*2;
        long o0 = ((long)(b*TT + r0)*HH + h)*DD + col;
        long o1 = ((long)(b*TT + r0 + 8)*HH + h)*DD + col;
        *(__half2*)(y + o0) = __floats2half2_rn(oa[dn][0]*il0, oa[dn][1]*il0);
        *(__half2*)(y + o1) = __floats2half2_rn(oa[dn][2]*il1, oa[dn][3]*il1);
    }
}

__global__ void offsets_k(const int* counts, int* poff, int* cursor) {
    if (threadIdx.x == 0 && blockIdx.x == 0) {
        int o = 0;
        for (int e = 0; e < EE; e++) {
            poff[e] = o; cursor[e] = 0;
            o += ((counts[e] + 127)/128)*128;
        }
        poff[EE] = o;
    }
}

__global__ void scatter_k(const int* __restrict__ idx2, const float* __restrict__ wts2,
                          int* __restrict__ cursor, const int* __restrict__ poff,
                          int* __restrict__ perm, float* __restrict__ gatew) {
    int t = blockIdx.x*blockDim.x + threadIdx.x;
    if (t >= M0) return;
    for (int kk = 0; kk < 2; kk++) {
        int e = idx2[t*2 + kk];
        int pos = atomicAdd(&cursor[e], 1);
        int r = poff[e] + pos;
        perm[r] = t; gatew[r] = wts2[t*2 + kk];
    }
}

// ---------------- launch ----------------
static void* sym(const void* s) { void* p = nullptr; cudaGetSymbolAddress(&p, s); return p; }

extern "C" void kernel_launch(void* const* d_in, const int* in_sizes, int n_in,
                              void* d_out, int out_size) {
    const float* x    = (const float*)d_in[0];
    const float* rc   = (const float*)d_in[1];
    const float* rs   = (const float*)d_in[2];
    const float* anw  = (const float*)d_in[3];
    const float* qw   = (const float*)d_in[4];
    const float* kw   = (const float*)d_in[5];
    const float* vw   = (const float*)d_in[6];
    const float* ow   = (const float*)d_in[7];
    const float* fnw  = (const float*)d_in[8];
    const float* rw   = (const float*)d_in[9];
    const float* w1   = (const float*)d_in[10];
    const float* w2   = (const float*)d_in[11];
    const float* w3   = (const float*)d_in[12];
    float* out = (float*)d_out;

    __half* h16   = (__half*)sym(g_h16);
    __half* qkv16 = (__half*)sym(g_qkv16);
    __half* y16   = (__half*)sym(g_y16);
    __half* hn16  = (__half*)sym(g_hn16);
    __half* gb16  = (__half*)sym(g_gb16);
    __half* w16   = (__half*)sym(g_w16all);
    __half* wqkv16= w16;
    __half* ow16  = w16 + OFF_OW;
    __half* w116  = w16 + OFF_W1;
    __half* w216  = w16 + OFF_W2;
    __half* w316  = w16 + OFF_W3;
    int*   counts = (int*)sym(g_counts);
    int*   cursor = (int*)sym(g_cursor);
    int*   poff   = (int*)sym(g_poff);
    int*   perm   = (int*)sym(g_perm);
    float* gatew  = (float*)sym(g_gatew);
    int*   idx2   = (int*)sym(g_idx2);
    float* wts2   = (float*)sym(g_wts2);

    cudaFuncSetAttribute(gemm16_k, cudaFuncAttributeMaxDynamicSharedMemorySize, DSM_G);
    cudaFuncSetAttribute(moe13_k, cudaFuncAttributeMaxDynamicSharedMemorySize, DSM_M);
    cudaFuncSetAttribute(fattn_k, cudaFuncAttributeMaxDynamicSharedMemorySize, DSM_F);

    // 0) fused weight conversion + MoE bookkeeping init
    int ncv = 4*N4C + 3*N4E;
    convw_k<<<(ncv + 255)/256, 256>>>((const float4*)qw, (const float4*)kw, (const float4*)vw,
                                      (const float4*)ow, (const float4*)w1, (const float4*)w2,
                                      (const float4*)w3, (__half2*)w16, counts, perm, gatew);
    // 1) attn rmsnorm (fp16 out)
    rmsnorm_k<<<M0, 256>>>(x, anw, h16);
    // 2) fused QKV projection with rope applied in epilogue (fp16 out, q in log2 domain)
    gemm16_k<<<dim3(3*CC/GBN, M0/GBM), 128, DSM_G>>>(h16, wqkv16, nullptr, qkv16, 3*CC, CC,
                                                     nullptr, nullptr, nullptr, nullptr, 0, nullptr, rc, rs);
    // 3) causal flash attention (exp2 softmax)
    fattn_k<<<dim3(TT/FQT, HH, BB), 256, DSM_F>>>(qkv16, y16);
    // 4) output projection + residual -> out
    gemm16_k<<<dim3(CC/GBN, M0/GBM), 128, DSM_G>>>(y16, ow16, out, nullptr, CC, CC,
                                                   x, nullptr, nullptr, nullptr, 0, nullptr, nullptr, nullptr);
    // 5) fused ffn rmsnorm + router
    rmsnorm_router_k<<<M0, 256>>>(out, fnw, hn16, rw, idx2, wts2, counts);
    // 6) gather bookkeeping
    offsets_k<<<1, 32>>>(counts, poff, cursor);
    scatter_k<<<(M0 + 255)/256, 256>>>(idx2, wts2, cursor, poff, perm, gatew);
    // 7) fused expert up-projection + silu*mul
    moe13_k<<<dim3(HDIM/GBN, MG/GBM), 256, DSM_M>>>(hn16, w116, w316, gb16, perm, poff);
    //    down-projection: gate-scaled atomic scatter into out
    gemm16_k<<<dim3(CC/GBN, MG/GBM), 128, DSM_G>>>(gb16, w216, out, nullptr, CC, HDIM,
                                                   nullptr, nullptr, poff, gatew, (long)CC*HDIM, perm, nullptr, nullptr);
}